// round 1
// baseline (speedup 1.0000x reference)
#include <cuda_runtime.h>
#include <cuda_bf16.h>
#include <math_constants.h>

// Problem constants
#define SEQ     2048
#define BATCH   2
#define DMODEL  1024
#define NHEADS  16
#define DK      64          // DMODEL / NHEADS
#define BH      (BATCH*NHEADS)   // 32
#define MROWS   (SEQ*BATCH)      // 4096

// Scratch (device globals; no runtime allocation)
__device__ float g_Q[BH * SEQ * DK];   // [bh][s][dk]
__device__ float g_K[BH * SEQ * DK];
__device__ float g_V[BH * SEQ * DK];
__device__ float g_A[MROWS * DMODEL];  // attention output, (s*B+b, d) layout

// ---------------------------------------------------------------------------
// Kernel 1: fused QKV projection.
// For p in {0,1,2}: out_p = X_p @ W_p^T + b_p, scattered into head-major layout.
// Tile 128x128, K-step 8, 256 threads, 8x8 micro-tile.
// grid = (DMODEL/128, MROWS/128, 3)
// ---------------------------------------------------------------------------
__global__ __launch_bounds__(256, 2)
void qkv_gemm(const float* __restrict__ xq, const float* __restrict__ xk,
              const float* __restrict__ xv, const float* __restrict__ W,
              const float* __restrict__ bias)
{
    const int p  = blockIdx.z;
    const float* X = (p == 0) ? xq : (p == 1) ? xk : xv;
    float* DST     = (p == 0) ? g_Q : (p == 1) ? g_K : g_V;

    const int m0 = blockIdx.y * 128;
    const int n0 = blockIdx.x * 128;

    __shared__ float As[8][128];
    __shared__ float Bs[8][128];

    const int tid = threadIdx.x;
    const int ty  = tid >> 4;        // 0..15
    const int tx  = tid & 15;        // 0..15

    const int loadRow = tid >> 1;          // 0..127
    const int loadK4  = (tid & 1) * 4;     // 0 or 4

    const float* Aptr = X + (size_t)(m0 + loadRow) * DMODEL + loadK4;
    const float* Bptr = W + (size_t)(p * DMODEL + n0 + loadRow) * DMODEL + loadK4;

    float acc[8][8];
#pragma unroll
    for (int i = 0; i < 8; i++)
#pragma unroll
        for (int j = 0; j < 8; j++) acc[i][j] = 0.f;

    for (int k0 = 0; k0 < DMODEL; k0 += 8) {
        float4 av = *(const float4*)(Aptr + k0);
        float4 bv = *(const float4*)(Bptr + k0);
        As[loadK4 + 0][loadRow] = av.x;
        As[loadK4 + 1][loadRow] = av.y;
        As[loadK4 + 2][loadRow] = av.z;
        As[loadK4 + 3][loadRow] = av.w;
        Bs[loadK4 + 0][loadRow] = bv.x;
        Bs[loadK4 + 1][loadRow] = bv.y;
        Bs[loadK4 + 2][loadRow] = bv.z;
        Bs[loadK4 + 3][loadRow] = bv.w;
        __syncthreads();

#pragma unroll
        for (int kk = 0; kk < 8; kk++) {
            float a[8], b[8];
            *(float4*)(a)     = *(const float4*)&As[kk][ty * 8];
            *(float4*)(a + 4) = *(const float4*)&As[kk][ty * 8 + 4];
            *(float4*)(b)     = *(const float4*)&Bs[kk][tx * 8];
            *(float4*)(b + 4) = *(const float4*)&Bs[kk][tx * 8 + 4];
#pragma unroll
            for (int i = 0; i < 8; i++)
#pragma unroll
                for (int j = 0; j < 8; j++)
                    acc[i][j] = fmaf(a[i], b[j], acc[i][j]);
        }
        __syncthreads();
    }

    // Epilogue: add bias, scatter to head-major [bh][s][dk]
#pragma unroll
    for (int ii = 0; ii < 8; ii++) {
        const int m   = m0 + ty * 8 + ii;
        const int s   = m >> 1;
        const int bb  = m & 1;
#pragma unroll
        for (int jj4 = 0; jj4 < 2; jj4++) {
            const int n = n0 + tx * 8 + jj4 * 4;   // 4-aligned, within one head
            const int h = n >> 6;
            const int j = n & 63;
            float4 v;
            v.x = acc[ii][jj4 * 4 + 0] + bias[p * DMODEL + n + 0];
            v.y = acc[ii][jj4 * 4 + 1] + bias[p * DMODEL + n + 1];
            v.z = acc[ii][jj4 * 4 + 2] + bias[p * DMODEL + n + 2];
            v.w = acc[ii][jj4 * 4 + 3] + bias[p * DMODEL + n + 3];
            *(float4*)&DST[(((size_t)(bb * NHEADS + h)) * SEQ + s) * DK + j] = v;
        }
    }
}

// ---------------------------------------------------------------------------
// Kernel 2: flash attention per (bh, q-tile of 64). K-tile = 32.
// O kept in registers (4x4 per thread), scores staged in smem.
// grid = (SEQ/64, BH), block 256.
// ---------------------------------------------------------------------------
__global__ __launch_bounds__(256, 2)
void attn_kernel()
{
    __shared__ float Qs[64][64];
    __shared__ float Ks[32][68];
    __shared__ float Vs[32][68];
    __shared__ float Ssm[64][33];
    __shared__ float mrow[64], lrow[64], arow[64];

    const int q0 = blockIdx.x * 64;
    const int bh = blockIdx.y;
    const int tid = threadIdx.x;
    const int ty = tid >> 4, tx = tid & 15;
    const int i0 = ty * 4;           // q-row base for this thread
    const int j0 = tx * 2;           // k-col base (score tile)
    const int warp = tid >> 5, lane = tid & 31;

    const float* Qg = g_Q + ((size_t)bh * SEQ + q0) * DK;
    const float* Kg = g_K + (size_t)bh * SEQ * DK;
    const float* Vg = g_V + (size_t)bh * SEQ * DK;

    // Load Q tile (64x64): 4 float4 per thread
#pragma unroll
    for (int r = 0; r < 4; r++) {
        int i4  = tid + r * 256;         // 0..1023
        int row = i4 >> 4;
        int c4  = (i4 & 15) * 4;
        *(float4*)&Qs[row][c4] = *(const float4*)(Qg + row * DK + c4);
    }
    if (tid < 64) { mrow[tid] = -1e30f; lrow[tid] = 0.f; }

    float o[4][4];
#pragma unroll
    for (int a = 0; a < 4; a++)
#pragma unroll
        for (int b = 0; b < 4; b++) o[a][b] = 0.f;

    for (int kt = 0; kt < SEQ / 32; kt++) {
        // Load K,V tiles (32x64 each): 2 float4 per thread per tile
#pragma unroll
        for (int r = 0; r < 2; r++) {
            int i4  = tid + r * 256;     // 0..511
            int row = i4 >> 4;
            int c4  = (i4 & 15) * 4;
            *(float4*)&Ks[row][c4] = *(const float4*)(Kg + (kt * 32 + row) * DK + c4);
            *(float4*)&Vs[row][c4] = *(const float4*)(Vg + (kt * 32 + row) * DK + c4);
        }
        __syncthreads();

        // S = Q . K^T * 1/8   (64x32 tile, 4x2 per thread, d vectorized by 4)
        float sreg[4][2];
#pragma unroll
        for (int a = 0; a < 4; a++) { sreg[a][0] = 0.f; sreg[a][1] = 0.f; }
        for (int d = 0; d < 64; d += 4) {
            float4 qa[4], kb[2];
#pragma unroll
            for (int a = 0; a < 4; a++) qa[a] = *(const float4*)&Qs[i0 + a][d];
#pragma unroll
            for (int b = 0; b < 2; b++) kb[b] = *(const float4*)&Ks[j0 + b][d];
#pragma unroll
            for (int a = 0; a < 4; a++)
#pragma unroll
                for (int b = 0; b < 2; b++) {
                    sreg[a][b] = fmaf(qa[a].x, kb[b].x, sreg[a][b]);
                    sreg[a][b] = fmaf(qa[a].y, kb[b].y, sreg[a][b]);
                    sreg[a][b] = fmaf(qa[a].z, kb[b].z, sreg[a][b]);
                    sreg[a][b] = fmaf(qa[a].w, kb[b].w, sreg[a][b]);
                }
        }
#pragma unroll
        for (int a = 0; a < 4; a++)
#pragma unroll
            for (int b = 0; b < 2; b++)
                Ssm[i0 + a][j0 + b] = sreg[a][b] * 0.125f;
        __syncthreads();

        // Online softmax: warp w owns rows [w*8, w*8+8)
#pragma unroll
        for (int r8 = 0; r8 < 8; r8++) {
            const int r = warp * 8 + r8;
            float val = Ssm[r][lane];
            float mx = val;
#pragma unroll
            for (int off = 16; off; off >>= 1)
                mx = fmaxf(mx, __shfl_xor_sync(0xffffffffu, mx, off));
            const float mold = mrow[r];
            const float mnew = fmaxf(mold, mx);
            const float pv = __expf(val - mnew);
            Ssm[r][lane] = pv;
            float sum = pv;
#pragma unroll
            for (int off = 16; off; off >>= 1)
                sum += __shfl_xor_sync(0xffffffffu, sum, off);
            if (lane == 0) {
                const float alpha = __expf(mold - mnew);
                arow[r] = alpha;
                lrow[r] = lrow[r] * alpha + sum;
                mrow[r] = mnew;
            }
        }
        __syncthreads();

        // O = O*alpha + P @ V   (thread owns rows i0..i0+3, cols tx*4..tx*4+3)
#pragma unroll
        for (int a = 0; a < 4; a++) {
            const float alpha = arow[i0 + a];
#pragma unroll
            for (int b = 0; b < 4; b++) o[a][b] *= alpha;
        }
        for (int j = 0; j < 32; j++) {
            const float4 vv = *(const float4*)&Vs[j][tx * 4];
            float pr[4];
#pragma unroll
            for (int a = 0; a < 4; a++) pr[a] = Ssm[i0 + a][j];
#pragma unroll
            for (int a = 0; a < 4; a++) {
                o[a][0] = fmaf(pr[a], vv.x, o[a][0]);
                o[a][1] = fmaf(pr[a], vv.y, o[a][1]);
                o[a][2] = fmaf(pr[a], vv.z, o[a][2]);
                o[a][3] = fmaf(pr[a], vv.w, o[a][3]);
            }
        }
        __syncthreads();
    }

    // Write out: g_A[(s*BATCH + b)*DMODEL + h*DK + d]
    const int bb = bh >> 4;
    const int h  = bh & 15;
#pragma unroll
    for (int a = 0; a < 4; a++) {
        const int sq = q0 + i0 + a;
        const float inv = 1.0f / lrow[i0 + a];
        float4 v;
        v.x = o[a][0] * inv; v.y = o[a][1] * inv;
        v.z = o[a][2] * inv; v.w = o[a][3] * inv;
        *(float4*)&g_A[(size_t)(sq * BATCH + bb) * DMODEL + h * DK + tx * 4] = v;
    }
}

// ---------------------------------------------------------------------------
// Kernel 3: out projection. out = g_A @ W^T + b, linear output.
// grid = (DMODEL/128, MROWS/128)
// ---------------------------------------------------------------------------
__global__ __launch_bounds__(256, 2)
void out_gemm(const float* __restrict__ W, const float* __restrict__ bias,
              float* __restrict__ out)
{
    const int m0 = blockIdx.y * 128;
    const int n0 = blockIdx.x * 128;

    __shared__ float As[8][128];
    __shared__ float Bs[8][128];

    const int tid = threadIdx.x;
    const int ty = tid >> 4, tx = tid & 15;
    const int loadRow = tid >> 1;
    const int loadK4  = (tid & 1) * 4;

    const float* Aptr = g_A + (size_t)(m0 + loadRow) * DMODEL + loadK4;
    const float* Bptr = W   + (size_t)(n0 + loadRow) * DMODEL + loadK4;

    float acc[8][8];
#pragma unroll
    for (int i = 0; i < 8; i++)
#pragma unroll
        for (int j = 0; j < 8; j++) acc[i][j] = 0.f;

    for (int k0 = 0; k0 < DMODEL; k0 += 8) {
        float4 av = *(const float4*)(Aptr + k0);
        float4 bv = *(const float4*)(Bptr + k0);
        As[loadK4 + 0][loadRow] = av.x;
        As[loadK4 + 1][loadRow] = av.y;
        As[loadK4 + 2][loadRow] = av.z;
        As[loadK4 + 3][loadRow] = av.w;
        Bs[loadK4 + 0][loadRow] = bv.x;
        Bs[loadK4 + 1][loadRow] = bv.y;
        Bs[loadK4 + 2][loadRow] = bv.z;
        Bs[loadK4 + 3][loadRow] = bv.w;
        __syncthreads();

#pragma unroll
        for (int kk = 0; kk < 8; kk++) {
            float a[8], b[8];
            *(float4*)(a)     = *(const float4*)&As[kk][ty * 8];
            *(float4*)(a + 4) = *(const float4*)&As[kk][ty * 8 + 4];
            *(float4*)(b)     = *(const float4*)&Bs[kk][tx * 8];
            *(float4*)(b + 4) = *(const float4*)&Bs[kk][tx * 8 + 4];
#pragma unroll
            for (int i = 0; i < 8; i++)
#pragma unroll
                for (int j = 0; j < 8; j++)
                    acc[i][j] = fmaf(a[i], b[j], acc[i][j]);
        }
        __syncthreads();
    }

#pragma unroll
    for (int ii = 0; ii < 8; ii++) {
        const int m = m0 + ty * 8 + ii;
#pragma unroll
        for (int jj4 = 0; jj4 < 2; jj4++) {
            const int n = n0 + tx * 8 + jj4 * 4;
            float4 v;
            v.x = acc[ii][jj4 * 4 + 0] + bias[n + 0];
            v.y = acc[ii][jj4 * 4 + 1] + bias[n + 1];
            v.z = acc[ii][jj4 * 4 + 2] + bias[n + 2];
            v.w = acc[ii][jj4 * 4 + 3] + bias[n + 3];
            *(float4*)&out[(size_t)m * DMODEL + n] = v;
        }
    }
}

// ---------------------------------------------------------------------------
extern "C" void kernel_launch(void* const* d_in, const int* in_sizes, int n_in,
                              void* d_out, int out_size)
{
    const float* q  = (const float*)d_in[0];
    const float* k  = (const float*)d_in[1];
    const float* v  = (const float*)d_in[2];
    const float* in_w  = (const float*)d_in[3];
    const float* in_b  = (const float*)d_in[4];
    const float* out_w = (const float*)d_in[5];
    const float* out_b = (const float*)d_in[6];
    float* out = (float*)d_out;

    dim3 gQKV(DMODEL / 128, MROWS / 128, 3);
    qkv_gemm<<<gQKV, 256>>>(q, k, v, in_w, in_b);

    dim3 gAttn(SEQ / 64, BH);
    attn_kernel<<<gAttn, 256>>>();

    dim3 gOut(DMODEL / 128, MROWS / 128);
    out_gemm<<<gOut, 256>>>(out_w, out_b, out);
}

// round 4
// speedup vs baseline: 1.1924x; 1.1924x over previous
#include <cuda_runtime.h>
#include <cuda_bf16.h>
#include <cstdint>

// ---------------------------------------------------------------------------
// Problem constants
// ---------------------------------------------------------------------------
#define SEQ     2048
#define BATCH   2
#define DMODEL  1024
#define NHEADS  16
#define DK      64
#define BH      (BATCH*NHEADS)   // 32
#define MROWS   (SEQ*BATCH)      // 4096

// ---------------------------------------------------------------------------
// Device scratch (no runtime allocation allowed)
// ---------------------------------------------------------------------------
__device__ float g_Q[BH * SEQ * DK];   // [bh][s][dk] fp32 for attention
__device__ float g_K[BH * SEQ * DK];
__device__ float g_V[BH * SEQ * DK];

// split-bf16 operands for HMMA GEMMs
__device__ __nv_bfloat16 g_Xhi[3 * MROWS * DMODEL];
__device__ __nv_bfloat16 g_Xlo[3 * MROWS * DMODEL];
__device__ __nv_bfloat16 g_Whi[3 * DMODEL * DMODEL];
__device__ __nv_bfloat16 g_Wlo[3 * DMODEL * DMODEL];
__device__ __nv_bfloat16 g_OWhi[DMODEL * DMODEL];
__device__ __nv_bfloat16 g_OWlo[DMODEL * DMODEL];
__device__ __nv_bfloat16 g_Ahi[MROWS * DMODEL];   // attention output hi/lo
__device__ __nv_bfloat16 g_Alo[MROWS * DMODEL];

// ---------------------------------------------------------------------------
// Helpers
// ---------------------------------------------------------------------------
__device__ __forceinline__ uint32_t smem_u32(const void* p) {
    uint32_t r;
    asm("{ .reg .u64 t; cvta.to.shared.u64 t, %1; cvt.u32.u64 %0, t; }"
        : "=r"(r) : "l"(p));
    return r;
}

__device__ __forceinline__ void ldsm4(uint32_t* r, uint32_t addr) {
    asm volatile("ldmatrix.sync.aligned.m8n8.x4.shared.b16 {%0,%1,%2,%3}, [%4];"
                 : "=r"(r[0]), "=r"(r[1]), "=r"(r[2]), "=r"(r[3]) : "r"(addr));
}

__device__ __forceinline__ void mma16816(float* c, const uint32_t* a, const uint32_t* b) {
    asm volatile(
        "mma.sync.aligned.m16n8k16.row.col.f32.bf16.bf16.f32 "
        "{%0,%1,%2,%3}, {%4,%5,%6,%7}, {%8,%9}, {%0,%1,%2,%3};"
        : "+f"(c[0]), "+f"(c[1]), "+f"(c[2]), "+f"(c[3])
        : "r"(a[0]), "r"(a[1]), "r"(a[2]), "r"(a[3]), "r"(b[0]), "r"(b[1]));
}

// ---------------------------------------------------------------------------
// Kernel 0: fp32 -> (bf16 hi, bf16 lo) split conversion, float4-vectorized.
// tag: 0 = X (q/k/v sections), 1 = in_proj_w, 2 = out_proj_w
// ---------------------------------------------------------------------------
__global__ __launch_bounds__(256)
void cvt_kernel(const float* __restrict__ src, int tag, long off, int n4)
{
    int i = blockIdx.x * 256 + threadIdx.x;
    if (i >= n4) return;
    __nv_bfloat16 *hi, *lo;
    if (tag == 0)      { hi = g_Xhi;  lo = g_Xlo;  }
    else if (tag == 1) { hi = g_Whi;  lo = g_Wlo;  }
    else               { hi = g_OWhi; lo = g_OWlo; }
    hi += off; lo += off;

    float4 x = ((const float4*)src)[i];
    __nv_bfloat16 h0 = __float2bfloat16(x.x);
    __nv_bfloat16 h1 = __float2bfloat16(x.y);
    __nv_bfloat16 h2 = __float2bfloat16(x.z);
    __nv_bfloat16 h3 = __float2bfloat16(x.w);
    __nv_bfloat16 l0 = __float2bfloat16(x.x - __bfloat162float(h0));
    __nv_bfloat16 l1 = __float2bfloat16(x.y - __bfloat162float(h1));
    __nv_bfloat16 l2 = __float2bfloat16(x.z - __bfloat162float(h2));
    __nv_bfloat16 l3 = __float2bfloat16(x.w - __bfloat162float(h3));
    __nv_bfloat162* hi2 = (__nv_bfloat162*)hi;
    __nv_bfloat162* lo2 = (__nv_bfloat162*)lo;
    hi2[2 * i]     = __halves2bfloat162(h0, h1);
    hi2[2 * i + 1] = __halves2bfloat162(h2, h3);
    lo2[2 * i]     = __halves2bfloat162(l0, l1);
    lo2[2 * i + 1] = __halves2bfloat162(l2, l3);
}

// ---------------------------------------------------------------------------
// Kernel 1: split-bf16 HMMA GEMM. D(64x64) = A(64xK) @ B(64xK)^T + bias.
// 128 threads = 4 warps (2x2), warp tile 32x32 (2 m16 x 4 n8 frags).
// K-chunk 32, register-prefetch double-buffered smem, XOR-swizzled ldmatrix.
// 3 products per k-step: hi*hi + hi*lo + lo*hi (fp32 accumulate).
// mode 0: qkv (A=g_Xhi/lo per p, B=g_Whi/lo per p, scatter head-major)
// mode 1: out (A=g_Ahi/lo, B=g_OWhi/lo, linear to dst)
// grid = (DMODEL/64, MROWS/64, mode==0 ? 3 : 1)
// ---------------------------------------------------------------------------
__global__ __launch_bounds__(128)
void gemm_mma(const float* __restrict__ bias_in, float* __restrict__ dst, int mode)
{
    // smem: [buf][tile: Ahi,Alo,Bhi,Blo][64 rows * 32 bf16]
    __shared__ __nv_bfloat16 sm[2][4][64 * 32];

    const int tid  = threadIdx.x;
    const int lane = tid & 31;
    const int wid  = tid >> 5;
    const int wm   = wid & 1;          // warp row (2)
    const int wn   = wid >> 1;         // warp col (2)
    const int p    = blockIdx.z;
    const int n0   = blockIdx.x * 64;
    const int m0   = blockIdx.y * 64;

    const __nv_bfloat16 *Ah, *Al, *Bh, *Bl;
    if (mode == 0) {
        Ah = g_Xhi + (size_t)p * MROWS * DMODEL;
        Al = g_Xlo + (size_t)p * MROWS * DMODEL;
        Bh = g_Whi + (size_t)p * DMODEL * DMODEL;
        Bl = g_Wlo + (size_t)p * DMODEL * DMODEL;
    } else {
        Ah = g_Ahi; Al = g_Alo; Bh = g_OWhi; Bl = g_OWlo;
    }
    const float* bptr = bias_in + p * DMODEL;

    // --- global->smem load mapping: 256 16B-blocks per tile-pair; 2 per thread
    const int r0 = tid >> 1;                 // row 0..63 (block0)
    const int c0 = (tid & 1) * 2;            // col-block 0 or 2
    // block0: (r0, c0), block1: (r0, c0+1)
    const int so00 = r0 * 32 + ((c0     ^ ((r0 >> 1) & 3)) * 8);
    const int so01 = r0 * 32 + (((c0+1) ^ ((r0 >> 1) & 3)) * 8);

    const size_t aoff = (size_t)(m0 + r0) * DMODEL + c0 * 8;
    const size_t boff = (size_t)(n0 + r0) * DMODEL + c0 * 8;

    // ldmatrix per-lane address components (tile-local)
    const int arow = wm * 32 + (lane & 7) + ((lane >> 3) & 1) * 8;  // + mf*16
    const int akb  = (lane >> 4);                                    // + ks*2
    const int brow = wn * 32 + (lane & 7) + (lane >> 4) * 8;         // + nq*16
    const int bkb  = ((lane >> 3) & 1);                              // + ks*2

    const uint32_t sbase = smem_u32(sm);

    float acc[2][4][4];
#pragma unroll
    for (int i = 0; i < 2; i++)
#pragma unroll
        for (int j = 0; j < 4; j++)
#pragma unroll
            for (int e = 0; e < 4; e++) acc[i][j][e] = 0.f;

    uint4 pah0, pah1, pal0, pal1, pbh0, pbh1, pbl0, pbl1;

#define FETCH(kc) do { \
    const size_t ko = (size_t)(kc) * 32; \
    pah0 = *(const uint4*)(Ah + aoff + ko); \
    pah1 = *(const uint4*)(Ah + aoff + ko + 8); \
    pal0 = *(const uint4*)(Al + aoff + ko); \
    pal1 = *(const uint4*)(Al + aoff + ko + 8); \
    pbh0 = *(const uint4*)(Bh + boff + ko); \
    pbh1 = *(const uint4*)(Bh + boff + ko + 8); \
    pbl0 = *(const uint4*)(Bl + boff + ko); \
    pbl1 = *(const uint4*)(Bl + boff + ko + 8); \
} while (0)

#define STORE(buf) do { \
    *(uint4*)&sm[buf][0][so00] = pah0; *(uint4*)&sm[buf][0][so01] = pah1; \
    *(uint4*)&sm[buf][1][so00] = pal0; *(uint4*)&sm[buf][1][so01] = pal1; \
    *(uint4*)&sm[buf][2][so00] = pbh0; *(uint4*)&sm[buf][2][so01] = pbh1; \
    *(uint4*)&sm[buf][3][so00] = pbl0; *(uint4*)&sm[buf][3][so01] = pbl1; \
} while (0)

    FETCH(0);
    STORE(0);
    __syncthreads();

    for (int kc = 0; kc < 32; kc++) {
        const int buf = kc & 1;
        if (kc < 31) FETCH(kc + 1);

        const uint32_t bufb = sbase + buf * 16384;
#pragma unroll
        for (int ks = 0; ks < 2; ks++) {
            uint32_t afh[2][4], afl[2][4];
#pragma unroll
            for (int mf = 0; mf < 2; mf++) {
                const int r  = arow + mf * 16;
                const int kb = ks * 2 + akb;
                const uint32_t off = (uint32_t)(r * 32 + ((kb ^ ((r >> 1) & 3)) * 8)) * 2;
                ldsm4(afh[mf], bufb + 0 * 4096 + off);
                ldsm4(afl[mf], bufb + 1 * 4096 + off);
            }
            uint32_t bfh[2][4], bfl[2][4];
#pragma unroll
            for (int nq = 0; nq < 2; nq++) {
                const int r  = brow + nq * 16;
                const int kb = ks * 2 + bkb;
                const uint32_t off = (uint32_t)(r * 32 + ((kb ^ ((r >> 1) & 3)) * 8)) * 2;
                ldsm4(bfh[nq], bufb + 2 * 4096 + off);
                ldsm4(bfl[nq], bufb + 3 * 4096 + off);
            }
#pragma unroll
            for (int mf = 0; mf < 2; mf++)
#pragma unroll
                for (int nf = 0; nf < 4; nf++) {
                    const uint32_t* bh = &bfh[nf >> 1][(nf & 1) * 2];
                    const uint32_t* bl = &bfl[nf >> 1][(nf & 1) * 2];
                    mma16816(acc[mf][nf], afh[mf], bh);
                    mma16816(acc[mf][nf], afh[mf], bl);
                    mma16816(acc[mf][nf], afl[mf], bh);
                }
        }
        __syncthreads();
        if (kc < 31) {
            STORE((kc + 1) & 1);
            __syncthreads();
        }
    }
#undef FETCH
#undef STORE

    // --- epilogue: add bias, write out
    const int gID = lane >> 2;
    const int tg  = lane & 3;
#pragma unroll
    for (int mf = 0; mf < 2; mf++) {
#pragma unroll
        for (int nf = 0; nf < 4; nf++) {
            const int n = n0 + wn * 32 + nf * 8 + tg * 2;
            const float bx = bptr[n], by = bptr[n + 1];
#pragma unroll
            for (int half = 0; half < 2; half++) {
                const int m = m0 + wm * 32 + mf * 16 + gID + half * 8;
                float2 v;
                v.x = acc[mf][nf][half * 2 + 0] + bx;
                v.y = acc[mf][nf][half * 2 + 1] + by;
                if (mode == 0) {
                    const int s  = m >> 1;
                    const int bb = m & 1;
                    const int h  = n >> 6;
                    const int j  = n & 63;
                    float* DST = (p == 0) ? g_Q : (p == 1) ? g_K : g_V;
                    *(float2*)&DST[(((size_t)(bb * NHEADS + h)) * SEQ + s) * DK + j] = v;
                } else {
                    *(float2*)&dst[(size_t)m * DMODEL + n] = v;
                }
            }
        }
    }
}

// ---------------------------------------------------------------------------
// Kernel 2: flash attention (SIMT fp32); epilogue emits split-bf16 into
// g_Ahi/g_Alo for the HMMA out-projection.
// grid = (SEQ/64, BH), block 256.
// ---------------------------------------------------------------------------
__global__ __launch_bounds__(256, 2)
void attn_kernel()
{
    __shared__ float Qs[64][64];
    __shared__ float Ks[32][68];
    __shared__ float Vs[32][68];
    __shared__ float Ssm[64][33];
    __shared__ float mrow[64], lrow[64], arow[64];

    const int q0 = blockIdx.x * 64;
    const int bh = blockIdx.y;
    const int tid = threadIdx.x;
    const int ty = tid >> 4, tx = tid & 15;
    const int i0 = ty * 4;
    const int j0 = tx * 2;
    const int warp = tid >> 5, lane = tid & 31;

    const float* Qg = g_Q + ((size_t)bh * SEQ + q0) * DK;
    const float* Kg = g_K + (size_t)bh * SEQ * DK;
    const float* Vg = g_V + (size_t)bh * SEQ * DK;

#pragma unroll
    for (int r = 0; r < 4; r++) {
        int i4  = tid + r * 256;
        int row = i4 >> 4;
        int c4  = (i4 & 15) * 4;
        *(float4*)&Qs[row][c4] = *(const float4*)(Qg + row * DK + c4);
    }
    if (tid < 64) { mrow[tid] = -1e30f; lrow[tid] = 0.f; }

    float o[4][4];
#pragma unroll
    for (int a = 0; a < 4; a++)
#pragma unroll
        for (int b = 0; b < 4; b++) o[a][b] = 0.f;

    for (int kt = 0; kt < SEQ / 32; kt++) {
#pragma unroll
        for (int r = 0; r < 2; r++) {
            int i4  = tid + r * 256;
            int row = i4 >> 4;
            int c4  = (i4 & 15) * 4;
            *(float4*)&Ks[row][c4] = *(const float4*)(Kg + (kt * 32 + row) * DK + c4);
            *(float4*)&Vs[row][c4] = *(const float4*)(Vg + (kt * 32 + row) * DK + c4);
        }
        __syncthreads();

        float sreg[4][2];
#pragma unroll
        for (int a = 0; a < 4; a++) { sreg[a][0] = 0.f; sreg[a][1] = 0.f; }
        for (int d = 0; d < 64; d += 4) {
            float4 qa[4], kb[2];
#pragma unroll
            for (int a = 0; a < 4; a++) qa[a] = *(const float4*)&Qs[i0 + a][d];
#pragma unroll
            for (int b = 0; b < 2; b++) kb[b] = *(const float4*)&Ks[j0 + b][d];
#pragma unroll
            for (int a = 0; a < 4; a++)
#pragma unroll
                for (int b = 0; b < 2; b++) {
                    sreg[a][b] = fmaf(qa[a].x, kb[b].x, sreg[a][b]);
                    sreg[a][b] = fmaf(qa[a].y, kb[b].y, sreg[a][b]);
                    sreg[a][b] = fmaf(qa[a].z, kb[b].z, sreg[a][b]);
                    sreg[a][b] = fmaf(qa[a].w, kb[b].w, sreg[a][b]);
                }
        }
#pragma unroll
        for (int a = 0; a < 4; a++)
#pragma unroll
            for (int b = 0; b < 2; b++)
                Ssm[i0 + a][j0 + b] = sreg[a][b] * 0.125f;
        __syncthreads();

#pragma unroll
        for (int r8 = 0; r8 < 8; r8++) {
            const int r = warp * 8 + r8;
            float val = Ssm[r][lane];
            float mx = val;
#pragma unroll
            for (int off = 16; off; off >>= 1)
                mx = fmaxf(mx, __shfl_xor_sync(0xffffffffu, mx, off));
            const float mold = mrow[r];
            const float mnew = fmaxf(mold, mx);
            const float pv = __expf(val - mnew);
            Ssm[r][lane] = pv;
            float sum = pv;
#pragma unroll
            for (int off = 16; off; off >>= 1)
                sum += __shfl_xor_sync(0xffffffffu, sum, off);
            if (lane == 0) {
                const float alpha = __expf(mold - mnew);
                arow[r] = alpha;
                lrow[r] = lrow[r] * alpha + sum;
                mrow[r] = mnew;
            }
        }
        __syncthreads();

#pragma unroll
        for (int a = 0; a < 4; a++) {
            const float alpha = arow[i0 + a];
#pragma unroll
            for (int b = 0; b < 4; b++) o[a][b] *= alpha;
        }
        for (int j = 0; j < 32; j++) {
            const float4 vv = *(const float4*)&Vs[j][tx * 4];
            float pr[4];
#pragma unroll
            for (int a = 0; a < 4; a++) pr[a] = Ssm[i0 + a][j];
#pragma unroll
            for (int a = 0; a < 4; a++) {
                o[a][0] = fmaf(pr[a], vv.x, o[a][0]);
                o[a][1] = fmaf(pr[a], vv.y, o[a][1]);
                o[a][2] = fmaf(pr[a], vv.z, o[a][2]);
                o[a][3] = fmaf(pr[a], vv.w, o[a][3]);
            }
        }
        __syncthreads();
    }

    const int bb = bh >> 4;
    const int h  = bh & 15;
#pragma unroll
    for (int a = 0; a < 4; a++) {
        const int sq = q0 + i0 + a;
        const float inv = 1.0f / lrow[i0 + a];
        float vals[4];
        vals[0] = o[a][0] * inv; vals[1] = o[a][1] * inv;
        vals[2] = o[a][2] * inv; vals[3] = o[a][3] * inv;
        const size_t idx = (size_t)(sq * BATCH + bb) * DMODEL + h * DK + tx * 4;
        __nv_bfloat16 hh[4], ll[4];
#pragma unroll
        for (int e = 0; e < 4; e++) {
            hh[e] = __float2bfloat16(vals[e]);
            ll[e] = __float2bfloat16(vals[e] - __bfloat162float(hh[e]));
        }
        *(__nv_bfloat162*)&g_Ahi[idx]     = __halves2bfloat162(hh[0], hh[1]);
        *(__nv_bfloat162*)&g_Ahi[idx + 2] = __halves2bfloat162(hh[2], hh[3]);
        *(__nv_bfloat162*)&g_Alo[idx]     = __halves2bfloat162(ll[0], ll[1]);
        *(__nv_bfloat162*)&g_Alo[idx + 2] = __halves2bfloat162(ll[2], ll[3]);
    }
}

// ---------------------------------------------------------------------------
extern "C" void kernel_launch(void* const* d_in, const int* in_sizes, int n_in,
                              void* d_out, int out_size)
{
    const float* q     = (const float*)d_in[0];
    const float* k     = (const float*)d_in[1];
    const float* v     = (const float*)d_in[2];
    const float* in_w  = (const float*)d_in[3];
    const float* in_b  = (const float*)d_in[4];
    const float* out_w = (const float*)d_in[5];
    const float* out_b = (const float*)d_in[6];
    float* out = (float*)d_out;

    const int nX4 = MROWS * DMODEL / 4;          // 1048576
    cvt_kernel<<<nX4 / 256, 256>>>(q, 0, 0L, nX4);
    cvt_kernel<<<nX4 / 256, 256>>>(k, 0, (long)MROWS * DMODEL, nX4);
    cvt_kernel<<<nX4 / 256, 256>>>(v, 0, 2L * MROWS * DMODEL, nX4);
    const int nW4 = 3 * DMODEL * DMODEL / 4;     // 786432
    cvt_kernel<<<nW4 / 256, 256>>>(in_w, 1, 0L, nW4);
    const int nO4 = DMODEL * DMODEL / 4;         // 262144
    cvt_kernel<<<nO4 / 256, 256>>>(out_w, 2, 0L, nO4);

    dim3 gQKV(DMODEL / 64, MROWS / 64, 3);
    gemm_mma<<<gQKV, 128>>>(in_b, out, 0);

    dim3 gAttn(SEQ / 64, BH);
    attn_kernel<<<gAttn, 256>>>();

    dim3 gOut(DMODEL / 64, MROWS / 64, 1);
    gemm_mma<<<gOut, 128>>>(out_b, out, 1);
}

// round 5
// speedup vs baseline: 3.2346x; 2.7127x over previous
#include <cuda_runtime.h>
#include <cuda_bf16.h>
#include <cstdint>

// ---------------------------------------------------------------------------
// Problem constants
// ---------------------------------------------------------------------------
#define SEQ     2048
#define BATCH   2
#define DMODEL  1024
#define NHEADS  16
#define DK      64
#define BH      (BATCH*NHEADS)   // 32
#define MROWS   (SEQ*BATCH)      // 4096

// ---------------------------------------------------------------------------
// Device scratch (no runtime allocation allowed)
// ---------------------------------------------------------------------------
// split-bf16 Q/K/V in head-major [bh][s][dk]
__device__ __nv_bfloat16 g_Qhi[BH * SEQ * DK];
__device__ __nv_bfloat16 g_Qlo[BH * SEQ * DK];
__device__ __nv_bfloat16 g_Khi[BH * SEQ * DK];
__device__ __nv_bfloat16 g_Klo[BH * SEQ * DK];
__device__ __nv_bfloat16 g_Vhi[BH * SEQ * DK];
__device__ __nv_bfloat16 g_Vlo[BH * SEQ * DK];

// split-bf16 operands for HMMA projections
__device__ __nv_bfloat16 g_Xhi[3 * MROWS * DMODEL];
__device__ __nv_bfloat16 g_Xlo[3 * MROWS * DMODEL];
__device__ __nv_bfloat16 g_Whi[3 * DMODEL * DMODEL];
__device__ __nv_bfloat16 g_Wlo[3 * DMODEL * DMODEL];
__device__ __nv_bfloat16 g_OWhi[DMODEL * DMODEL];
__device__ __nv_bfloat16 g_OWlo[DMODEL * DMODEL];
__device__ __nv_bfloat16 g_Ahi[MROWS * DMODEL];   // attention output hi/lo
__device__ __nv_bfloat16 g_Alo[MROWS * DMODEL];

// ---------------------------------------------------------------------------
// Helpers
// ---------------------------------------------------------------------------
__device__ __forceinline__ uint32_t smem_u32(const void* p) {
    uint32_t r;
    asm("{ .reg .u64 t; cvta.to.shared.u64 t, %1; cvt.u32.u64 %0, t; }"
        : "=r"(r) : "l"(p));
    return r;
}

__device__ __forceinline__ void ldsm4(uint32_t* r, uint32_t addr) {
    asm volatile("ldmatrix.sync.aligned.m8n8.x4.shared.b16 {%0,%1,%2,%3}, [%4];"
                 : "=r"(r[0]), "=r"(r[1]), "=r"(r[2]), "=r"(r[3]) : "r"(addr));
}

__device__ __forceinline__ void ldsm4t(uint32_t* r, uint32_t addr) {
    asm volatile("ldmatrix.sync.aligned.m8n8.x4.trans.shared.b16 {%0,%1,%2,%3}, [%4];"
                 : "=r"(r[0]), "=r"(r[1]), "=r"(r[2]), "=r"(r[3]) : "r"(addr));
}

__device__ __forceinline__ void mma16816(float* c, const uint32_t* a, const uint32_t* b) {
    asm volatile(
        "mma.sync.aligned.m16n8k16.row.col.f32.bf16.bf16.f32 "
        "{%0,%1,%2,%3}, {%4,%5,%6,%7}, {%8,%9}, {%0,%1,%2,%3};"
        : "+f"(c[0]), "+f"(c[1]), "+f"(c[2]), "+f"(c[3])
        : "r"(a[0]), "r"(a[1]), "r"(a[2]), "r"(a[3]), "r"(b[0]), "r"(b[1]));
}

__device__ __forceinline__ void cp16(uint32_t d, const void* s) {
    asm volatile("cp.async.cg.shared.global [%0], [%1], 16;" :: "r"(d), "l"(s));
}

__device__ __forceinline__ uint32_t pack2(__nv_bfloat16 a, __nv_bfloat16 b) {
    __nv_bfloat162 t = __halves2bfloat162(a, b);
    return *(uint32_t*)&t;
}

// ---------------------------------------------------------------------------
// Kernel 0: fp32 -> (bf16 hi, bf16 lo) split conversion, float4-vectorized.
// tag: 0 = X (q/k/v sections), 1 = in_proj_w, 2 = out_proj_w
// ---------------------------------------------------------------------------
__global__ __launch_bounds__(256)
void cvt_kernel(const float* __restrict__ src, int tag, long off, int n4)
{
    int i = blockIdx.x * 256 + threadIdx.x;
    if (i >= n4) return;
    __nv_bfloat16 *hi, *lo;
    if (tag == 0)      { hi = g_Xhi;  lo = g_Xlo;  }
    else if (tag == 1) { hi = g_Whi;  lo = g_Wlo;  }
    else               { hi = g_OWhi; lo = g_OWlo; }
    hi += off; lo += off;

    float4 x = ((const float4*)src)[i];
    __nv_bfloat16 h0 = __float2bfloat16(x.x);
    __nv_bfloat16 h1 = __float2bfloat16(x.y);
    __nv_bfloat16 h2 = __float2bfloat16(x.z);
    __nv_bfloat16 h3 = __float2bfloat16(x.w);
    __nv_bfloat16 l0 = __float2bfloat16(x.x - __bfloat162float(h0));
    __nv_bfloat16 l1 = __float2bfloat16(x.y - __bfloat162float(h1));
    __nv_bfloat16 l2 = __float2bfloat16(x.z - __bfloat162float(h2));
    __nv_bfloat16 l3 = __float2bfloat16(x.w - __bfloat162float(h3));
    __nv_bfloat162* hi2 = (__nv_bfloat162*)hi;
    __nv_bfloat162* lo2 = (__nv_bfloat162*)lo;
    hi2[2 * i]     = __halves2bfloat162(h0, h1);
    hi2[2 * i + 1] = __halves2bfloat162(h2, h3);
    lo2[2 * i]     = __halves2bfloat162(l0, l1);
    lo2[2 * i + 1] = __halves2bfloat162(l2, l3);
}

// ---------------------------------------------------------------------------
// Kernel 1: split-bf16 HMMA GEMM. D(64x64) = A(64xK) @ B(64xK)^T + bias.
// mode 0: qkv (scatter head-major as split bf16 into g_{Q,K,V}{hi,lo})
// mode 1: out (linear fp32 to dst)
// grid = (DMODEL/64, MROWS/64, mode==0 ? 3 : 1)
// ---------------------------------------------------------------------------
__global__ __launch_bounds__(128)
void gemm_mma(const float* __restrict__ bias_in, float* __restrict__ dst, int mode)
{
    __shared__ __nv_bfloat16 sm[2][4][64 * 32];

    const int tid  = threadIdx.x;
    const int lane = tid & 31;
    const int wid  = tid >> 5;
    const int wm   = wid & 1;
    const int wn   = wid >> 1;
    const int p    = blockIdx.z;
    const int n0   = blockIdx.x * 64;
    const int m0   = blockIdx.y * 64;

    const __nv_bfloat16 *Ah, *Al, *Bh, *Bl;
    if (mode == 0) {
        Ah = g_Xhi + (size_t)p * MROWS * DMODEL;
        Al = g_Xlo + (size_t)p * MROWS * DMODEL;
        Bh = g_Whi + (size_t)p * DMODEL * DMODEL;
        Bl = g_Wlo + (size_t)p * DMODEL * DMODEL;
    } else {
        Ah = g_Ahi; Al = g_Alo; Bh = g_OWhi; Bl = g_OWlo;
    }
    const float* bptr = bias_in + p * DMODEL;

    const int r0 = tid >> 1;
    const int c0 = (tid & 1) * 2;
    const int so00 = r0 * 32 + ((c0     ^ ((r0 >> 1) & 3)) * 8);
    const int so01 = r0 * 32 + (((c0+1) ^ ((r0 >> 1) & 3)) * 8);

    const size_t aoff = (size_t)(m0 + r0) * DMODEL + c0 * 8;
    const size_t boff = (size_t)(n0 + r0) * DMODEL + c0 * 8;

    const int arow = wm * 32 + (lane & 7) + ((lane >> 3) & 1) * 8;
    const int akb  = (lane >> 4);
    const int brow = wn * 32 + (lane & 7) + (lane >> 4) * 8;
    const int bkb  = ((lane >> 3) & 1);

    const uint32_t sbase = smem_u32(sm);

    float acc[2][4][4];
#pragma unroll
    for (int i = 0; i < 2; i++)
#pragma unroll
        for (int j = 0; j < 4; j++)
#pragma unroll
            for (int e = 0; e < 4; e++) acc[i][j][e] = 0.f;

    uint4 pah0, pah1, pal0, pal1, pbh0, pbh1, pbl0, pbl1;

#define FETCH(kc) do { \
    const size_t ko = (size_t)(kc) * 32; \
    pah0 = *(const uint4*)(Ah + aoff + ko); \
    pah1 = *(const uint4*)(Ah + aoff + ko + 8); \
    pal0 = *(const uint4*)(Al + aoff + ko); \
    pal1 = *(const uint4*)(Al + aoff + ko + 8); \
    pbh0 = *(const uint4*)(Bh + boff + ko); \
    pbh1 = *(const uint4*)(Bh + boff + ko + 8); \
    pbl0 = *(const uint4*)(Bl + boff + ko); \
    pbl1 = *(const uint4*)(Bl + boff + ko + 8); \
} while (0)

#define STORE(buf) do { \
    *(uint4*)&sm[buf][0][so00] = pah0; *(uint4*)&sm[buf][0][so01] = pah1; \
    *(uint4*)&sm[buf][1][so00] = pal0; *(uint4*)&sm[buf][1][so01] = pal1; \
    *(uint4*)&sm[buf][2][so00] = pbh0; *(uint4*)&sm[buf][2][so01] = pbh1; \
    *(uint4*)&sm[buf][3][so00] = pbl0; *(uint4*)&sm[buf][3][so01] = pbl1; \
} while (0)

    FETCH(0);
    STORE(0);
    __syncthreads();

    for (int kc = 0; kc < 32; kc++) {
        const int buf = kc & 1;
        if (kc < 31) FETCH(kc + 1);

        const uint32_t bufb = sbase + buf * 16384;
#pragma unroll
        for (int ks = 0; ks < 2; ks++) {
            uint32_t afh[2][4], afl[2][4];
#pragma unroll
            for (int mf = 0; mf < 2; mf++) {
                const int r  = arow + mf * 16;
                const int kb = ks * 2 + akb;
                const uint32_t off = (uint32_t)(r * 32 + ((kb ^ ((r >> 1) & 3)) * 8)) * 2;
                ldsm4(afh[mf], bufb + 0 * 4096 + off);
                ldsm4(afl[mf], bufb + 1 * 4096 + off);
            }
            uint32_t bfh[2][4], bfl[2][4];
#pragma unroll
            for (int nq = 0; nq < 2; nq++) {
                const int r  = brow + nq * 16;
                const int kb = ks * 2 + bkb;
                const uint32_t off = (uint32_t)(r * 32 + ((kb ^ ((r >> 1) & 3)) * 8)) * 2;
                ldsm4(bfh[nq], bufb + 2 * 4096 + off);
                ldsm4(bfl[nq], bufb + 3 * 4096 + off);
            }
#pragma unroll
            for (int mf = 0; mf < 2; mf++)
#pragma unroll
                for (int nf = 0; nf < 4; nf++) {
                    const uint32_t* bhp = &bfh[nf >> 1][(nf & 1) * 2];
                    const uint32_t* blp = &bfl[nf >> 1][(nf & 1) * 2];
                    mma16816(acc[mf][nf], afh[mf], bhp);
                    mma16816(acc[mf][nf], afh[mf], blp);
                    mma16816(acc[mf][nf], afl[mf], bhp);
                }
        }
        __syncthreads();
        if (kc < 31) {
            STORE((kc + 1) & 1);
            __syncthreads();
        }
    }
#undef FETCH
#undef STORE

    // --- epilogue
    const int gID = lane >> 2;
    const int tg  = lane & 3;
#pragma unroll
    for (int mf = 0; mf < 2; mf++) {
#pragma unroll
        for (int nf = 0; nf < 4; nf++) {
            const int n = n0 + wn * 32 + nf * 8 + tg * 2;
            const float bx = bptr[n], by = bptr[n + 1];
#pragma unroll
            for (int half = 0; half < 2; half++) {
                const int m = m0 + wm * 32 + mf * 16 + gID + half * 8;
                const float fx = acc[mf][nf][half * 2 + 0] + bx;
                const float fy = acc[mf][nf][half * 2 + 1] + by;
                if (mode == 0) {
                    const int s  = m >> 1;
                    const int bb = m & 1;
                    const int h  = n >> 6;
                    const int j  = n & 63;
                    __nv_bfloat16* DH = (p == 0) ? g_Qhi : (p == 1) ? g_Khi : g_Vhi;
                    __nv_bfloat16* DL = (p == 0) ? g_Qlo : (p == 1) ? g_Klo : g_Vlo;
                    __nv_bfloat16 hx = __float2bfloat16(fx);
                    __nv_bfloat16 hy = __float2bfloat16(fy);
                    __nv_bfloat16 lx = __float2bfloat16(fx - __bfloat162float(hx));
                    __nv_bfloat16 ly = __float2bfloat16(fy - __bfloat162float(hy));
                    const size_t idx = (((size_t)(bb * NHEADS + h)) * SEQ + s) * DK + j;
                    *(__nv_bfloat162*)&DH[idx] = __halves2bfloat162(hx, hy);
                    *(__nv_bfloat162*)&DL[idx] = __halves2bfloat162(lx, ly);
                } else {
                    float2 v; v.x = fx; v.y = fy;
                    *(float2*)&dst[(size_t)m * DMODEL + n] = v;
                }
            }
        }
    }
}

// ---------------------------------------------------------------------------
// Kernel 2: split-bf16 HMMA flash attention.
// CTA = (64 q-rows, one bh). 4 warps x m16. K-tile 64, cp.async double buffer.
// S = QK^T (3-product split), online softmax in exp2 domain, O += P V
// (3-product split, ldmatrix.trans for V^T frags).
// grid = (SEQ/64, BH), block 128, dyn smem 64KB.
// ---------------------------------------------------------------------------
#define AT_SMEM 65536

__global__ __launch_bounds__(128)
void attn_mma()
{
    extern __shared__ char kvsm[];
    const uint32_t kvb = smem_u32(kvsm);
    const int tid  = threadIdx.x;
    const int lane = tid & 31;
    const int warp = tid >> 5;
    const int gID  = lane >> 2;
    const int tg   = lane & 3;
    const int q0   = blockIdx.x * 64;
    const int bh   = blockIdx.y;

    const __nv_bfloat16* Kh = g_Khi + (size_t)bh * SEQ * DK;
    const __nv_bfloat16* Kl = g_Klo + (size_t)bh * SEQ * DK;
    const __nv_bfloat16* Vh = g_Vhi + (size_t)bh * SEQ * DK;
    const __nv_bfloat16* Vl = g_Vlo + (size_t)bh * SEQ * DK;

    // Q fragments (persistent in registers)
    uint32_t qh[4][4], ql[4][4];
    {
        const __nv_bfloat16* Qh = g_Qhi + ((size_t)bh * SEQ + q0 + warp * 16) * DK;
        const __nv_bfloat16* Ql = g_Qlo + ((size_t)bh * SEQ + q0 + warp * 16) * DK;
#pragma unroll
        for (int ks = 0; ks < 4; ks++) {
            const int c = ks * 16 + tg * 2;
            qh[ks][0] = *(const uint32_t*)&Qh[(gID)     * DK + c];
            qh[ks][1] = *(const uint32_t*)&Qh[(gID + 8) * DK + c];
            qh[ks][2] = *(const uint32_t*)&Qh[(gID)     * DK + c + 8];
            qh[ks][3] = *(const uint32_t*)&Qh[(gID + 8) * DK + c + 8];
            ql[ks][0] = *(const uint32_t*)&Ql[(gID)     * DK + c];
            ql[ks][1] = *(const uint32_t*)&Ql[(gID + 8) * DK + c];
            ql[ks][2] = *(const uint32_t*)&Ql[(gID)     * DK + c + 8];
            ql[ks][3] = *(const uint32_t*)&Ql[(gID + 8) * DK + c + 8];
        }
    }

    float o[8][4];
#pragma unroll
    for (int j = 0; j < 8; j++)
#pragma unroll
        for (int e = 0; e < 4; e++) o[j][e] = 0.f;
    float mrun[2] = {-1e30f, -1e30f};
    float lrun[2] = {0.f, 0.f};

    // tile loader mapping
    const int lrow = tid >> 1;
    const int lc0  = (tid & 1) * 4;

#define ISSUE(kt, buf) do { \
    const size_t grow = ((size_t)((kt) * 64 + lrow)) * DK + lc0 * 8; \
    const uint32_t sb_ = kvb + (buf) * 32768 + lrow * 128; \
    _Pragma("unroll") \
    for (int i_ = 0; i_ < 4; i_++) { \
        const int blk_ = lc0 + i_; \
        const uint32_t so_ = sb_ + (uint32_t)((blk_ ^ (lrow & 7)) * 16); \
        cp16(so_,          Kh + grow + i_ * 8); \
        cp16(so_ + 8192,   Kl + grow + i_ * 8); \
        cp16(so_ + 16384,  Vh + grow + i_ * 8); \
        cp16(so_ + 24576,  Vl + grow + i_ * 8); \
    } \
    asm volatile("cp.async.commit_group;" ::: "memory"); \
} while (0)

    ISSUE(0, 0);

    // per-lane ldsm address components
    const int krow = (lane & 7) + (lane >> 4) * 8;        // + ng*16
    const int kkb  = (lane >> 3) & 1;                      // + ks*2
    const int vrow = (lane & 7) + ((lane >> 3) & 1) * 8;   // + t*16
    const int vdb  = (lane >> 4);                          // + dg*2

    for (int kt = 0; kt < 32; kt++) {
        const int buf = kt & 1;
        if (kt < 31) {
            ISSUE(kt + 1, buf ^ 1);
            asm volatile("cp.async.wait_group 1;" ::: "memory");
        } else {
            asm volatile("cp.async.wait_group 0;" ::: "memory");
        }
        __syncthreads();

        const uint32_t kb_hi = kvb + buf * 32768;

        // --- S = Q K^T ---
        float s[8][4];
#pragma unroll
        for (int j = 0; j < 8; j++)
#pragma unroll
            for (int e = 0; e < 4; e++) s[j][e] = 0.f;

#pragma unroll
        for (int ng = 0; ng < 4; ng++) {
            const int r = ng * 16 + krow;
            const uint32_t rbase = kb_hi + r * 128;
#pragma unroll
            for (int ks = 0; ks < 4; ks++) {
                const int kb = ks * 2 + kkb;
                const uint32_t off = rbase + (uint32_t)((kb ^ (r & 7)) * 16);
                uint32_t bh4[4], bl4[4];
                ldsm4(bh4, off);
                ldsm4(bl4, off + 8192);
                mma16816(s[ng * 2],     qh[ks], &bh4[0]);
                mma16816(s[ng * 2],     qh[ks], &bl4[0]);
                mma16816(s[ng * 2],     ql[ks], &bh4[0]);
                mma16816(s[ng * 2 + 1], qh[ks], &bh4[2]);
                mma16816(s[ng * 2 + 1], qh[ks], &bl4[2]);
                mma16816(s[ng * 2 + 1], ql[ks], &bh4[2]);
            }
        }

        // --- online softmax (exp2 domain; scale = 1/8 * log2e) ---
        const float SC = 0.125f * 1.4426950408889634f;
#pragma unroll
        for (int hf = 0; hf < 2; hf++) {
            float mx = -1e30f;
#pragma unroll
            for (int j = 0; j < 8; j++) {
                s[j][hf * 2]     *= SC;
                s[j][hf * 2 + 1] *= SC;
                mx = fmaxf(mx, fmaxf(s[j][hf * 2], s[j][hf * 2 + 1]));
            }
            mx = fmaxf(mx, __shfl_xor_sync(0xffffffffu, mx, 1));
            mx = fmaxf(mx, __shfl_xor_sync(0xffffffffu, mx, 2));
            const float mnew  = fmaxf(mrun[hf], mx);
            const float alpha = exp2f(mrun[hf] - mnew);
            mrun[hf] = mnew;
            float sum = 0.f;
#pragma unroll
            for (int j = 0; j < 8; j++) {
                const float p0 = exp2f(s[j][hf * 2]     - mnew);
                const float p1 = exp2f(s[j][hf * 2 + 1] - mnew);
                s[j][hf * 2]     = p0;
                s[j][hf * 2 + 1] = p1;
                sum += p0 + p1;
            }
            sum += __shfl_xor_sync(0xffffffffu, sum, 1);
            sum += __shfl_xor_sync(0xffffffffu, sum, 2);
            lrun[hf] = lrun[hf] * alpha + sum;
#pragma unroll
            for (int j = 0; j < 8; j++) {
                o[j][hf * 2]     *= alpha;
                o[j][hf * 2 + 1] *= alpha;
            }
        }

        // --- O += P V ---
#pragma unroll
        for (int t = 0; t < 4; t++) {
            uint32_t ph[4], pl[4];
#pragma unroll
            for (int e = 0; e < 2; e++) {
                const float f0 = s[2 * t + e][0], f1 = s[2 * t + e][1];
                const float f2 = s[2 * t + e][2], f3 = s[2 * t + e][3];
                const __nv_bfloat16 h0 = __float2bfloat16(f0);
                const __nv_bfloat16 h1 = __float2bfloat16(f1);
                const __nv_bfloat16 h2 = __float2bfloat16(f2);
                const __nv_bfloat16 h3 = __float2bfloat16(f3);
                ph[e * 2 + 0] = pack2(h0, h1);   // rows gID (a0/a2)
                ph[e * 2 + 1] = pack2(h2, h3);   // rows gID+8 (a1/a3)
                pl[e * 2 + 0] = pack2(__float2bfloat16(f0 - __bfloat162float(h0)),
                                      __float2bfloat16(f1 - __bfloat162float(h1)));
                pl[e * 2 + 1] = pack2(__float2bfloat16(f2 - __bfloat162float(h2)),
                                      __float2bfloat16(f3 - __bfloat162float(h3)));
            }
            // reorder into a0..a3 = {gID klo, gID+8 klo, gID khi, gID+8 khi}
            uint32_t pah[4] = { ph[0], ph[1], ph[2], ph[3] };
            uint32_t pal[4] = { pl[0], pl[1], pl[2], pl[3] };

            const int r = t * 16 + vrow;
            const uint32_t rbase = kb_hi + 16384 + r * 128;
#pragma unroll
            for (int dg = 0; dg < 4; dg++) {
                const int db = dg * 2 + vdb;
                const uint32_t off = rbase + (uint32_t)((db ^ (r & 7)) * 16);
                uint32_t vh4[4], vl4[4];
                ldsm4t(vh4, off);
                ldsm4t(vl4, off + 8192);
                mma16816(o[dg * 2],     pah, &vh4[0]);
                mma16816(o[dg * 2],     pal, &vh4[0]);
                mma16816(o[dg * 2],     pah, &vl4[0]);
                mma16816(o[dg * 2 + 1], pah, &vh4[2]);
                mma16816(o[dg * 2 + 1], pal, &vh4[2]);
                mma16816(o[dg * 2 + 1], pah, &vl4[2]);
            }
        }
        __syncthreads();
    }
#undef ISSUE

    // --- epilogue: normalize, split to bf16 hi/lo, write (s*B+b, h*64+d) ---
    const int bb  = bh >> 4;
    const int hh_ = bh & 15;
#pragma unroll
    for (int half = 0; half < 2; half++) {
        const int r = q0 + warp * 16 + gID + half * 8;
        const float inv = 1.0f / lrun[half];
#pragma unroll
        for (int j = 0; j < 8; j++) {
            const float f0 = o[j][half * 2 + 0] * inv;
            const float f1 = o[j][half * 2 + 1] * inv;
            const __nv_bfloat16 h0 = __float2bfloat16(f0);
            const __nv_bfloat16 h1 = __float2bfloat16(f1);
            const __nv_bfloat16 l0 = __float2bfloat16(f0 - __bfloat162float(h0));
            const __nv_bfloat16 l1 = __float2bfloat16(f1 - __bfloat162float(h1));
            const size_t idx = ((size_t)(r * BATCH + bb)) * DMODEL + hh_ * DK + j * 8 + tg * 2;
            *(__nv_bfloat162*)&g_Ahi[idx] = __halves2bfloat162(h0, h1);
            *(__nv_bfloat162*)&g_Alo[idx] = __halves2bfloat162(l0, l1);
        }
    }
}

// ---------------------------------------------------------------------------
extern "C" void kernel_launch(void* const* d_in, const int* in_sizes, int n_in,
                              void* d_out, int out_size)
{
    const float* q     = (const float*)d_in[0];
    const float* k     = (const float*)d_in[1];
    const float* v     = (const float*)d_in[2];
    const float* in_w  = (const float*)d_in[3];
    const float* in_b  = (const float*)d_in[4];
    const float* out_w = (const float*)d_in[5];
    const float* out_b = (const float*)d_in[6];
    float* out = (float*)d_out;

    static bool attr_done = false;
    if (!attr_done) {
        cudaFuncSetAttribute(attn_mma, cudaFuncAttributeMaxDynamicSharedMemorySize, AT_SMEM);
        attr_done = true;
    }

    const int nX4 = MROWS * DMODEL / 4;
    cvt_kernel<<<nX4 / 256, 256>>>(q, 0, 0L, nX4);
    cvt_kernel<<<nX4 / 256, 256>>>(k, 0, (long)MROWS * DMODEL, nX4);
    cvt_kernel<<<nX4 / 256, 256>>>(v, 0, 2L * MROWS * DMODEL, nX4);
    const int nW4 = 3 * DMODEL * DMODEL / 4;
    cvt_kernel<<<nW4 / 256, 256>>>(in_w, 1, 0L, nW4);
    const int nO4 = DMODEL * DMODEL / 4;
    cvt_kernel<<<nO4 / 256, 256>>>(out_w, 2, 0L, nO4);

    dim3 gQKV(DMODEL / 64, MROWS / 64, 3);
    gemm_mma<<<gQKV, 128>>>(in_b, out, 0);

    dim3 gAttn(SEQ / 64, BH);
    attn_mma<<<gAttn, 128, AT_SMEM>>>();

    dim3 gOut(DMODEL / 64, MROWS / 64, 1);
    gemm_mma<<<gOut, 128>>>(out_b, out, 1);
}

// round 6
// speedup vs baseline: 3.6887x; 1.1404x over previous
#include <cuda_runtime.h>
#include <cuda_bf16.h>
#include <cstdint>

// ---------------------------------------------------------------------------
// Problem constants
// ---------------------------------------------------------------------------
#define SEQ     2048
#define BATCH   2
#define DMODEL  1024
#define NHEADS  16
#define DK      64
#define BH      (BATCH*NHEADS)   // 32
#define MROWS   (SEQ*BATCH)      // 4096

// ---------------------------------------------------------------------------
// Device scratch (no runtime allocation allowed)
// ---------------------------------------------------------------------------
__device__ __nv_bfloat16 g_Qhi[BH * SEQ * DK];
__device__ __nv_bfloat16 g_Qlo[BH * SEQ * DK];
__device__ __nv_bfloat16 g_Khi[BH * SEQ * DK];
__device__ __nv_bfloat16 g_Klo[BH * SEQ * DK];
__device__ __nv_bfloat16 g_Vhi[BH * SEQ * DK];
__device__ __nv_bfloat16 g_Vlo[BH * SEQ * DK];

__device__ __nv_bfloat16 g_Xhi[3 * MROWS * DMODEL];
__device__ __nv_bfloat16 g_Xlo[3 * MROWS * DMODEL];
__device__ __nv_bfloat16 g_Whi[3 * DMODEL * DMODEL];
__device__ __nv_bfloat16 g_Wlo[3 * DMODEL * DMODEL];
__device__ __nv_bfloat16 g_OWhi[DMODEL * DMODEL];
__device__ __nv_bfloat16 g_OWlo[DMODEL * DMODEL];
__device__ __nv_bfloat16 g_Ahi[MROWS * DMODEL];
__device__ __nv_bfloat16 g_Alo[MROWS * DMODEL];

// ---------------------------------------------------------------------------
// Helpers
// ---------------------------------------------------------------------------
__device__ __forceinline__ uint32_t smem_u32(const void* p) {
    uint32_t r;
    asm("{ .reg .u64 t; cvta.to.shared.u64 t, %1; cvt.u32.u64 %0, t; }"
        : "=r"(r) : "l"(p));
    return r;
}

__device__ __forceinline__ void ldsm4(uint32_t* r, uint32_t addr) {
    asm volatile("ldmatrix.sync.aligned.m8n8.x4.shared.b16 {%0,%1,%2,%3}, [%4];"
                 : "=r"(r[0]), "=r"(r[1]), "=r"(r[2]), "=r"(r[3]) : "r"(addr));
}

__device__ __forceinline__ void ldsm4t(uint32_t* r, uint32_t addr) {
    asm volatile("ldmatrix.sync.aligned.m8n8.x4.trans.shared.b16 {%0,%1,%2,%3}, [%4];"
                 : "=r"(r[0]), "=r"(r[1]), "=r"(r[2]), "=r"(r[3]) : "r"(addr));
}

__device__ __forceinline__ void mma16816(float* c, const uint32_t* a, const uint32_t* b) {
    asm volatile(
        "mma.sync.aligned.m16n8k16.row.col.f32.bf16.bf16.f32 "
        "{%0,%1,%2,%3}, {%4,%5,%6,%7}, {%8,%9}, {%0,%1,%2,%3};"
        : "+f"(c[0]), "+f"(c[1]), "+f"(c[2]), "+f"(c[3])
        : "r"(a[0]), "r"(a[1]), "r"(a[2]), "r"(a[3]), "r"(b[0]), "r"(b[1]));
}

__device__ __forceinline__ void cp16(uint32_t d, const void* s) {
    asm volatile("cp.async.cg.shared.global [%0], [%1], 16;" :: "r"(d), "l"(s));
}

__device__ __forceinline__ uint32_t pack2(__nv_bfloat16 a, __nv_bfloat16 b) {
    __nv_bfloat162 t = __halves2bfloat162(a, b);
    return *(uint32_t*)&t;
}

// ---------------------------------------------------------------------------
// Kernel 0: fp32 -> (bf16 hi, bf16 lo) split conversion
// ---------------------------------------------------------------------------
__global__ __launch_bounds__(256)
void cvt_kernel(const float* __restrict__ src, int tag, long off, int n4)
{
    int i = blockIdx.x * 256 + threadIdx.x;
    if (i >= n4) return;
    __nv_bfloat16 *hi, *lo;
    if (tag == 0)      { hi = g_Xhi;  lo = g_Xlo;  }
    else if (tag == 1) { hi = g_Whi;  lo = g_Wlo;  }
    else               { hi = g_OWhi; lo = g_OWlo; }
    hi += off; lo += off;

    float4 x = ((const float4*)src)[i];
    __nv_bfloat16 h0 = __float2bfloat16(x.x);
    __nv_bfloat16 h1 = __float2bfloat16(x.y);
    __nv_bfloat16 h2 = __float2bfloat16(x.z);
    __nv_bfloat16 h3 = __float2bfloat16(x.w);
    __nv_bfloat16 l0 = __float2bfloat16(x.x - __bfloat162float(h0));
    __nv_bfloat16 l1 = __float2bfloat16(x.y - __bfloat162float(h1));
    __nv_bfloat16 l2 = __float2bfloat16(x.z - __bfloat162float(h2));
    __nv_bfloat16 l3 = __float2bfloat16(x.w - __bfloat162float(h3));
    __nv_bfloat162* hi2 = (__nv_bfloat162*)hi;
    __nv_bfloat162* lo2 = (__nv_bfloat162*)lo;
    hi2[2 * i]     = __halves2bfloat162(h0, h1);
    hi2[2 * i + 1] = __halves2bfloat162(h2, h3);
    lo2[2 * i]     = __halves2bfloat162(l0, l1);
    lo2[2 * i + 1] = __halves2bfloat162(l2, l3);
}

// ---------------------------------------------------------------------------
// Kernel 1: split-bf16 HMMA GEMM, 128x128 CTA tile, 256 threads (8 warps 2x4),
// warp tile 64x32 (4 m16 x 4 n8). K-chunk 32, cp.async double-buffered.
// mode 0: qkv (scatter head-major split-bf16), mode 1: out (fp32 linear)
// grid = (DMODEL/128, MROWS/128, mode==0?3:1), dyn smem 64KB
// ---------------------------------------------------------------------------
#define GB_SMEM 65536   // 2 bufs x 4 arrays x (128 x 32 bf16 = 8KB)

__global__ __launch_bounds__(256, 1)
void gemm_mma(const float* __restrict__ bias_in, float* __restrict__ dst, int mode)
{
    extern __shared__ char gsm[];
    const uint32_t sbase = smem_u32(gsm);

    const int tid  = threadIdx.x;
    const int lane = tid & 31;
    const int wid  = tid >> 5;
    const int wm   = wid & 1;          // 2 warp rows  (64 m each)
    const int wn   = wid >> 1;         // 4 warp cols  (32 n each)
    const int p    = blockIdx.z;
    const int n0   = blockIdx.x * 128;
    const int m0   = blockIdx.y * 128;

    const __nv_bfloat16 *Ah, *Al, *Bh, *Bl;
    if (mode == 0) {
        Ah = g_Xhi + (size_t)p * MROWS * DMODEL;
        Al = g_Xlo + (size_t)p * MROWS * DMODEL;
        Bh = g_Whi + (size_t)p * DMODEL * DMODEL;
        Bl = g_Wlo + (size_t)p * DMODEL * DMODEL;
    } else {
        Ah = g_Ahi; Al = g_Alo; Bh = g_OWhi; Bl = g_OWlo;
    }
    const float* bptr = bias_in + p * DMODEL;

    // loader mapping: thread t -> row (0..127), 2 col-blocks of 16B
    const int lrow = tid >> 1;
    const int lc0  = (tid & 1) * 2;
    const uint32_t soff0 = (uint32_t)(lrow * 32 + (((lc0)     ^ ((lrow >> 1) & 3)) * 8)) * 2;
    const uint32_t soff1 = (uint32_t)(lrow * 32 + (((lc0 + 1) ^ ((lrow >> 1) & 3)) * 8)) * 2;

    const size_t aoff = (size_t)(m0 + lrow) * DMODEL + lc0 * 8;
    const size_t boff = (size_t)(n0 + lrow) * DMODEL + lc0 * 8;

#define GISSUE(kc, buf) do { \
    const size_t ko = (size_t)(kc) * 32; \
    const uint32_t sb_ = sbase + (buf) * 32768; \
    cp16(sb_         + soff0, Ah + aoff + ko);      \
    cp16(sb_         + soff1, Ah + aoff + ko + 8);  \
    cp16(sb_ + 8192  + soff0, Al + aoff + ko);      \
    cp16(sb_ + 8192  + soff1, Al + aoff + ko + 8);  \
    cp16(sb_ + 16384 + soff0, Bh + boff + ko);      \
    cp16(sb_ + 16384 + soff1, Bh + boff + ko + 8);  \
    cp16(sb_ + 24576 + soff0, Bl + boff + ko);      \
    cp16(sb_ + 24576 + soff1, Bl + boff + ko + 8);  \
    asm volatile("cp.async.commit_group;" ::: "memory"); \
} while (0)

    // ldsm per-lane address components
    const int arow = (lane & 7) + ((lane >> 3) & 1) * 8;   // + wm*64 + mf*16
    const int akb  = (lane >> 4);
    const int brow = (lane & 7) + (lane >> 4) * 8;         // + wn*32 + nq*16
    const int bkb  = ((lane >> 3) & 1);

    float acc[4][4][4];
#pragma unroll
    for (int i = 0; i < 4; i++)
#pragma unroll
        for (int j = 0; j < 4; j++)
#pragma unroll
            for (int e = 0; e < 4; e++) acc[i][j][e] = 0.f;

    GISSUE(0, 0);

    for (int kc = 0; kc < 32; kc++) {
        const int buf = kc & 1;
        if (kc < 31) {
            GISSUE(kc + 1, buf ^ 1);
            asm volatile("cp.async.wait_group 1;" ::: "memory");
        } else {
            asm volatile("cp.async.wait_group 0;" ::: "memory");
        }
        __syncthreads();

        const uint32_t bufb = sbase + buf * 32768;
#pragma unroll
        for (int ks = 0; ks < 2; ks++) {
            uint32_t afh[4][4], afl[4][4];
#pragma unroll
            for (int mf = 0; mf < 4; mf++) {
                const int r  = wm * 64 + mf * 16 + arow;
                const int kb = ks * 2 + akb;
                const uint32_t off = (uint32_t)(r * 32 + ((kb ^ ((r >> 1) & 3)) * 8)) * 2;
                ldsm4(afh[mf], bufb + off);
                ldsm4(afl[mf], bufb + 8192 + off);
            }
            uint32_t bfh[2][4], bfl[2][4];
#pragma unroll
            for (int nq = 0; nq < 2; nq++) {
                const int r  = wn * 32 + nq * 16 + brow;
                const int kb = ks * 2 + bkb;
                const uint32_t off = (uint32_t)(r * 32 + ((kb ^ ((r >> 1) & 3)) * 8)) * 2;
                ldsm4(bfh[nq], bufb + 16384 + off);
                ldsm4(bfl[nq], bufb + 24576 + off);
            }
#pragma unroll
            for (int mf = 0; mf < 4; mf++)
#pragma unroll
                for (int nf = 0; nf < 4; nf++) {
                    const uint32_t* bhp = &bfh[nf >> 1][(nf & 1) * 2];
                    const uint32_t* blp = &bfl[nf >> 1][(nf & 1) * 2];
                    mma16816(acc[mf][nf], afh[mf], bhp);
                    mma16816(acc[mf][nf], afh[mf], blp);
                    mma16816(acc[mf][nf], afl[mf], bhp);
                }
        }
        __syncthreads();
    }
#undef GISSUE

    // --- epilogue
    const int gID = lane >> 2;
    const int tg  = lane & 3;
#pragma unroll
    for (int mf = 0; mf < 4; mf++) {
#pragma unroll
        for (int nf = 0; nf < 4; nf++) {
            const int n = n0 + wn * 32 + nf * 8 + tg * 2;
            const float bx = bptr[n], by = bptr[n + 1];
#pragma unroll
            for (int half = 0; half < 2; half++) {
                const int m = m0 + wm * 64 + mf * 16 + gID + half * 8;
                const float fx = acc[mf][nf][half * 2 + 0] + bx;
                const float fy = acc[mf][nf][half * 2 + 1] + by;
                if (mode == 0) {
                    const int s  = m >> 1;
                    const int bb = m & 1;
                    const int h  = n >> 6;
                    const int j  = n & 63;
                    __nv_bfloat16* DH = (p == 0) ? g_Qhi : (p == 1) ? g_Khi : g_Vhi;
                    __nv_bfloat16* DL = (p == 0) ? g_Qlo : (p == 1) ? g_Klo : g_Vlo;
                    __nv_bfloat16 hx = __float2bfloat16(fx);
                    __nv_bfloat16 hy = __float2bfloat16(fy);
                    __nv_bfloat16 lx = __float2bfloat16(fx - __bfloat162float(hx));
                    __nv_bfloat16 ly = __float2bfloat16(fy - __bfloat162float(hy));
                    const size_t idx = (((size_t)(bb * NHEADS + h)) * SEQ + s) * DK + j;
                    *(__nv_bfloat162*)&DH[idx] = __halves2bfloat162(hx, hy);
                    *(__nv_bfloat162*)&DL[idx] = __halves2bfloat162(lx, ly);
                } else {
                    float2 v; v.x = fx; v.y = fy;
                    *(float2*)&dst[(size_t)m * DMODEL + n] = v;
                }
            }
        }
    }
}

// ---------------------------------------------------------------------------
// Kernel 2: split-bf16 HMMA flash attention.
// CTA = (128 q-rows, one bh). 8 warps x m16. K-tile 64, cp.async double buffer.
// grid = (SEQ/128, BH), block 256, dyn smem 64KB.
// ---------------------------------------------------------------------------
#define AT_SMEM 65536

__global__ __launch_bounds__(256, 1)
void attn_mma()
{
    extern __shared__ char kvsm[];
    const uint32_t kvb = smem_u32(kvsm);
    const int tid  = threadIdx.x;
    const int lane = tid & 31;
    const int warp = tid >> 5;
    const int gID  = lane >> 2;
    const int tg   = lane & 3;
    const int q0   = blockIdx.x * 128;
    const int bh   = blockIdx.y;

    const __nv_bfloat16* Kh = g_Khi + (size_t)bh * SEQ * DK;
    const __nv_bfloat16* Kl = g_Klo + (size_t)bh * SEQ * DK;
    const __nv_bfloat16* Vh = g_Vhi + (size_t)bh * SEQ * DK;
    const __nv_bfloat16* Vl = g_Vlo + (size_t)bh * SEQ * DK;

    // Q fragments (persistent)
    uint32_t qh[4][4], ql[4][4];
    {
        const __nv_bfloat16* Qh = g_Qhi + ((size_t)bh * SEQ + q0 + warp * 16) * DK;
        const __nv_bfloat16* Ql = g_Qlo + ((size_t)bh * SEQ + q0 + warp * 16) * DK;
#pragma unroll
        for (int ks = 0; ks < 4; ks++) {
            const int c = ks * 16 + tg * 2;
            qh[ks][0] = *(const uint32_t*)&Qh[(gID)     * DK + c];
            qh[ks][1] = *(const uint32_t*)&Qh[(gID + 8) * DK + c];
            qh[ks][2] = *(const uint32_t*)&Qh[(gID)     * DK + c + 8];
            qh[ks][3] = *(const uint32_t*)&Qh[(gID + 8) * DK + c + 8];
            ql[ks][0] = *(const uint32_t*)&Ql[(gID)     * DK + c];
            ql[ks][1] = *(const uint32_t*)&Ql[(gID + 8) * DK + c];
            ql[ks][2] = *(const uint32_t*)&Ql[(gID)     * DK + c + 8];
            ql[ks][3] = *(const uint32_t*)&Ql[(gID + 8) * DK + c + 8];
        }
    }

    float o[8][4];
#pragma unroll
    for (int j = 0; j < 8; j++)
#pragma unroll
        for (int e = 0; e < 4; e++) o[j][e] = 0.f;
    float mrun[2] = {-1e30f, -1e30f};
    float lrun[2] = {0.f, 0.f};

    // loader: 256 threads, 64 rows x 8 blocks x 4 arrays
    const int lrow = tid >> 2;            // 0..63
    const int lc0  = (tid & 3) * 2;       // 0,2,4,6

#define ISSUE(kt, buf) do { \
    const size_t grow = ((size_t)((kt) * 64 + lrow)) * DK + lc0 * 8; \
    const uint32_t sb_ = kvb + (buf) * 32768 + lrow * 128; \
    _Pragma("unroll") \
    for (int i_ = 0; i_ < 2; i_++) { \
        const int blk_ = lc0 + i_; \
        const uint32_t so_ = sb_ + (uint32_t)((blk_ ^ (lrow & 7)) * 16); \
        cp16(so_,          Kh + grow + i_ * 8); \
        cp16(so_ + 8192,   Kl + grow + i_ * 8); \
        cp16(so_ + 16384,  Vh + grow + i_ * 8); \
        cp16(so_ + 24576,  Vl + grow + i_ * 8); \
    } \
    asm volatile("cp.async.commit_group;" ::: "memory"); \
} while (0)

    ISSUE(0, 0);

    const int krow = (lane & 7) + (lane >> 4) * 8;
    const int kkb  = (lane >> 3) & 1;
    const int vrow = (lane & 7) + ((lane >> 3) & 1) * 8;
    const int vdb  = (lane >> 4);

    for (int kt = 0; kt < 32; kt++) {
        const int buf = kt & 1;
        if (kt < 31) {
            ISSUE(kt + 1, buf ^ 1);
            asm volatile("cp.async.wait_group 1;" ::: "memory");
        } else {
            asm volatile("cp.async.wait_group 0;" ::: "memory");
        }
        __syncthreads();

        const uint32_t kb_hi = kvb + buf * 32768;

        // --- S = Q K^T ---
        float s[8][4];
#pragma unroll
        for (int j = 0; j < 8; j++)
#pragma unroll
            for (int e = 0; e < 4; e++) s[j][e] = 0.f;

#pragma unroll
        for (int ng = 0; ng < 4; ng++) {
            const int r = ng * 16 + krow;
            const uint32_t rbase = kb_hi + r * 128;
#pragma unroll
            for (int ks = 0; ks < 4; ks++) {
                const int kb = ks * 2 + kkb;
                const uint32_t off = rbase + (uint32_t)((kb ^ (r & 7)) * 16);
                uint32_t bh4[4], bl4[4];
                ldsm4(bh4, off);
                ldsm4(bl4, off + 8192);
                mma16816(s[ng * 2],     qh[ks], &bh4[0]);
                mma16816(s[ng * 2],     qh[ks], &bl4[0]);
                mma16816(s[ng * 2],     ql[ks], &bh4[0]);
                mma16816(s[ng * 2 + 1], qh[ks], &bh4[2]);
                mma16816(s[ng * 2 + 1], qh[ks], &bl4[2]);
                mma16816(s[ng * 2 + 1], ql[ks], &bh4[2]);
            }
        }

        // --- online softmax (exp2 domain) ---
        const float SC = 0.125f * 1.4426950408889634f;
#pragma unroll
        for (int hf = 0; hf < 2; hf++) {
            float mx = -1e30f;
#pragma unroll
            for (int j = 0; j < 8; j++) {
                s[j][hf * 2]     *= SC;
                s[j][hf * 2 + 1] *= SC;
                mx = fmaxf(mx, fmaxf(s[j][hf * 2], s[j][hf * 2 + 1]));
            }
            mx = fmaxf(mx, __shfl_xor_sync(0xffffffffu, mx, 1));
            mx = fmaxf(mx, __shfl_xor_sync(0xffffffffu, mx, 2));
            const float mnew  = fmaxf(mrun[hf], mx);
            const float alpha = exp2f(mrun[hf] - mnew);
            mrun[hf] = mnew;
            float sum = 0.f;
#pragma unroll
            for (int j = 0; j < 8; j++) {
                const float p0 = exp2f(s[j][hf * 2]     - mnew);
                const float p1 = exp2f(s[j][hf * 2 + 1] - mnew);
                s[j][hf * 2]     = p0;
                s[j][hf * 2 + 1] = p1;
                sum += p0 + p1;
            }
            sum += __shfl_xor_sync(0xffffffffu, sum, 1);
            sum += __shfl_xor_sync(0xffffffffu, sum, 2);
            lrun[hf] = lrun[hf] * alpha + sum;
#pragma unroll
            for (int j = 0; j < 8; j++) {
                o[j][hf * 2]     *= alpha;
                o[j][hf * 2 + 1] *= alpha;
            }
        }

        // --- O += P V ---
#pragma unroll
        for (int t = 0; t < 4; t++) {
            uint32_t pah[4], pal[4];
#pragma unroll
            for (int e = 0; e < 2; e++) {
                const float f0 = s[2 * t + e][0], f1 = s[2 * t + e][1];
                const float f2 = s[2 * t + e][2], f3 = s[2 * t + e][3];
                const __nv_bfloat16 h0 = __float2bfloat16(f0);
                const __nv_bfloat16 h1 = __float2bfloat16(f1);
                const __nv_bfloat16 h2 = __float2bfloat16(f2);
                const __nv_bfloat16 h3 = __float2bfloat16(f3);
                pah[e * 2 + 0] = pack2(h0, h1);
                pah[e * 2 + 1] = pack2(h2, h3);
                pal[e * 2 + 0] = pack2(__float2bfloat16(f0 - __bfloat162float(h0)),
                                       __float2bfloat16(f1 - __bfloat162float(h1)));
                pal[e * 2 + 1] = pack2(__float2bfloat16(f2 - __bfloat162float(h2)),
                                       __float2bfloat16(f3 - __bfloat162float(h3)));
            }

            const int r = t * 16 + vrow;
            const uint32_t rbase = kb_hi + 16384 + r * 128;
#pragma unroll
            for (int dg = 0; dg < 4; dg++) {
                const int db = dg * 2 + vdb;
                const uint32_t off = rbase + (uint32_t)((db ^ (r & 7)) * 16);
                uint32_t vh4[4], vl4[4];
                ldsm4t(vh4, off);
                ldsm4t(vl4, off + 8192);
                mma16816(o[dg * 2],     pah, &vh4[0]);
                mma16816(o[dg * 2],     pal, &vh4[0]);
                mma16816(o[dg * 2],     pah, &vl4[0]);
                mma16816(o[dg * 2 + 1], pah, &vh4[2]);
                mma16816(o[dg * 2 + 1], pal, &vh4[2]);
                mma16816(o[dg * 2 + 1], pah, &vl4[2]);
            }
        }
        __syncthreads();
    }
#undef ISSUE

    // --- epilogue ---
    const int bb  = bh >> 4;
    const int hh_ = bh & 15;
#pragma unroll
    for (int half = 0; half < 2; half++) {
        const int r = q0 + warp * 16 + gID + half * 8;
        const float inv = 1.0f / lrun[half];
#pragma unroll
        for (int j = 0; j < 8; j++) {
            const float f0 = o[j][half * 2 + 0] * inv;
            const float f1 = o[j][half * 2 + 1] * inv;
            const __nv_bfloat16 h0 = __float2bfloat16(f0);
            const __nv_bfloat16 h1 = __float2bfloat16(f1);
            const __nv_bfloat16 l0 = __float2bfloat16(f0 - __bfloat162float(h0));
            const __nv_bfloat16 l1 = __float2bfloat16(f1 - __bfloat162float(h1));
            const size_t idx = ((size_t)(r * BATCH + bb)) * DMODEL + hh_ * DK + j * 8 + tg * 2;
            *(__nv_bfloat162*)&g_Ahi[idx] = __halves2bfloat162(h0, h1);
            *(__nv_bfloat162*)&g_Alo[idx] = __halves2bfloat162(l0, l1);
        }
    }
}

// ---------------------------------------------------------------------------
extern "C" void kernel_launch(void* const* d_in, const int* in_sizes, int n_in,
                              void* d_out, int out_size)
{
    const float* q     = (const float*)d_in[0];
    const float* k     = (const float*)d_in[1];
    const float* v     = (const float*)d_in[2];
    const float* in_w  = (const float*)d_in[3];
    const float* in_b  = (const float*)d_in[4];
    const float* out_w = (const float*)d_in[5];
    const float* out_b = (const float*)d_in[6];
    float* out = (float*)d_out;

    static bool attr_done = false;
    if (!attr_done) {
        cudaFuncSetAttribute(attn_mma, cudaFuncAttributeMaxDynamicSharedMemorySize, AT_SMEM);
        cudaFuncSetAttribute(gemm_mma, cudaFuncAttributeMaxDynamicSharedMemorySize, GB_SMEM);
        attr_done = true;
    }

    const int nX4 = MROWS * DMODEL / 4;
    cvt_kernel<<<nX4 / 256, 256>>>(q, 0, 0L, nX4);
    cvt_kernel<<<nX4 / 256, 256>>>(k, 0, (long)MROWS * DMODEL, nX4);
    cvt_kernel<<<nX4 / 256, 256>>>(v, 0, 2L * MROWS * DMODEL, nX4);
    const int nW4 = 3 * DMODEL * DMODEL / 4;
    cvt_kernel<<<nW4 / 256, 256>>>(in_w, 1, 0L, nW4);
    const int nO4 = DMODEL * DMODEL / 4;
    cvt_kernel<<<nO4 / 256, 256>>>(out_w, 2, 0L, nO4);

    dim3 gQKV(DMODEL / 128, MROWS / 128, 3);
    gemm_mma<<<gQKV, 256, GB_SMEM>>>(in_b, out, 0);

    dim3 gAttn(SEQ / 128, BH);
    attn_mma<<<gAttn, 256, AT_SMEM>>>();

    dim3 gOut(DMODEL / 128, MROWS / 128, 1);
    gemm_mma<<<gOut, 256, GB_SMEM>>>(out_b, out, 1);
}

// round 7
// speedup vs baseline: 5.0869x; 1.3790x over previous
#include <cuda_runtime.h>
#include <cuda_fp16.h>
#include <cstdint>

// ---------------------------------------------------------------------------
// Problem constants
// ---------------------------------------------------------------------------
#define SEQ     2048
#define BATCH   2
#define DMODEL  1024
#define NHEADS  16
#define DK      64
#define BH      (BATCH*NHEADS)   // 32
#define MROWS   (SEQ*BATCH)      // 4096

// ---------------------------------------------------------------------------
// Device scratch
// ---------------------------------------------------------------------------
__device__ __half g_Qf [BH * SEQ * DK];     // Q rounded fp16
__device__ __half g_Khi[BH * SEQ * DK];     // K split fp16
__device__ __half g_Klo[BH * SEQ * DK];
__device__ __half g_Vf [BH * SEQ * DK];     // V rounded fp16

__device__ __half g_Xf [3 * MROWS * DMODEL];  // X rounded fp16
__device__ __half g_Whi[3 * DMODEL * DMODEL]; // in_proj_w split
__device__ __half g_Wlo[3 * DMODEL * DMODEL];
__device__ __half g_OWhi[DMODEL * DMODEL];    // out_proj_w split
__device__ __half g_OWlo[DMODEL * DMODEL];
__device__ __half g_Af [MROWS * DMODEL];      // attention out rounded fp16

// ---------------------------------------------------------------------------
// Helpers
// ---------------------------------------------------------------------------
__device__ __forceinline__ uint32_t smem_u32(const void* p) {
    uint32_t r;
    asm("{ .reg .u64 t; cvta.to.shared.u64 t, %1; cvt.u32.u64 %0, t; }"
        : "=r"(r) : "l"(p));
    return r;
}

__device__ __forceinline__ void ldsm4(uint32_t* r, uint32_t addr) {
    asm volatile("ldmatrix.sync.aligned.m8n8.x4.shared.b16 {%0,%1,%2,%3}, [%4];"
                 : "=r"(r[0]), "=r"(r[1]), "=r"(r[2]), "=r"(r[3]) : "r"(addr));
}

__device__ __forceinline__ void ldsm4t(uint32_t* r, uint32_t addr) {
    asm volatile("ldmatrix.sync.aligned.m8n8.x4.trans.shared.b16 {%0,%1,%2,%3}, [%4];"
                 : "=r"(r[0]), "=r"(r[1]), "=r"(r[2]), "=r"(r[3]) : "r"(addr));
}

__device__ __forceinline__ void mma16816(float* c, const uint32_t* a, const uint32_t* b) {
    asm volatile(
        "mma.sync.aligned.m16n8k16.row.col.f32.f16.f16.f32 "
        "{%0,%1,%2,%3}, {%4,%5,%6,%7}, {%8,%9}, {%0,%1,%2,%3};"
        : "+f"(c[0]), "+f"(c[1]), "+f"(c[2]), "+f"(c[3])
        : "r"(a[0]), "r"(a[1]), "r"(a[2]), "r"(a[3]), "r"(b[0]), "r"(b[1]));
}

__device__ __forceinline__ void cp16(uint32_t d, const void* s) {
    asm volatile("cp.async.cg.shared.global [%0], [%1], 16;" :: "r"(d), "l"(s));
}

__device__ __forceinline__ uint32_t pack2h(__half a, __half b) {
    __half2 t = __halves2half2(a, b);
    return *(uint32_t*)&t;
}

// ---------------------------------------------------------------------------
// Kernel 0: one fused conversion kernel.
// job 0/1/2: q/k/v -> g_Xf (single fp16). job 3: in_w -> Whi/Wlo split.
// job 4: out_w -> OWhi/OWlo split. grid = (4096, 5)
// ---------------------------------------------------------------------------
__global__ __launch_bounds__(256)
void cvt_all(const float* __restrict__ q, const float* __restrict__ k,
             const float* __restrict__ v, const float* __restrict__ in_w,
             const float* __restrict__ out_w)
{
    const int job = blockIdx.y;
    const int i = blockIdx.x * 256 + threadIdx.x;
    if (job < 3) {
        const int n4 = MROWS * DMODEL / 4;
        if (i >= n4) return;
        const float* src = (job == 0) ? q : (job == 1) ? k : v;
        float4 x = ((const float4*)src)[i];
        __half2* d = (__half2*)(g_Xf + (size_t)job * MROWS * DMODEL);
        d[2 * i]     = __halves2half2(__float2half_rn(x.x), __float2half_rn(x.y));
        d[2 * i + 1] = __halves2half2(__float2half_rn(x.z), __float2half_rn(x.w));
    } else {
        const int n4 = (job == 3) ? 3 * DMODEL * DMODEL / 4 : DMODEL * DMODEL / 4;
        if (i >= n4) return;
        const float* src = (job == 3) ? in_w : out_w;
        __half* hi = (job == 3) ? g_Whi : g_OWhi;
        __half* lo = (job == 3) ? g_Wlo : g_OWlo;
        float4 x = ((const float4*)src)[i];
        __half h0 = __float2half_rn(x.x), h1 = __float2half_rn(x.y);
        __half h2 = __float2half_rn(x.z), h3 = __float2half_rn(x.w);
        __half l0 = __float2half_rn(x.x - __half2float(h0));
        __half l1 = __float2half_rn(x.y - __half2float(h1));
        __half l2 = __float2half_rn(x.z - __half2float(h2));
        __half l3 = __float2half_rn(x.w - __half2float(h3));
        ((__half2*)hi)[2 * i]     = __halves2half2(h0, h1);
        ((__half2*)hi)[2 * i + 1] = __halves2half2(h2, h3);
        ((__half2*)lo)[2 * i]     = __halves2half2(l0, l1);
        ((__half2*)lo)[2 * i + 1] = __halves2half2(l2, l3);
    }
}

// ---------------------------------------------------------------------------
// Kernel 1: fp16 2-product HMMA GEMM, 128x128 CTA tile, 256 threads.
// D = Af @ (Bh + Bl)^T + bias.  K-chunk 32, 3-stage cp.async pipeline.
// mode 0: qkv (p=0 -> Qf, p=1 -> Khi/Klo, p=2 -> Vf, head-major)
// mode 1: out (fp32 linear to dst)
// ---------------------------------------------------------------------------
#define GSTAGE  24576   // Af 8KB + Bh 8KB + Bl 8KB
#define GB_SMEM (3 * GSTAGE)

__global__ __launch_bounds__(256, 1)
void gemm_mma(const float* __restrict__ bias_in, float* __restrict__ dst, int mode)
{
    extern __shared__ char gsm[];
    const uint32_t sbase = smem_u32(gsm);

    const int tid  = threadIdx.x;
    const int lane = tid & 31;
    const int wid  = tid >> 5;
    const int wm   = wid & 1;
    const int wn   = wid >> 1;
    const int p    = blockIdx.z;
    const int n0   = blockIdx.x * 128;
    const int m0   = blockIdx.y * 128;

    const __half *Afp, *Bh, *Bl;
    if (mode == 0) {
        Afp = g_Xf  + (size_t)p * MROWS * DMODEL;
        Bh  = g_Whi + (size_t)p * DMODEL * DMODEL;
        Bl  = g_Wlo + (size_t)p * DMODEL * DMODEL;
    } else {
        Afp = g_Af; Bh = g_OWhi; Bl = g_OWlo;
    }
    const float* bptr = bias_in + p * DMODEL;

    // loader: thread -> row (0..127), 2 16B-blocks (64B rows, 4 blocks)
    const int lrow = tid >> 1;
    const int lc0  = (tid & 1) * 2;
    const uint32_t soff0 = (uint32_t)(lrow * 64 + (((lc0)     ^ ((lrow >> 1) & 3)) * 16));
    const uint32_t soff1 = (uint32_t)(lrow * 64 + (((lc0 + 1) ^ ((lrow >> 1) & 3)) * 16));
    const size_t aoff = (size_t)(m0 + lrow) * DMODEL + lc0 * 8;
    const size_t boff = (size_t)(n0 + lrow) * DMODEL + lc0 * 8;

#define GISSUE(kc, st) do { \
    const size_t ko = (size_t)(kc) * 32; \
    const uint32_t sb_ = sbase + (st) * GSTAGE; \
    cp16(sb_         + soff0, Afp + aoff + ko);     \
    cp16(sb_         + soff1, Afp + aoff + ko + 8); \
    cp16(sb_ + 8192  + soff0, Bh + boff + ko);      \
    cp16(sb_ + 8192  + soff1, Bh + boff + ko + 8);  \
    cp16(sb_ + 16384 + soff0, Bl + boff + ko);      \
    cp16(sb_ + 16384 + soff1, Bl + boff + ko + 8);  \
    asm volatile("cp.async.commit_group;" ::: "memory"); \
} while (0)

    const int arow = (lane & 7) + ((lane >> 3) & 1) * 8;   // + wm*64 + mf*16
    const int akb  = (lane >> 4);
    const int brow = (lane & 7) + (lane >> 4) * 8;         // + wn*32 + nq*16
    const int bkb  = ((lane >> 3) & 1);

    float acc[4][4][4];
#pragma unroll
    for (int i = 0; i < 4; i++)
#pragma unroll
        for (int j = 0; j < 4; j++)
#pragma unroll
            for (int e = 0; e < 4; e++) acc[i][j][e] = 0.f;

    GISSUE(0, 0);
    GISSUE(1, 1);

    for (int kc = 0; kc < 32; kc++) {
        const int st = kc % 3;
        if (kc < 30) {
            asm volatile("cp.async.wait_group 1;" ::: "memory");
        } else {
            asm volatile("cp.async.wait_group 0;" ::: "memory");
        }
        __syncthreads();
        if (kc + 2 < 32) GISSUE(kc + 2, (kc + 2) % 3);

        const uint32_t bufb = sbase + st * GSTAGE;
#pragma unroll
        for (int ks = 0; ks < 2; ks++) {
            uint32_t af[4][4];
#pragma unroll
            for (int mf = 0; mf < 4; mf++) {
                const int r  = wm * 64 + mf * 16 + arow;
                const int kb = ks * 2 + akb;
                const uint32_t off = (uint32_t)(r * 64 + ((kb ^ ((r >> 1) & 3)) * 16));
                ldsm4(af[mf], bufb + off);
            }
            uint32_t bfh[2][4], bfl[2][4];
#pragma unroll
            for (int nq = 0; nq < 2; nq++) {
                const int r  = wn * 32 + nq * 16 + brow;
                const int kb = ks * 2 + bkb;
                const uint32_t off = (uint32_t)(r * 64 + ((kb ^ ((r >> 1) & 3)) * 16));
                ldsm4(bfh[nq], bufb + 8192 + off);
                ldsm4(bfl[nq], bufb + 16384 + off);
            }
#pragma unroll
            for (int mf = 0; mf < 4; mf++)
#pragma unroll
                for (int nf = 0; nf < 4; nf++) {
                    mma16816(acc[mf][nf], af[mf], &bfh[nf >> 1][(nf & 1) * 2]);
                    mma16816(acc[mf][nf], af[mf], &bfl[nf >> 1][(nf & 1) * 2]);
                }
        }
    }
#undef GISSUE
    __syncthreads();

    // --- epilogue
    const int gID = lane >> 2;
    const int tg  = lane & 3;
#pragma unroll
    for (int mf = 0; mf < 4; mf++) {
#pragma unroll
        for (int nf = 0; nf < 4; nf++) {
            const int n = n0 + wn * 32 + nf * 8 + tg * 2;
            const float bx = bptr[n], by = bptr[n + 1];
#pragma unroll
            for (int half = 0; half < 2; half++) {
                const int m = m0 + wm * 64 + mf * 16 + gID + half * 8;
                const float fx = acc[mf][nf][half * 2 + 0] + bx;
                const float fy = acc[mf][nf][half * 2 + 1] + by;
                if (mode == 0) {
                    const int s  = m >> 1;
                    const int bb = m & 1;
                    const int h  = n >> 6;
                    const int j  = n & 63;
                    const size_t idx = (((size_t)(bb * NHEADS + h)) * SEQ + s) * DK + j;
                    if (p == 1) {
                        __half hx = __float2half_rn(fx);
                        __half hy = __float2half_rn(fy);
                        __half lx = __float2half_rn(fx - __half2float(hx));
                        __half ly = __float2half_rn(fy - __half2float(hy));
                        *(__half2*)&g_Khi[idx] = __halves2half2(hx, hy);
                        *(__half2*)&g_Klo[idx] = __halves2half2(lx, ly);
                    } else {
                        __half* D = (p == 0) ? g_Qf : g_Vf;
                        *(__half2*)&D[idx] =
                            __halves2half2(__float2half_rn(fx), __float2half_rn(fy));
                    }
                } else {
                    float2 v; v.x = fx; v.y = fy;
                    *(float2*)&dst[(size_t)m * DMODEL + n] = v;
                }
            }
        }
    }
}

// ---------------------------------------------------------------------------
// Kernel 2: fp16 2-product HMMA flash attention.
// CTA = (128 q-rows, one bh). 8 warps x m16. K-tile 64, 3-stage cp.async.
// S = Qf (Kh+Kl)^T ; O += (Ph+Pl) Vf.
// grid = (SEQ/128, BH), block 256.
// ---------------------------------------------------------------------------
#define ASTAGE  24576   // Kh 8KB + Kl 8KB + Vf 8KB
#define AT_SMEM (3 * ASTAGE)

__global__ __launch_bounds__(256, 1)
void attn_mma()
{
    extern __shared__ char kvsm[];
    const uint32_t kvb = smem_u32(kvsm);
    const int tid  = threadIdx.x;
    const int lane = tid & 31;
    const int warp = tid >> 5;
    const int gID  = lane >> 2;
    const int tg   = lane & 3;
    const int q0   = blockIdx.x * 128;
    const int bh   = blockIdx.y;

    const __half* Kh = g_Khi + (size_t)bh * SEQ * DK;
    const __half* Kl = g_Klo + (size_t)bh * SEQ * DK;
    const __half* Vf = g_Vf  + (size_t)bh * SEQ * DK;

    // Q fragments (single fp16, persistent)
    uint32_t qf[4][4];
    {
        const __half* Q = g_Qf + ((size_t)bh * SEQ + q0 + warp * 16) * DK;
#pragma unroll
        for (int ks = 0; ks < 4; ks++) {
            const int c = ks * 16 + tg * 2;
            qf[ks][0] = *(const uint32_t*)&Q[(gID)     * DK + c];
            qf[ks][1] = *(const uint32_t*)&Q[(gID + 8) * DK + c];
            qf[ks][2] = *(const uint32_t*)&Q[(gID)     * DK + c + 8];
            qf[ks][3] = *(const uint32_t*)&Q[(gID + 8) * DK + c + 8];
        }
    }

    float o[8][4];
#pragma unroll
    for (int j = 0; j < 8; j++)
#pragma unroll
        for (int e = 0; e < 4; e++) o[j][e] = 0.f;
    float mrun[2] = {-1e30f, -1e30f};
    float lrun[2] = {0.f, 0.f};

    // loader: 64 rows x 8 blocks (128B rows) x 3 arrays; 6 cp16/thread
    const int lrow = tid >> 2;            // 0..63
    const int lc0  = (tid & 3) * 2;       // 0,2,4,6

#define ISSUE(kt, st) do { \
    const size_t grow = ((size_t)((kt) * 64 + lrow)) * DK + lc0 * 8; \
    const uint32_t sb_ = kvb + (st) * ASTAGE + lrow * 128; \
    _Pragma("unroll") \
    for (int i_ = 0; i_ < 2; i_++) { \
        const int blk_ = lc0 + i_; \
        const uint32_t so_ = sb_ + (uint32_t)((blk_ ^ (lrow & 7)) * 16); \
        cp16(so_,          Kh + grow + i_ * 8); \
        cp16(so_ + 8192,   Kl + grow + i_ * 8); \
        cp16(so_ + 16384,  Vf + grow + i_ * 8); \
    } \
    asm volatile("cp.async.commit_group;" ::: "memory"); \
} while (0)

    ISSUE(0, 0);
    ISSUE(1, 1);

    const int krow = (lane & 7) + (lane >> 4) * 8;
    const int kkb  = (lane >> 3) & 1;
    const int vrow = (lane & 7) + ((lane >> 3) & 1) * 8;
    const int vdb  = (lane >> 4);

    for (int kt = 0; kt < 32; kt++) {
        const int st = kt % 3;
        if (kt < 30) {
            asm volatile("cp.async.wait_group 1;" ::: "memory");
        } else {
            asm volatile("cp.async.wait_group 0;" ::: "memory");
        }
        __syncthreads();
        if (kt + 2 < 32) ISSUE(kt + 2, (kt + 2) % 3);

        const uint32_t stage = kvb + st * ASTAGE;

        // --- S = Qf (Kh+Kl)^T ---
        float s[8][4];
#pragma unroll
        for (int j = 0; j < 8; j++)
#pragma unroll
            for (int e = 0; e < 4; e++) s[j][e] = 0.f;

#pragma unroll
        for (int ng = 0; ng < 4; ng++) {
            const int r = ng * 16 + krow;
            const uint32_t rbase = stage + r * 128;
#pragma unroll
            for (int ks = 0; ks < 4; ks++) {
                const int kb = ks * 2 + kkb;
                const uint32_t off = rbase + (uint32_t)((kb ^ (r & 7)) * 16);
                uint32_t kh4[4], kl4[4];
                ldsm4(kh4, off);
                ldsm4(kl4, off + 8192);
                mma16816(s[ng * 2],     qf[ks], &kh4[0]);
                mma16816(s[ng * 2],     qf[ks], &kl4[0]);
                mma16816(s[ng * 2 + 1], qf[ks], &kh4[2]);
                mma16816(s[ng * 2 + 1], qf[ks], &kl4[2]);
            }
        }

        // --- online softmax (exp2 domain) ---
        const float SC = 0.125f * 1.4426950408889634f;
#pragma unroll
        for (int hf = 0; hf < 2; hf++) {
            float mx = -1e30f;
#pragma unroll
            for (int j = 0; j < 8; j++) {
                s[j][hf * 2]     *= SC;
                s[j][hf * 2 + 1] *= SC;
                mx = fmaxf(mx, fmaxf(s[j][hf * 2], s[j][hf * 2 + 1]));
            }
            mx = fmaxf(mx, __shfl_xor_sync(0xffffffffu, mx, 1));
            mx = fmaxf(mx, __shfl_xor_sync(0xffffffffu, mx, 2));
            const float mnew  = fmaxf(mrun[hf], mx);
            const float alpha = exp2f(mrun[hf] - mnew);
            mrun[hf] = mnew;
            float sum = 0.f;
#pragma unroll
            for (int j = 0; j < 8; j++) {
                const float p0 = exp2f(s[j][hf * 2]     - mnew);
                const float p1 = exp2f(s[j][hf * 2 + 1] - mnew);
                s[j][hf * 2]     = p0;
                s[j][hf * 2 + 1] = p1;
                sum += p0 + p1;
            }
            sum += __shfl_xor_sync(0xffffffffu, sum, 1);
            sum += __shfl_xor_sync(0xffffffffu, sum, 2);
            lrun[hf] = lrun[hf] * alpha + sum;
#pragma unroll
            for (int j = 0; j < 8; j++) {
                o[j][hf * 2]     *= alpha;
                o[j][hf * 2 + 1] *= alpha;
            }
        }

        // --- O += (Ph + Pl) Vf ---
#pragma unroll
        for (int t = 0; t < 4; t++) {
            uint32_t pah[4], pal[4];
#pragma unroll
            for (int e = 0; e < 2; e++) {
                const float f0 = s[2 * t + e][0], f1 = s[2 * t + e][1];
                const float f2 = s[2 * t + e][2], f3 = s[2 * t + e][3];
                const __half h0 = __float2half_rn(f0);
                const __half h1 = __float2half_rn(f1);
                const __half h2 = __float2half_rn(f2);
                const __half h3 = __float2half_rn(f3);
                pah[e * 2 + 0] = pack2h(h0, h1);
                pah[e * 2 + 1] = pack2h(h2, h3);
                pal[e * 2 + 0] = pack2h(__float2half_rn(f0 - __half2float(h0)),
                                        __float2half_rn(f1 - __half2float(h1)));
                pal[e * 2 + 1] = pack2h(__float2half_rn(f2 - __half2float(h2)),
                                        __float2half_rn(f3 - __half2float(h3)));
            }

            const int r = t * 16 + vrow;
            const uint32_t rbase = stage + 16384 + r * 128;
#pragma unroll
            for (int dg = 0; dg < 4; dg++) {
                const int db = dg * 2 + vdb;
                const uint32_t off = rbase + (uint32_t)((db ^ (r & 7)) * 16);
                uint32_t vf4[4];
                ldsm4t(vf4, off);
                mma16816(o[dg * 2],     pah, &vf4[0]);
                mma16816(o[dg * 2],     pal, &vf4[0]);
                mma16816(o[dg * 2 + 1], pah, &vf4[2]);
                mma16816(o[dg * 2 + 1], pal, &vf4[2]);
            }
        }
    }
#undef ISSUE

    // --- epilogue: normalize, round to fp16, write g_Af ---
    const int bb  = bh >> 4;
    const int hh_ = bh & 15;
#pragma unroll
    for (int half = 0; half < 2; half++) {
        const int r = q0 + warp * 16 + gID + half * 8;
        const float inv = 1.0f / lrun[half];
#pragma unroll
        for (int j = 0; j < 8; j++) {
            const float f0 = o[j][half * 2 + 0] * inv;
            const float f1 = o[j][half * 2 + 1] * inv;
            const size_t idx = ((size_t)(r * BATCH + bb)) * DMODEL + hh_ * DK + j * 8 + tg * 2;
            *(__half2*)&g_Af[idx] =
                __halves2half2(__float2half_rn(f0), __float2half_rn(f1));
        }
    }
}

// ---------------------------------------------------------------------------
extern "C" void kernel_launch(void* const* d_in, const int* in_sizes, int n_in,
                              void* d_out, int out_size)
{
    const float* q     = (const float*)d_in[0];
    const float* k     = (const float*)d_in[1];
    const float* v     = (const float*)d_in[2];
    const float* in_w  = (const float*)d_in[3];
    const float* in_b  = (const float*)d_in[4];
    const float* out_w = (const float*)d_in[5];
    const float* out_b = (const float*)d_in[6];
    float* out = (float*)d_out;

    static bool attr_done = false;
    if (!attr_done) {
        cudaFuncSetAttribute(attn_mma, cudaFuncAttributeMaxDynamicSharedMemorySize, AT_SMEM);
        cudaFuncSetAttribute(gemm_mma, cudaFuncAttributeMaxDynamicSharedMemorySize, GB_SMEM);
        attr_done = true;
    }

    cvt_all<<<dim3(4096, 5), 256>>>(q, k, v, in_w, out_w);

    dim3 gQKV(DMODEL / 128, MROWS / 128, 3);
    gemm_mma<<<gQKV, 256, GB_SMEM>>>(in_b, out, 0);

    dim3 gAttn(SEQ / 128, BH);
    attn_mma<<<gAttn, 256, AT_SMEM>>>();

    dim3 gOut(DMODEL / 128, MROWS / 128, 1);
    gemm_mma<<<gOut, 256, GB_SMEM>>>(out_b, out, 1);
}

// round 8
// speedup vs baseline: 5.7224x; 1.1249x over previous
#include <cuda_runtime.h>
#include <cuda_fp16.h>
#include <cstdint>

// ---------------------------------------------------------------------------
// Problem constants
// ---------------------------------------------------------------------------
#define SEQ     2048
#define BATCH   2
#define DMODEL  1024
#define NHEADS  16
#define DK      64
#define BH      (BATCH*NHEADS)   // 32
#define MROWS   (SEQ*BATCH)      // 4096

// ---------------------------------------------------------------------------
// Device scratch
// ---------------------------------------------------------------------------
__device__ __half g_Qf [BH * SEQ * DK];     // Q rounded fp16
__device__ __half g_Khi[BH * SEQ * DK];     // K split fp16
__device__ __half g_Klo[BH * SEQ * DK];
__device__ __half g_Vf [BH * SEQ * DK];     // V rounded fp16

__device__ __half g_Xf [3 * MROWS * DMODEL];  // X rounded fp16
__device__ __half g_Whi[3 * DMODEL * DMODEL]; // in_proj_w split
__device__ __half g_Wlo[3 * DMODEL * DMODEL];
__device__ __half g_OWhi[DMODEL * DMODEL];    // out_proj_w split
__device__ __half g_OWlo[DMODEL * DMODEL];
__device__ __half g_Af [MROWS * DMODEL];      // attention out rounded fp16

// ---------------------------------------------------------------------------
// Helpers
// ---------------------------------------------------------------------------
__device__ __forceinline__ uint32_t smem_u32(const void* p) {
    uint32_t r;
    asm("{ .reg .u64 t; cvta.to.shared.u64 t, %1; cvt.u32.u64 %0, t; }"
        : "=r"(r) : "l"(p));
    return r;
}

__device__ __forceinline__ void ldsm4(uint32_t* r, uint32_t addr) {
    asm volatile("ldmatrix.sync.aligned.m8n8.x4.shared.b16 {%0,%1,%2,%3}, [%4];"
                 : "=r"(r[0]), "=r"(r[1]), "=r"(r[2]), "=r"(r[3]) : "r"(addr));
}

__device__ __forceinline__ void ldsm4t(uint32_t* r, uint32_t addr) {
    asm volatile("ldmatrix.sync.aligned.m8n8.x4.trans.shared.b16 {%0,%1,%2,%3}, [%4];"
                 : "=r"(r[0]), "=r"(r[1]), "=r"(r[2]), "=r"(r[3]) : "r"(addr));
}

__device__ __forceinline__ void mma16816(float* c, const uint32_t* a, const uint32_t* b) {
    asm volatile(
        "mma.sync.aligned.m16n8k16.row.col.f32.f16.f16.f32 "
        "{%0,%1,%2,%3}, {%4,%5,%6,%7}, {%8,%9}, {%0,%1,%2,%3};"
        : "+f"(c[0]), "+f"(c[1]), "+f"(c[2]), "+f"(c[3])
        : "r"(a[0]), "r"(a[1]), "r"(a[2]), "r"(a[3]), "r"(b[0]), "r"(b[1]));
}

__device__ __forceinline__ void cp16(uint32_t d, const void* s) {
    asm volatile("cp.async.cg.shared.global [%0], [%1], 16;" :: "r"(d), "l"(s));
}

__device__ __forceinline__ uint32_t pack2h(__half a, __half b) {
    __half2 t = __halves2half2(a, b);
    return *(uint32_t*)&t;
}

// ---------------------------------------------------------------------------
// Kernel 0: fused conversion. jobs 0-2: q/k/v -> g_Xf fp16; 3: in_w split;
// 4: out_w split. grid = (4096, 5)
// ---------------------------------------------------------------------------
__global__ __launch_bounds__(256)
void cvt_all(const float* __restrict__ q, const float* __restrict__ k,
             const float* __restrict__ v, const float* __restrict__ in_w,
             const float* __restrict__ out_w)
{
    const int job = blockIdx.y;
    const int i = blockIdx.x * 256 + threadIdx.x;
    if (job < 3) {
        const int n4 = MROWS * DMODEL / 4;
        if (i >= n4) return;
        const float* src = (job == 0) ? q : (job == 1) ? k : v;
        float4 x = ((const float4*)src)[i];
        __half2* d = (__half2*)(g_Xf + (size_t)job * MROWS * DMODEL);
        d[2 * i]     = __halves2half2(__float2half_rn(x.x), __float2half_rn(x.y));
        d[2 * i + 1] = __halves2half2(__float2half_rn(x.z), __float2half_rn(x.w));
    } else {
        const int n4 = (job == 3) ? 3 * DMODEL * DMODEL / 4 : DMODEL * DMODEL / 4;
        if (i >= n4) return;
        const float* src = (job == 3) ? in_w : out_w;
        __half* hi = (job == 3) ? g_Whi : g_OWhi;
        __half* lo = (job == 3) ? g_Wlo : g_OWlo;
        float4 x = ((const float4*)src)[i];
        __half h0 = __float2half_rn(x.x), h1 = __float2half_rn(x.y);
        __half h2 = __float2half_rn(x.z), h3 = __float2half_rn(x.w);
        __half l0 = __float2half_rn(x.x - __half2float(h0));
        __half l1 = __float2half_rn(x.y - __half2float(h1));
        __half l2 = __float2half_rn(x.z - __half2float(h2));
        __half l3 = __float2half_rn(x.w - __half2float(h3));
        ((__half2*)hi)[2 * i]     = __halves2half2(h0, h1);
        ((__half2*)hi)[2 * i + 1] = __halves2half2(h2, h3);
        ((__half2*)lo)[2 * i]     = __halves2half2(l0, l1);
        ((__half2*)lo)[2 * i + 1] = __halves2half2(l2, l3);
    }
}

// ---------------------------------------------------------------------------
// Kernel 1: fp16 2-product HMMA GEMM, 128x128 CTA tile, 256 threads,
// __launch_bounds__(256,2) -> <=128 regs -> 2 CTAs/SM.
// ---------------------------------------------------------------------------
#define GSTAGE  24576   // Af 8KB + Bh 8KB + Bl 8KB
#define GB_SMEM (3 * GSTAGE)

__global__ __launch_bounds__(256, 2)
void gemm_mma(const float* __restrict__ bias_in, float* __restrict__ dst, int mode)
{
    extern __shared__ char gsm[];
    const uint32_t sbase = smem_u32(gsm);

    const int tid  = threadIdx.x;
    const int lane = tid & 31;
    const int wid  = tid >> 5;
    const int wm   = wid & 1;
    const int wn   = wid >> 1;
    const int p    = blockIdx.z;
    const int n0   = blockIdx.x * 128;
    const int m0   = blockIdx.y * 128;

    const __half *Afp, *Bh, *Bl;
    if (mode == 0) {
        Afp = g_Xf  + (size_t)p * MROWS * DMODEL;
        Bh  = g_Whi + (size_t)p * DMODEL * DMODEL;
        Bl  = g_Wlo + (size_t)p * DMODEL * DMODEL;
    } else {
        Afp = g_Af; Bh = g_OWhi; Bl = g_OWlo;
    }
    const float* bptr = bias_in + p * DMODEL;

    const int lrow = tid >> 1;
    const int lc0  = (tid & 1) * 2;
    const uint32_t soff0 = (uint32_t)(lrow * 64 + (((lc0)     ^ ((lrow >> 1) & 3)) * 16));
    const uint32_t soff1 = (uint32_t)(lrow * 64 + (((lc0 + 1) ^ ((lrow >> 1) & 3)) * 16));
    const size_t aoff = (size_t)(m0 + lrow) * DMODEL + lc0 * 8;
    const size_t boff = (size_t)(n0 + lrow) * DMODEL + lc0 * 8;

#define GISSUE(kc, st) do { \
    const size_t ko = (size_t)(kc) * 32; \
    const uint32_t sb_ = sbase + (st) * GSTAGE; \
    cp16(sb_         + soff0, Afp + aoff + ko);     \
    cp16(sb_         + soff1, Afp + aoff + ko + 8); \
    cp16(sb_ + 8192  + soff0, Bh + boff + ko);      \
    cp16(sb_ + 8192  + soff1, Bh + boff + ko + 8);  \
    cp16(sb_ + 16384 + soff0, Bl + boff + ko);      \
    cp16(sb_ + 16384 + soff1, Bl + boff + ko + 8);  \
    asm volatile("cp.async.commit_group;" ::: "memory"); \
} while (0)

    const int arow = (lane & 7) + ((lane >> 3) & 1) * 8;
    const int akb  = (lane >> 4);
    const int brow = (lane & 7) + (lane >> 4) * 8;
    const int bkb  = ((lane >> 3) & 1);

    float acc[4][4][4];
#pragma unroll
    for (int i = 0; i < 4; i++)
#pragma unroll
        for (int j = 0; j < 4; j++)
#pragma unroll
            for (int e = 0; e < 4; e++) acc[i][j][e] = 0.f;

    GISSUE(0, 0);
    GISSUE(1, 1);

    for (int kc = 0; kc < 32; kc++) {
        const int st = kc % 3;
        if (kc < 30) {
            asm volatile("cp.async.wait_group 1;" ::: "memory");
        } else {
            asm volatile("cp.async.wait_group 0;" ::: "memory");
        }
        __syncthreads();
        if (kc + 2 < 32) GISSUE(kc + 2, (kc + 2) % 3);

        const uint32_t bufb = sbase + st * GSTAGE;
#pragma unroll
        for (int ks = 0; ks < 2; ks++) {
            uint32_t af[4][4];
#pragma unroll
            for (int mf = 0; mf < 4; mf++) {
                const int r  = wm * 64 + mf * 16 + arow;
                const int kb = ks * 2 + akb;
                const uint32_t off = (uint32_t)(r * 64 + ((kb ^ ((r >> 1) & 3)) * 16));
                ldsm4(af[mf], bufb + off);
            }
            uint32_t bfh[2][4], bfl[2][4];
#pragma unroll
            for (int nq = 0; nq < 2; nq++) {
                const int r  = wn * 32 + nq * 16 + brow;
                const int kb = ks * 2 + bkb;
                const uint32_t off = (uint32_t)(r * 64 + ((kb ^ ((r >> 1) & 3)) * 16));
                ldsm4(bfh[nq], bufb + 8192 + off);
                ldsm4(bfl[nq], bufb + 16384 + off);
            }
#pragma unroll
            for (int mf = 0; mf < 4; mf++)
#pragma unroll
                for (int nf = 0; nf < 4; nf++) {
                    mma16816(acc[mf][nf], af[mf], &bfh[nf >> 1][(nf & 1) * 2]);
                    mma16816(acc[mf][nf], af[mf], &bfl[nf >> 1][(nf & 1) * 2]);
                }
        }
    }
#undef GISSUE
    __syncthreads();

    const int gID = lane >> 2;
    const int tg  = lane & 3;
#pragma unroll
    for (int mf = 0; mf < 4; mf++) {
#pragma unroll
        for (int nf = 0; nf < 4; nf++) {
            const int n = n0 + wn * 32 + nf * 8 + tg * 2;
            const float bx = bptr[n], by = bptr[n + 1];
#pragma unroll
            for (int half = 0; half < 2; half++) {
                const int m = m0 + wm * 64 + mf * 16 + gID + half * 8;
                const float fx = acc[mf][nf][half * 2 + 0] + bx;
                const float fy = acc[mf][nf][half * 2 + 1] + by;
                if (mode == 0) {
                    const int s  = m >> 1;
                    const int bb = m & 1;
                    const int h  = n >> 6;
                    const int j  = n & 63;
                    const size_t idx = (((size_t)(bb * NHEADS + h)) * SEQ + s) * DK + j;
                    if (p == 1) {
                        __half hx = __float2half_rn(fx);
                        __half hy = __float2half_rn(fy);
                        __half lx = __float2half_rn(fx - __half2float(hx));
                        __half ly = __float2half_rn(fy - __half2float(hy));
                        *(__half2*)&g_Khi[idx] = __halves2half2(hx, hy);
                        *(__half2*)&g_Klo[idx] = __halves2half2(lx, ly);
                    } else {
                        __half* D = (p == 0) ? g_Qf : g_Vf;
                        *(__half2*)&D[idx] =
                            __halves2half2(__float2half_rn(fx), __float2half_rn(fy));
                    }
                } else {
                    float2 v; v.x = fx; v.y = fy;
                    *(float2*)&dst[(size_t)m * DMODEL + n] = v;
                }
            }
        }
    }
}

// ---------------------------------------------------------------------------
// Kernel 2: fp16 2-product HMMA flash attention.
// CTA = (64 q-rows, one bh), 4 warps x m16, 128 threads -> 3 CTAs/SM.
// K-tile 64, 3-stage cp.async. grid = (SEQ/64, BH).
// ---------------------------------------------------------------------------
#define ASTAGE  24576   // Kh 8KB + Kl 8KB + Vf 8KB
#define AT_SMEM (3 * ASTAGE)

__global__ __launch_bounds__(128, 3)
void attn_mma()
{
    extern __shared__ char kvsm[];
    const uint32_t kvb = smem_u32(kvsm);
    const int tid  = threadIdx.x;
    const int lane = tid & 31;
    const int warp = tid >> 5;
    const int gID  = lane >> 2;
    const int tg   = lane & 3;
    const int q0   = blockIdx.x * 64;
    const int bh   = blockIdx.y;

    const __half* Kh = g_Khi + (size_t)bh * SEQ * DK;
    const __half* Kl = g_Klo + (size_t)bh * SEQ * DK;
    const __half* Vf = g_Vf  + (size_t)bh * SEQ * DK;

    // Q fragments (single fp16, persistent)
    uint32_t qf[4][4];
    {
        const __half* Q = g_Qf + ((size_t)bh * SEQ + q0 + warp * 16) * DK;
#pragma unroll
        for (int ks = 0; ks < 4; ks++) {
            const int c = ks * 16 + tg * 2;
            qf[ks][0] = *(const uint32_t*)&Q[(gID)     * DK + c];
            qf[ks][1] = *(const uint32_t*)&Q[(gID + 8) * DK + c];
            qf[ks][2] = *(const uint32_t*)&Q[(gID)     * DK + c + 8];
            qf[ks][3] = *(const uint32_t*)&Q[(gID + 8) * DK + c + 8];
        }
    }

    float o[8][4];
#pragma unroll
    for (int j = 0; j < 8; j++)
#pragma unroll
        for (int e = 0; e < 4; e++) o[j][e] = 0.f;
    float mrun[2] = {-1e30f, -1e30f};
    float lrun[2] = {0.f, 0.f};

    // loader: 128 threads; 64 rows x 8 blocks x 3 arrays = 12 cp16/thread
    const int lrow = tid >> 1;            // 0..63
    const int lc0  = (tid & 1) * 4;       // 0 or 4

#define ISSUE(kt, st) do { \
    const size_t grow = ((size_t)((kt) * 64 + lrow)) * DK + lc0 * 8; \
    const uint32_t sb_ = kvb + (st) * ASTAGE + lrow * 128; \
    _Pragma("unroll") \
    for (int i_ = 0; i_ < 4; i_++) { \
        const int blk_ = lc0 + i_; \
        const uint32_t so_ = sb_ + (uint32_t)((blk_ ^ (lrow & 7)) * 16); \
        cp16(so_,          Kh + grow + i_ * 8); \
        cp16(so_ + 8192,   Kl + grow + i_ * 8); \
        cp16(so_ + 16384,  Vf + grow + i_ * 8); \
    } \
    asm volatile("cp.async.commit_group;" ::: "memory"); \
} while (0)

    ISSUE(0, 0);
    ISSUE(1, 1);

    const int krow = (lane & 7) + (lane >> 4) * 8;
    const int kkb  = (lane >> 3) & 1;
    const int vrow = (lane & 7) + ((lane >> 3) & 1) * 8;
    const int vdb  = (lane >> 4);

    for (int kt = 0; kt < 32; kt++) {
        const int st = kt % 3;
        if (kt < 30) {
            asm volatile("cp.async.wait_group 1;" ::: "memory");
        } else {
            asm volatile("cp.async.wait_group 0;" ::: "memory");
        }
        __syncthreads();
        if (kt + 2 < 32) ISSUE(kt + 2, (kt + 2) % 3);

        const uint32_t stage = kvb + st * ASTAGE;

        // --- S = Qf (Kh+Kl)^T ---
        float s[8][4];
#pragma unroll
        for (int j = 0; j < 8; j++)
#pragma unroll
            for (int e = 0; e < 4; e++) s[j][e] = 0.f;

#pragma unroll
        for (int ng = 0; ng < 4; ng++) {
            const int r = ng * 16 + krow;
            const uint32_t rbase = stage + r * 128;
#pragma unroll
            for (int ks = 0; ks < 4; ks++) {
                const int kb = ks * 2 + kkb;
                const uint32_t off = rbase + (uint32_t)((kb ^ (r & 7)) * 16);
                uint32_t kh4[4], kl4[4];
                ldsm4(kh4, off);
                ldsm4(kl4, off + 8192);
                mma16816(s[ng * 2],     qf[ks], &kh4[0]);
                mma16816(s[ng * 2],     qf[ks], &kl4[0]);
                mma16816(s[ng * 2 + 1], qf[ks], &kh4[2]);
                mma16816(s[ng * 2 + 1], qf[ks], &kl4[2]);
            }
        }

        // --- online softmax (exp2 domain) ---
        const float SC = 0.125f * 1.4426950408889634f;
#pragma unroll
        for (int hf = 0; hf < 2; hf++) {
            float mx = -1e30f;
#pragma unroll
            for (int j = 0; j < 8; j++) {
                s[j][hf * 2]     *= SC;
                s[j][hf * 2 + 1] *= SC;
                mx = fmaxf(mx, fmaxf(s[j][hf * 2], s[j][hf * 2 + 1]));
            }
            mx = fmaxf(mx, __shfl_xor_sync(0xffffffffu, mx, 1));
            mx = fmaxf(mx, __shfl_xor_sync(0xffffffffu, mx, 2));
            const float mnew  = fmaxf(mrun[hf], mx);
            const float alpha = exp2f(mrun[hf] - mnew);
            mrun[hf] = mnew;
            float sum = 0.f;
#pragma unroll
            for (int j = 0; j < 8; j++) {
                const float p0 = exp2f(s[j][hf * 2]     - mnew);
                const float p1 = exp2f(s[j][hf * 2 + 1] - mnew);
                s[j][hf * 2]     = p0;
                s[j][hf * 2 + 1] = p1;
                sum += p0 + p1;
            }
            sum += __shfl_xor_sync(0xffffffffu, sum, 1);
            sum += __shfl_xor_sync(0xffffffffu, sum, 2);
            lrun[hf] = lrun[hf] * alpha + sum;
#pragma unroll
            for (int j = 0; j < 8; j++) {
                o[j][hf * 2]     *= alpha;
                o[j][hf * 2 + 1] *= alpha;
            }
        }

        // --- O += (Ph + Pl) Vf ---
#pragma unroll
        for (int t = 0; t < 4; t++) {
            uint32_t pah[4], pal[4];
#pragma unroll
            for (int e = 0; e < 2; e++) {
                const float f0 = s[2 * t + e][0], f1 = s[2 * t + e][1];
                const float f2 = s[2 * t + e][2], f3 = s[2 * t + e][3];
                const __half h0 = __float2half_rn(f0);
                const __half h1 = __float2half_rn(f1);
                const __half h2 = __float2half_rn(f2);
                const __half h3 = __float2half_rn(f3);
                pah[e * 2 + 0] = pack2h(h0, h1);
                pah[e * 2 + 1] = pack2h(h2, h3);
                pal[e * 2 + 0] = pack2h(__float2half_rn(f0 - __half2float(h0)),
                                        __float2half_rn(f1 - __half2float(h1)));
                pal[e * 2 + 1] = pack2h(__float2half_rn(f2 - __half2float(h2)),
                                        __float2half_rn(f3 - __half2float(h3)));
            }

            const int r = t * 16 + vrow;
            const uint32_t rbase = stage + 16384 + r * 128;
#pragma unroll
            for (int dg = 0; dg < 4; dg++) {
                const int db = dg * 2 + vdb;
                const uint32_t off = rbase + (uint32_t)((db ^ (r & 7)) * 16);
                uint32_t vf4[4];
                ldsm4t(vf4, off);
                mma16816(o[dg * 2],     pah, &vf4[0]);
                mma16816(o[dg * 2],     pal, &vf4[0]);
                mma16816(o[dg * 2 + 1], pah, &vf4[2]);
                mma16816(o[dg * 2 + 1], pal, &vf4[2]);
            }
        }
    }
#undef ISSUE

    // --- epilogue: normalize, round to fp16, write g_Af ---
    const int bb  = bh >> 4;
    const int hh_ = bh & 15;
#pragma unroll
    for (int half = 0; half < 2; half++) {
        const int r = q0 + warp * 16 + gID + half * 8;
        const float inv = 1.0f / lrun[half];
#pragma unroll
        for (int j = 0; j < 8; j++) {
            const float f0 = o[j][half * 2 + 0] * inv;
            const float f1 = o[j][half * 2 + 1] * inv;
            const size_t idx = ((size_t)(r * BATCH + bb)) * DMODEL + hh_ * DK + j * 8 + tg * 2;
            *(__half2*)&g_Af[idx] =
                __halves2half2(__float2half_rn(f0), __float2half_rn(f1));
        }
    }
}

// ---------------------------------------------------------------------------
extern "C" void kernel_launch(void* const* d_in, const int* in_sizes, int n_in,
                              void* d_out, int out_size)
{
    const float* q     = (const float*)d_in[0];
    const float* k     = (const float*)d_in[1];
    const float* v     = (const float*)d_in[2];
    const float* in_w  = (const float*)d_in[3];
    const float* in_b  = (const float*)d_in[4];
    const float* out_w = (const float*)d_in[5];
    const float* out_b = (const float*)d_in[6];
    float* out = (float*)d_out;

    static bool attr_done = false;
    if (!attr_done) {
        cudaFuncSetAttribute(attn_mma, cudaFuncAttributeMaxDynamicSharedMemorySize, AT_SMEM);
        cudaFuncSetAttribute(gemm_mma, cudaFuncAttributeMaxDynamicSharedMemorySize, GB_SMEM);
        attr_done = true;
    }

    cvt_all<<<dim3(4096, 5), 256>>>(q, k, v, in_w, out_w);

    dim3 gQKV(DMODEL / 128, MROWS / 128, 3);
    gemm_mma<<<gQKV, 256, GB_SMEM>>>(in_b, out, 0);

    dim3 gAttn(SEQ / 64, BH);
    attn_mma<<<gAttn, 128, AT_SMEM>>>();

    dim3 gOut(DMODEL / 128, MROWS / 128, 1);
    gemm_mma<<<gOut, 256, GB_SMEM>>>(out_b, out, 1);
}

// round 9
// speedup vs baseline: 6.0745x; 1.0615x over previous
#include <cuda_runtime.h>
#include <cuda_fp16.h>
#include <cstdint>

// ---------------------------------------------------------------------------
// Problem constants
// ---------------------------------------------------------------------------
#define SEQ     2048
#define BATCH   2
#define DMODEL  1024
#define NHEADS  16
#define DK      64
#define BH      (BATCH*NHEADS)   // 32
#define MROWS   (SEQ*BATCH)      // 4096

// ---------------------------------------------------------------------------
// Device scratch
// ---------------------------------------------------------------------------
__device__ __half g_Qf [BH * SEQ * DK];     // Q rounded fp16
__device__ __half g_Khi[BH * SEQ * DK];     // K split fp16
__device__ __half g_Klo[BH * SEQ * DK];
__device__ __half g_Vf [BH * SEQ * DK];     // V rounded fp16

__device__ __half g_Xf [3 * MROWS * DMODEL];  // X rounded fp16
__device__ __half g_Whi[3 * DMODEL * DMODEL]; // in_proj_w split
__device__ __half g_Wlo[3 * DMODEL * DMODEL];
__device__ __half g_OWhi[DMODEL * DMODEL];    // out_proj_w split
__device__ __half g_OWlo[DMODEL * DMODEL];
__device__ __half g_Af [MROWS * DMODEL];      // attention out rounded fp16

// ---------------------------------------------------------------------------
// Helpers
// ---------------------------------------------------------------------------
__device__ __forceinline__ uint32_t smem_u32(const void* p) {
    uint32_t r;
    asm("{ .reg .u64 t; cvta.to.shared.u64 t, %1; cvt.u32.u64 %0, t; }"
        : "=r"(r) : "l"(p));
    return r;
}

__device__ __forceinline__ void ldsm4(uint32_t* r, uint32_t addr) {
    asm volatile("ldmatrix.sync.aligned.m8n8.x4.shared.b16 {%0,%1,%2,%3}, [%4];"
                 : "=r"(r[0]), "=r"(r[1]), "=r"(r[2]), "=r"(r[3]) : "r"(addr));
}

__device__ __forceinline__ void ldsm4t(uint32_t* r, uint32_t addr) {
    asm volatile("ldmatrix.sync.aligned.m8n8.x4.trans.shared.b16 {%0,%1,%2,%3}, [%4];"
                 : "=r"(r[0]), "=r"(r[1]), "=r"(r[2]), "=r"(r[3]) : "r"(addr));
}

__device__ __forceinline__ void mma16816(float* c, const uint32_t* a, const uint32_t* b) {
    asm volatile(
        "mma.sync.aligned.m16n8k16.row.col.f32.f16.f16.f32 "
        "{%0,%1,%2,%3}, {%4,%5,%6,%7}, {%8,%9}, {%0,%1,%2,%3};"
        : "+f"(c[0]), "+f"(c[1]), "+f"(c[2]), "+f"(c[3])
        : "r"(a[0]), "r"(a[1]), "r"(a[2]), "r"(a[3]), "r"(b[0]), "r"(b[1]));
}

__device__ __forceinline__ void cp16(uint32_t d, const void* s) {
    asm volatile("cp.async.cg.shared.global [%0], [%1], 16;" :: "r"(d), "l"(s));
}

__device__ __forceinline__ uint32_t packf2(float a, float b) {
    float2 t; t.x = a; t.y = b;
    __half2 h = __float22half2_rn(t);
    return *(uint32_t*)&h;
}

// ---------------------------------------------------------------------------
// Kernel 0: fused conversion. jobs 0-2: q/k/v -> g_Xf fp16; 3: in_w split;
// 4: out_w split. grid = (4096, 5)
// ---------------------------------------------------------------------------
__global__ __launch_bounds__(256)
void cvt_all(const float* __restrict__ q, const float* __restrict__ k,
             const float* __restrict__ v, const float* __restrict__ in_w,
             const float* __restrict__ out_w)
{
    const int job = blockIdx.y;
    const int i = blockIdx.x * 256 + threadIdx.x;
    if (job < 3) {
        const int n4 = MROWS * DMODEL / 4;
        if (i >= n4) return;
        const float* src = (job == 0) ? q : (job == 1) ? k : v;
        float4 x = ((const float4*)src)[i];
        __half2* d = (__half2*)(g_Xf + (size_t)job * MROWS * DMODEL);
        d[2 * i]     = __halves2half2(__float2half_rn(x.x), __float2half_rn(x.y));
        d[2 * i + 1] = __halves2half2(__float2half_rn(x.z), __float2half_rn(x.w));
    } else {
        const int n4 = (job == 3) ? 3 * DMODEL * DMODEL / 4 : DMODEL * DMODEL / 4;
        if (i >= n4) return;
        const float* src = (job == 3) ? in_w : out_w;
        __half* hi = (job == 3) ? g_Whi : g_OWhi;
        __half* lo = (job == 3) ? g_Wlo : g_OWlo;
        float4 x = ((const float4*)src)[i];
        __half h0 = __float2half_rn(x.x), h1 = __float2half_rn(x.y);
        __half h2 = __float2half_rn(x.z), h3 = __float2half_rn(x.w);
        __half l0 = __float2half_rn(x.x - __half2float(h0));
        __half l1 = __float2half_rn(x.y - __half2float(h1));
        __half l2 = __float2half_rn(x.z - __half2float(h2));
        __half l3 = __float2half_rn(x.w - __half2float(h3));
        ((__half2*)hi)[2 * i]     = __halves2half2(h0, h1);
        ((__half2*)hi)[2 * i + 1] = __halves2half2(h2, h3);
        ((__half2*)lo)[2 * i]     = __halves2half2(l0, l1);
        ((__half2*)lo)[2 * i + 1] = __halves2half2(l2, l3);
    }
}

// ---------------------------------------------------------------------------
// Kernel 1: fp16 2-product HMMA GEMM, 128x128 CTA tile, 256 threads,
// __launch_bounds__(256,2) -> 2 CTAs/SM. K-chunk 32, 3-stage cp.async.
// ---------------------------------------------------------------------------
#define GSTAGE  24576   // Af 8KB + Bh 8KB + Bl 8KB
#define GB_SMEM (3 * GSTAGE)

__global__ __launch_bounds__(256, 2)
void gemm_mma(const float* __restrict__ bias_in, float* __restrict__ dst, int mode)
{
    extern __shared__ char gsm[];
    const uint32_t sbase = smem_u32(gsm);

    const int tid  = threadIdx.x;
    const int lane = tid & 31;
    const int wid  = tid >> 5;
    const int wm   = wid & 1;
    const int wn   = wid >> 1;
    const int p    = blockIdx.z;
    const int n0   = blockIdx.x * 128;
    const int m0   = blockIdx.y * 128;

    const __half *Afp, *Bh, *Bl;
    if (mode == 0) {
        Afp = g_Xf  + (size_t)p * MROWS * DMODEL;
        Bh  = g_Whi + (size_t)p * DMODEL * DMODEL;
        Bl  = g_Wlo + (size_t)p * DMODEL * DMODEL;
    } else {
        Afp = g_Af; Bh = g_OWhi; Bl = g_OWlo;
    }
    const float* bptr = bias_in + p * DMODEL;

    const int lrow = tid >> 1;
    const int lc0  = (tid & 1) * 2;
    const uint32_t soff0 = (uint32_t)(lrow * 64 + (((lc0)     ^ ((lrow >> 1) & 3)) * 16));
    const uint32_t soff1 = (uint32_t)(lrow * 64 + (((lc0 + 1) ^ ((lrow >> 1) & 3)) * 16));
    const size_t aoff = (size_t)(m0 + lrow) * DMODEL + lc0 * 8;
    const size_t boff = (size_t)(n0 + lrow) * DMODEL + lc0 * 8;

#define GISSUE(kc, st) do { \
    const size_t ko = (size_t)(kc) * 32; \
    const uint32_t sb_ = sbase + (st) * GSTAGE; \
    cp16(sb_         + soff0, Afp + aoff + ko);     \
    cp16(sb_         + soff1, Afp + aoff + ko + 8); \
    cp16(sb_ + 8192  + soff0, Bh + boff + ko);      \
    cp16(sb_ + 8192  + soff1, Bh + boff + ko + 8);  \
    cp16(sb_ + 16384 + soff0, Bl + boff + ko);      \
    cp16(sb_ + 16384 + soff1, Bl + boff + ko + 8);  \
    asm volatile("cp.async.commit_group;" ::: "memory"); \
} while (0)

    const int arow = (lane & 7) + ((lane >> 3) & 1) * 8;
    const int akb  = (lane >> 4);
    const int brow = (lane & 7) + (lane >> 4) * 8;
    const int bkb  = ((lane >> 3) & 1);

    float acc[4][4][4];
#pragma unroll
    for (int i = 0; i < 4; i++)
#pragma unroll
        for (int j = 0; j < 4; j++)
#pragma unroll
            for (int e = 0; e < 4; e++) acc[i][j][e] = 0.f;

    GISSUE(0, 0);
    GISSUE(1, 1);

    for (int kc = 0; kc < 32; kc++) {
        const int st = kc % 3;
        if (kc < 30) {
            asm volatile("cp.async.wait_group 1;" ::: "memory");
        } else {
            asm volatile("cp.async.wait_group 0;" ::: "memory");
        }
        __syncthreads();
        if (kc + 2 < 32) GISSUE(kc + 2, (kc + 2) % 3);

        const uint32_t bufb = sbase + st * GSTAGE;
#pragma unroll
        for (int ks = 0; ks < 2; ks++) {
            uint32_t af[4][4];
#pragma unroll
            for (int mf = 0; mf < 4; mf++) {
                const int r  = wm * 64 + mf * 16 + arow;
                const int kb = ks * 2 + akb;
                const uint32_t off = (uint32_t)(r * 64 + ((kb ^ ((r >> 1) & 3)) * 16));
                ldsm4(af[mf], bufb + off);
            }
            uint32_t bfh[2][4], bfl[2][4];
#pragma unroll
            for (int nq = 0; nq < 2; nq++) {
                const int r  = wn * 32 + nq * 16 + brow;
                const int kb = ks * 2 + bkb;
                const uint32_t off = (uint32_t)(r * 64 + ((kb ^ ((r >> 1) & 3)) * 16));
                ldsm4(bfh[nq], bufb + 8192 + off);
                ldsm4(bfl[nq], bufb + 16384 + off);
            }
#pragma unroll
            for (int mf = 0; mf < 4; mf++)
#pragma unroll
                for (int nf = 0; nf < 4; nf++) {
                    mma16816(acc[mf][nf], af[mf], &bfh[nf >> 1][(nf & 1) * 2]);
                    mma16816(acc[mf][nf], af[mf], &bfl[nf >> 1][(nf & 1) * 2]);
                }
        }
    }
#undef GISSUE
    __syncthreads();

    const int gID = lane >> 2;
    const int tg  = lane & 3;
#pragma unroll
    for (int mf = 0; mf < 4; mf++) {
#pragma unroll
        for (int nf = 0; nf < 4; nf++) {
            const int n = n0 + wn * 32 + nf * 8 + tg * 2;
            const float bx = bptr[n], by = bptr[n + 1];
#pragma unroll
            for (int half = 0; half < 2; half++) {
                const int m = m0 + wm * 64 + mf * 16 + gID + half * 8;
                const float fx = acc[mf][nf][half * 2 + 0] + bx;
                const float fy = acc[mf][nf][half * 2 + 1] + by;
                if (mode == 0) {
                    const int s  = m >> 1;
                    const int bb = m & 1;
                    const int h  = n >> 6;
                    const int j  = n & 63;
                    const size_t idx = (((size_t)(bb * NHEADS + h)) * SEQ + s) * DK + j;
                    if (p == 1) {
                        __half hx = __float2half_rn(fx);
                        __half hy = __float2half_rn(fy);
                        __half lx = __float2half_rn(fx - __half2float(hx));
                        __half ly = __float2half_rn(fy - __half2float(hy));
                        *(__half2*)&g_Khi[idx] = __halves2half2(hx, hy);
                        *(__half2*)&g_Klo[idx] = __halves2half2(lx, ly);
                    } else {
                        __half* D = (p == 0) ? g_Qf : g_Vf;
                        *(uint32_t*)&D[idx] = packf2(fx, fy);
                    }
                } else {
                    float2 v; v.x = fx; v.y = fy;
                    *(float2*)&dst[(size_t)m * DMODEL + n] = v;
                }
            }
        }
    }
}

// ---------------------------------------------------------------------------
// Kernel 2: fp16 HMMA flash attention.
// S = Qf (Kh+Kl)^T  (2-product);  O += Pf Vf  (single product).
// CTA = (64 q-rows, one bh), 4 warps, 128 threads, 3 CTAs/SM.
// K-tile 64, 3-stage cp.async. grid = (SEQ/64, BH).
// ---------------------------------------------------------------------------
#define ASTAGE  24576   // Kh 8KB + Kl 8KB + Vf 8KB
#define AT_SMEM (3 * ASTAGE)

__global__ __launch_bounds__(128, 3)
void attn_mma()
{
    extern __shared__ char kvsm[];
    const uint32_t kvb = smem_u32(kvsm);
    const int tid  = threadIdx.x;
    const int lane = tid & 31;
    const int warp = tid >> 5;
    const int gID  = lane >> 2;
    const int tg   = lane & 3;
    const int q0   = blockIdx.x * 64;
    const int bh   = blockIdx.y;

    const __half* Kh = g_Khi + (size_t)bh * SEQ * DK;
    const __half* Kl = g_Klo + (size_t)bh * SEQ * DK;
    const __half* Vf = g_Vf  + (size_t)bh * SEQ * DK;

    // Q fragments (single fp16, persistent)
    uint32_t qf[4][4];
    {
        const __half* Q = g_Qf + ((size_t)bh * SEQ + q0 + warp * 16) * DK;
#pragma unroll
        for (int ks = 0; ks < 4; ks++) {
            const int c = ks * 16 + tg * 2;
            qf[ks][0] = *(const uint32_t*)&Q[(gID)     * DK + c];
            qf[ks][1] = *(const uint32_t*)&Q[(gID + 8) * DK + c];
            qf[ks][2] = *(const uint32_t*)&Q[(gID)     * DK + c + 8];
            qf[ks][3] = *(const uint32_t*)&Q[(gID + 8) * DK + c + 8];
        }
    }

    float o[8][4];
#pragma unroll
    for (int j = 0; j < 8; j++)
#pragma unroll
        for (int e = 0; e < 4; e++) o[j][e] = 0.f;
    float mrun[2] = {-1e30f, -1e30f};
    float lrun[2] = {0.f, 0.f};

    // loader: 128 threads; 64 rows x 8 blocks x 3 arrays = 12 cp16/thread
    const int lrow = tid >> 1;            // 0..63
    const int lc0  = (tid & 1) * 4;       // 0 or 4

#define ISSUE(kt, st) do { \
    const size_t grow = ((size_t)((kt) * 64 + lrow)) * DK + lc0 * 8; \
    const uint32_t sb_ = kvb + (st) * ASTAGE + lrow * 128; \
    _Pragma("unroll") \
    for (int i_ = 0; i_ < 4; i_++) { \
        const int blk_ = lc0 + i_; \
        const uint32_t so_ = sb_ + (uint32_t)((blk_ ^ (lrow & 7)) * 16); \
        cp16(so_,          Kh + grow + i_ * 8); \
        cp16(so_ + 8192,   Kl + grow + i_ * 8); \
        cp16(so_ + 16384,  Vf + grow + i_ * 8); \
    } \
    asm volatile("cp.async.commit_group;" ::: "memory"); \
} while (0)

    ISSUE(0, 0);
    ISSUE(1, 1);

    const int krow = (lane & 7) + (lane >> 4) * 8;
    const int kkb  = (lane >> 3) & 1;
    const int vrow = (lane & 7) + ((lane >> 3) & 1) * 8;
    const int vdb  = (lane >> 4);

    for (int kt = 0; kt < 32; kt++) {
        const int st = kt % 3;
        if (kt < 30) {
            asm volatile("cp.async.wait_group 1;" ::: "memory");
        } else {
            asm volatile("cp.async.wait_group 0;" ::: "memory");
        }
        __syncthreads();
        if (kt + 2 < 32) ISSUE(kt + 2, (kt + 2) % 3);

        const uint32_t stage = kvb + st * ASTAGE;

        // --- S = Qf (Kh+Kl)^T ---
        float s[8][4];
#pragma unroll
        for (int j = 0; j < 8; j++)
#pragma unroll
            for (int e = 0; e < 4; e++) s[j][e] = 0.f;

#pragma unroll
        for (int ng = 0; ng < 4; ng++) {
            const int r = ng * 16 + krow;
            const uint32_t rbase = stage + r * 128;
#pragma unroll
            for (int ks = 0; ks < 4; ks++) {
                const int kb = ks * 2 + kkb;
                const uint32_t off = rbase + (uint32_t)((kb ^ (r & 7)) * 16);
                uint32_t kh4[4], kl4[4];
                ldsm4(kh4, off);
                ldsm4(kl4, off + 8192);
                mma16816(s[ng * 2],     qf[ks], &kh4[0]);
                mma16816(s[ng * 2],     qf[ks], &kl4[0]);
                mma16816(s[ng * 2 + 1], qf[ks], &kh4[2]);
                mma16816(s[ng * 2 + 1], qf[ks], &kl4[2]);
            }
        }

        // --- online softmax (exp2 domain) ---
        const float SC = 0.125f * 1.4426950408889634f;
#pragma unroll
        for (int hf = 0; hf < 2; hf++) {
            float mx = -1e30f;
#pragma unroll
            for (int j = 0; j < 8; j++) {
                s[j][hf * 2]     *= SC;
                s[j][hf * 2 + 1] *= SC;
                mx = fmaxf(mx, fmaxf(s[j][hf * 2], s[j][hf * 2 + 1]));
            }
            mx = fmaxf(mx, __shfl_xor_sync(0xffffffffu, mx, 1));
            mx = fmaxf(mx, __shfl_xor_sync(0xffffffffu, mx, 2));
            const float mnew  = fmaxf(mrun[hf], mx);
            const float alpha = exp2f(mrun[hf] - mnew);
            mrun[hf] = mnew;
            float sum = 0.f;
#pragma unroll
            for (int j = 0; j < 8; j++) {
                const float p0 = exp2f(s[j][hf * 2]     - mnew);
                const float p1 = exp2f(s[j][hf * 2 + 1] - mnew);
                s[j][hf * 2]     = p0;
                s[j][hf * 2 + 1] = p1;
                sum += p0 + p1;
            }
            sum += __shfl_xor_sync(0xffffffffu, sum, 1);
            sum += __shfl_xor_sync(0xffffffffu, sum, 2);
            lrun[hf] = lrun[hf] * alpha + sum;
#pragma unroll
            for (int j = 0; j < 8; j++) {
                o[j][hf * 2]     *= alpha;
                o[j][hf * 2 + 1] *= alpha;
            }
        }

        // --- O += Pf Vf (single product) ---
#pragma unroll
        for (int t = 0; t < 4; t++) {
            uint32_t pah[4];
            pah[0] = packf2(s[2 * t + 0][0], s[2 * t + 0][1]);
            pah[1] = packf2(s[2 * t + 0][2], s[2 * t + 0][3]);
            pah[2] = packf2(s[2 * t + 1][0], s[2 * t + 1][1]);
            pah[3] = packf2(s[2 * t + 1][2], s[2 * t + 1][3]);

            const int r = t * 16 + vrow;
            const uint32_t rbase = stage + 16384 + r * 128;
#pragma unroll
            for (int dg = 0; dg < 4; dg++) {
                const int db = dg * 2 + vdb;
                const uint32_t off = rbase + (uint32_t)((db ^ (r & 7)) * 16);
                uint32_t vf4[4];
                ldsm4t(vf4, off);
                mma16816(o[dg * 2],     pah, &vf4[0]);
                mma16816(o[dg * 2 + 1], pah, &vf4[2]);
            }
        }
    }
#undef ISSUE

    // --- epilogue: normalize, round to fp16, write g_Af ---
    const int bb  = bh >> 4;
    const int hh_ = bh & 15;
#pragma unroll
    for (int half = 0; half < 2; half++) {
        const int r = q0 + warp * 16 + gID + half * 8;
        const float inv = 1.0f / lrun[half];
#pragma unroll
        for (int j = 0; j < 8; j++) {
            const float f0 = o[j][half * 2 + 0] * inv;
            const float f1 = o[j][half * 2 + 1] * inv;
            const size_t idx = ((size_t)(r * BATCH + bb)) * DMODEL + hh_ * DK + j * 8 + tg * 2;
            *(uint32_t*)&g_Af[idx] = packf2(f0, f1);
        }
    }
}

// ---------------------------------------------------------------------------
extern "C" void kernel_launch(void* const* d_in, const int* in_sizes, int n_in,
                              void* d_out, int out_size)
{
    const float* q     = (const float*)d_in[0];
    const float* k     = (const float*)d_in[1];
    const float* v     = (const float*)d_in[2];
    const float* in_w  = (const float*)d_in[3];
    const float* in_b  = (const float*)d_in[4];
    const float* out_w = (const float*)d_in[5];
    const float* out_b = (const float*)d_in[6];
    float* out = (float*)d_out;

    static bool attr_done = false;
    if (!attr_done) {
        cudaFuncSetAttribute(attn_mma, cudaFuncAttributeMaxDynamicSharedMemorySize, AT_SMEM);
        cudaFuncSetAttribute(gemm_mma, cudaFuncAttributeMaxDynamicSharedMemorySize, GB_SMEM);
        attr_done = true;
    }

    cvt_all<<<dim3(4096, 5), 256>>>(q, k, v, in_w, out_w);

    dim3 gQKV(DMODEL / 128, MROWS / 128, 3);
    gemm_mma<<<gQKV, 256, GB_SMEM>>>(in_b, out, 0);

    dim3 gAttn(SEQ / 64, BH);
    attn_mma<<<gAttn, 128, AT_SMEM>>>();

    dim3 gOut(DMODEL / 128, MROWS / 128, 1);
    gemm_mma<<<gOut, 256, GB_SMEM>>>(out_b, out, 1);
}

// round 10
// speedup vs baseline: 6.9932x; 1.1512x over previous
#include <cuda_runtime.h>
#include <cuda_fp16.h>
#include <cstdint>

// ---------------------------------------------------------------------------
// Problem constants
// ---------------------------------------------------------------------------
#define SEQ     2048
#define BATCH   2
#define DMODEL  1024
#define NHEADS  16
#define DK      64
#define BH      (BATCH*NHEADS)   // 32
#define MROWS   (SEQ*BATCH)      // 4096

// ---------------------------------------------------------------------------
// Device scratch
// ---------------------------------------------------------------------------
__device__ __half g_Qf [BH * SEQ * DK];     // Q rounded fp16
__device__ __half g_Kf [BH * SEQ * DK];     // K rounded fp16
__device__ __half g_Vf [BH * SEQ * DK];     // V rounded fp16

__device__ __half g_Xf [3 * MROWS * DMODEL];  // X rounded fp16
__device__ __half g_Whi[3 * DMODEL * DMODEL]; // in_proj_w split
__device__ __half g_Wlo[3 * DMODEL * DMODEL];
__device__ __half g_OWhi[DMODEL * DMODEL];    // out_proj_w split
__device__ __half g_OWlo[DMODEL * DMODEL];
__device__ __half g_Af [MROWS * DMODEL];      // attention out rounded fp16

// ---------------------------------------------------------------------------
// Helpers
// ---------------------------------------------------------------------------
__device__ __forceinline__ uint32_t smem_u32(const void* p) {
    uint32_t r;
    asm("{ .reg .u64 t; cvta.to.shared.u64 t, %1; cvt.u32.u64 %0, t; }"
        : "=r"(r) : "l"(p));
    return r;
}

__device__ __forceinline__ void ldsm4(uint32_t* r, uint32_t addr) {
    asm volatile("ldmatrix.sync.aligned.m8n8.x4.shared.b16 {%0,%1,%2,%3}, [%4];"
                 : "=r"(r[0]), "=r"(r[1]), "=r"(r[2]), "=r"(r[3]) : "r"(addr));
}

__device__ __forceinline__ void ldsm4t(uint32_t* r, uint32_t addr) {
    asm volatile("ldmatrix.sync.aligned.m8n8.x4.trans.shared.b16 {%0,%1,%2,%3}, [%4];"
                 : "=r"(r[0]), "=r"(r[1]), "=r"(r[2]), "=r"(r[3]) : "r"(addr));
}

__device__ __forceinline__ void mma16816(float* c, const uint32_t* a, const uint32_t* b) {
    asm volatile(
        "mma.sync.aligned.m16n8k16.row.col.f32.f16.f16.f32 "
        "{%0,%1,%2,%3}, {%4,%5,%6,%7}, {%8,%9}, {%0,%1,%2,%3};"
        : "+f"(c[0]), "+f"(c[1]), "+f"(c[2]), "+f"(c[3])
        : "r"(a[0]), "r"(a[1]), "r"(a[2]), "r"(a[3]), "r"(b[0]), "r"(b[1]));
}

__device__ __forceinline__ void cp16(uint32_t d, const void* s) {
    asm volatile("cp.async.cg.shared.global [%0], [%1], 16;" :: "r"(d), "l"(s));
}

__device__ __forceinline__ uint32_t packf2(float a, float b) {
    float2 t; t.x = a; t.y = b;
    __half2 h = __float22half2_rn(t);
    return *(uint32_t*)&h;
}

// ---------------------------------------------------------------------------
// Kernel 0: fused conversion. jobs 0-2: q/k/v -> g_Xf fp16; 3: in_w split;
// 4: out_w split. grid = (4096, 5)
// ---------------------------------------------------------------------------
__global__ __launch_bounds__(256)
void cvt_all(const float* __restrict__ q, const float* __restrict__ k,
             const float* __restrict__ v, const float* __restrict__ in_w,
             const float* __restrict__ out_w)
{
    const int job = blockIdx.y;
    const int i = blockIdx.x * 256 + threadIdx.x;
    if (job < 3) {
        const int n4 = MROWS * DMODEL / 4;
        if (i >= n4) return;
        const float* src = (job == 0) ? q : (job == 1) ? k : v;
        float4 x = ((const float4*)src)[i];
        __half2* d = (__half2*)(g_Xf + (size_t)job * MROWS * DMODEL);
        d[2 * i]     = __halves2half2(__float2half_rn(x.x), __float2half_rn(x.y));
        d[2 * i + 1] = __halves2half2(__float2half_rn(x.z), __float2half_rn(x.w));
    } else {
        const int n4 = (job == 3) ? 3 * DMODEL * DMODEL / 4 : DMODEL * DMODEL / 4;
        if (i >= n4) return;
        const float* src = (job == 3) ? in_w : out_w;
        __half* hi = (job == 3) ? g_Whi : g_OWhi;
        __half* lo = (job == 3) ? g_Wlo : g_OWlo;
        float4 x = ((const float4*)src)[i];
        __half h0 = __float2half_rn(x.x), h1 = __float2half_rn(x.y);
        __half h2 = __float2half_rn(x.z), h3 = __float2half_rn(x.w);
        __half l0 = __float2half_rn(x.x - __half2float(h0));
        __half l1 = __float2half_rn(x.y - __half2float(h1));
        __half l2 = __float2half_rn(x.z - __half2float(h2));
        __half l3 = __float2half_rn(x.w - __half2float(h3));
        ((__half2*)hi)[2 * i]     = __halves2half2(h0, h1);
        ((__half2*)hi)[2 * i + 1] = __halves2half2(h2, h3);
        ((__half2*)lo)[2 * i]     = __halves2half2(l0, l1);
        ((__half2*)lo)[2 * i + 1] = __halves2half2(l2, l3);
    }
}

// ---------------------------------------------------------------------------
// Kernel 1: fp16 2-product HMMA GEMM, 128x128 CTA tile, 256 threads,
// __launch_bounds__(256,2) -> 2 CTAs/SM. K-chunk 32, 3-stage cp.async.
// ---------------------------------------------------------------------------
#define GSTAGE  24576   // Af 8KB + Bh 8KB + Bl 8KB
#define GB_SMEM (3 * GSTAGE)

__global__ __launch_bounds__(256, 2)
void gemm_mma(const float* __restrict__ bias_in, float* __restrict__ dst, int mode)
{
    extern __shared__ char gsm[];
    const uint32_t sbase = smem_u32(gsm);

    const int tid  = threadIdx.x;
    const int lane = tid & 31;
    const int wid  = tid >> 5;
    const int wm   = wid & 1;
    const int wn   = wid >> 1;
    const int p    = blockIdx.z;
    const int n0   = blockIdx.x * 128;
    const int m0   = blockIdx.y * 128;

    const __half *Afp, *Bh, *Bl;
    if (mode == 0) {
        Afp = g_Xf  + (size_t)p * MROWS * DMODEL;
        Bh  = g_Whi + (size_t)p * DMODEL * DMODEL;
        Bl  = g_Wlo + (size_t)p * DMODEL * DMODEL;
    } else {
        Afp = g_Af; Bh = g_OWhi; Bl = g_OWlo;
    }
    const float* bptr = bias_in + p * DMODEL;

    const int lrow = tid >> 1;
    const int lc0  = (tid & 1) * 2;
    const uint32_t soff0 = (uint32_t)(lrow * 64 + (((lc0)     ^ ((lrow >> 1) & 3)) * 16));
    const uint32_t soff1 = (uint32_t)(lrow * 64 + (((lc0 + 1) ^ ((lrow >> 1) & 3)) * 16));
    const size_t aoff = (size_t)(m0 + lrow) * DMODEL + lc0 * 8;
    const size_t boff = (size_t)(n0 + lrow) * DMODEL + lc0 * 8;

#define GISSUE(kc, st) do { \
    const size_t ko = (size_t)(kc) * 32; \
    const uint32_t sb_ = sbase + (st) * GSTAGE; \
    cp16(sb_         + soff0, Afp + aoff + ko);     \
    cp16(sb_         + soff1, Afp + aoff + ko + 8); \
    cp16(sb_ + 8192  + soff0, Bh + boff + ko);      \
    cp16(sb_ + 8192  + soff1, Bh + boff + ko + 8);  \
    cp16(sb_ + 16384 + soff0, Bl + boff + ko);      \
    cp16(sb_ + 16384 + soff1, Bl + boff + ko + 8);  \
    asm volatile("cp.async.commit_group;" ::: "memory"); \
} while (0)

    const int arow = (lane & 7) + ((lane >> 3) & 1) * 8;
    const int akb  = (lane >> 4);
    const int brow = (lane & 7) + (lane >> 4) * 8;
    const int bkb  = ((lane >> 3) & 1);

    float acc[4][4][4];
#pragma unroll
    for (int i = 0; i < 4; i++)
#pragma unroll
        for (int j = 0; j < 4; j++)
#pragma unroll
            for (int e = 0; e < 4; e++) acc[i][j][e] = 0.f;

    GISSUE(0, 0);
    GISSUE(1, 1);

    for (int kc = 0; kc < 32; kc++) {
        const int st = kc % 3;
        if (kc < 30) {
            asm volatile("cp.async.wait_group 1;" ::: "memory");
        } else {
            asm volatile("cp.async.wait_group 0;" ::: "memory");
        }
        __syncthreads();
        if (kc + 2 < 32) GISSUE(kc + 2, (kc + 2) % 3);

        const uint32_t bufb = sbase + st * GSTAGE;
#pragma unroll
        for (int ks = 0; ks < 2; ks++) {
            uint32_t af[4][4];
#pragma unroll
            for (int mf = 0; mf < 4; mf++) {
                const int r  = wm * 64 + mf * 16 + arow;
                const int kb = ks * 2 + akb;
                const uint32_t off = (uint32_t)(r * 64 + ((kb ^ ((r >> 1) & 3)) * 16));
                ldsm4(af[mf], bufb + off);
            }
            uint32_t bfh[2][4], bfl[2][4];
#pragma unroll
            for (int nq = 0; nq < 2; nq++) {
                const int r  = wn * 32 + nq * 16 + brow;
                const int kb = ks * 2 + bkb;
                const uint32_t off = (uint32_t)(r * 64 + ((kb ^ ((r >> 1) & 3)) * 16));
                ldsm4(bfh[nq], bufb + 8192 + off);
                ldsm4(bfl[nq], bufb + 16384 + off);
            }
#pragma unroll
            for (int mf = 0; mf < 4; mf++)
#pragma unroll
                for (int nf = 0; nf < 4; nf++) {
                    mma16816(acc[mf][nf], af[mf], &bfh[nf >> 1][(nf & 1) * 2]);
                    mma16816(acc[mf][nf], af[mf], &bfl[nf >> 1][(nf & 1) * 2]);
                }
        }
    }
#undef GISSUE
    __syncthreads();

    const int gID = lane >> 2;
    const int tg  = lane & 3;
#pragma unroll
    for (int mf = 0; mf < 4; mf++) {
#pragma unroll
        for (int nf = 0; nf < 4; nf++) {
            const int n = n0 + wn * 32 + nf * 8 + tg * 2;
            const float bx = bptr[n], by = bptr[n + 1];
#pragma unroll
            for (int half = 0; half < 2; half++) {
                const int m = m0 + wm * 64 + mf * 16 + gID + half * 8;
                const float fx = acc[mf][nf][half * 2 + 0] + bx;
                const float fy = acc[mf][nf][half * 2 + 1] + by;
                if (mode == 0) {
                    const int s  = m >> 1;
                    const int bb = m & 1;
                    const int h  = n >> 6;
                    const int j  = n & 63;
                    const size_t idx = (((size_t)(bb * NHEADS + h)) * SEQ + s) * DK + j;
                    __half* D = (p == 0) ? g_Qf : (p == 1) ? g_Kf : g_Vf;
                    *(uint32_t*)&D[idx] = packf2(fx, fy);
                } else {
                    float2 v; v.x = fx; v.y = fy;
                    *(float2*)&dst[(size_t)m * DMODEL + n] = v;
                }
            }
        }
    }
}

// ---------------------------------------------------------------------------
// Kernel 2: fp16 HMMA flash attention, all operands single fp16.
// S = Qf Kf^T ; O += Pf Vf. CTA = 64 q-rows, 4 warps, 4 CTAs/SM.
// K-tile 64, 3-stage cp.async (16KB/stage). grid = (SEQ/64, BH).
// ---------------------------------------------------------------------------
#define ASTAGE  16384   // Kf 8KB + Vf 8KB
#define AT_SMEM (3 * ASTAGE)

__global__ __launch_bounds__(128, 4)
void attn_mma()
{
    extern __shared__ char kvsm[];
    const uint32_t kvb = smem_u32(kvsm);
    const int tid  = threadIdx.x;
    const int lane = tid & 31;
    const int warp = tid >> 5;
    const int gID  = lane >> 2;
    const int tg   = lane & 3;
    const int q0   = blockIdx.x * 64;
    const int bh   = blockIdx.y;

    const __half* Kf = g_Kf + (size_t)bh * SEQ * DK;
    const __half* Vf = g_Vf + (size_t)bh * SEQ * DK;

    // Q fragments (single fp16, persistent)
    uint32_t qf[4][4];
    {
        const __half* Q = g_Qf + ((size_t)bh * SEQ + q0 + warp * 16) * DK;
#pragma unroll
        for (int ks = 0; ks < 4; ks++) {
            const int c = ks * 16 + tg * 2;
            qf[ks][0] = *(const uint32_t*)&Q[(gID)     * DK + c];
            qf[ks][1] = *(const uint32_t*)&Q[(gID + 8) * DK + c];
            qf[ks][2] = *(const uint32_t*)&Q[(gID)     * DK + c + 8];
            qf[ks][3] = *(const uint32_t*)&Q[(gID + 8) * DK + c + 8];
        }
    }

    float o[8][4];
#pragma unroll
    for (int j = 0; j < 8; j++)
#pragma unroll
        for (int e = 0; e < 4; e++) o[j][e] = 0.f;
    float mrun[2] = {-1e30f, -1e30f};
    float lrun[2] = {0.f, 0.f};

    // loader: 128 threads; 64 rows x 8 blocks x 2 arrays = 8 cp16/thread
    const int lrow = tid >> 1;            // 0..63
    const int lc0  = (tid & 1) * 4;       // 0 or 4

#define ISSUE(kt, st) do { \
    const size_t grow = ((size_t)((kt) * 64 + lrow)) * DK + lc0 * 8; \
    const uint32_t sb_ = kvb + (st) * ASTAGE + lrow * 128; \
    _Pragma("unroll") \
    for (int i_ = 0; i_ < 4; i_++) { \
        const int blk_ = lc0 + i_; \
        const uint32_t so_ = sb_ + (uint32_t)((blk_ ^ (lrow & 7)) * 16); \
        cp16(so_,         Kf + grow + i_ * 8); \
        cp16(so_ + 8192,  Vf + grow + i_ * 8); \
    } \
    asm volatile("cp.async.commit_group;" ::: "memory"); \
} while (0)

    ISSUE(0, 0);
    ISSUE(1, 1);

    const int krow = (lane & 7) + (lane >> 4) * 8;
    const int kkb  = (lane >> 3) & 1;
    const int vrow = (lane & 7) + ((lane >> 3) & 1) * 8;
    const int vdb  = (lane >> 4);

    for (int kt = 0; kt < 32; kt++) {
        const int st = kt % 3;
        if (kt < 30) {
            asm volatile("cp.async.wait_group 1;" ::: "memory");
        } else {
            asm volatile("cp.async.wait_group 0;" ::: "memory");
        }
        __syncthreads();
        if (kt + 2 < 32) ISSUE(kt + 2, (kt + 2) % 3);

        const uint32_t stage = kvb + st * ASTAGE;

        // --- S = Qf Kf^T ---
        float s[8][4];
#pragma unroll
        for (int j = 0; j < 8; j++)
#pragma unroll
            for (int e = 0; e < 4; e++) s[j][e] = 0.f;

#pragma unroll
        for (int ng = 0; ng < 4; ng++) {
            const int r = ng * 16 + krow;
            const uint32_t rbase = stage + r * 128;
#pragma unroll
            for (int ks = 0; ks < 4; ks++) {
                const int kb = ks * 2 + kkb;
                const uint32_t off = rbase + (uint32_t)((kb ^ (r & 7)) * 16);
                uint32_t kh4[4];
                ldsm4(kh4, off);
                mma16816(s[ng * 2],     qf[ks], &kh4[0]);
                mma16816(s[ng * 2 + 1], qf[ks], &kh4[2]);
            }
        }

        // --- online softmax (exp2 domain) ---
        const float SC = 0.125f * 1.4426950408889634f;
#pragma unroll
        for (int hf = 0; hf < 2; hf++) {
            float mx = -1e30f;
#pragma unroll
            for (int j = 0; j < 8; j++) {
                s[j][hf * 2]     *= SC;
                s[j][hf * 2 + 1] *= SC;
                mx = fmaxf(mx, fmaxf(s[j][hf * 2], s[j][hf * 2 + 1]));
            }
            mx = fmaxf(mx, __shfl_xor_sync(0xffffffffu, mx, 1));
            mx = fmaxf(mx, __shfl_xor_sync(0xffffffffu, mx, 2));
            const float mnew  = fmaxf(mrun[hf], mx);
            const float alpha = exp2f(mrun[hf] - mnew);
            mrun[hf] = mnew;
            float sum = 0.f;
#pragma unroll
            for (int j = 0; j < 8; j++) {
                const float p0 = exp2f(s[j][hf * 2]     - mnew);
                const float p1 = exp2f(s[j][hf * 2 + 1] - mnew);
                s[j][hf * 2]     = p0;
                s[j][hf * 2 + 1] = p1;
                sum += p0 + p1;
            }
            sum += __shfl_xor_sync(0xffffffffu, sum, 1);
            sum += __shfl_xor_sync(0xffffffffu, sum, 2);
            lrun[hf] = lrun[hf] * alpha + sum;
#pragma unroll
            for (int j = 0; j < 8; j++) {
                o[j][hf * 2]     *= alpha;
                o[j][hf * 2 + 1] *= alpha;
            }
        }

        // --- O += Pf Vf ---
#pragma unroll
        for (int t = 0; t < 4; t++) {
            uint32_t pah[4];
            pah[0] = packf2(s[2 * t + 0][0], s[2 * t + 0][1]);
            pah[1] = packf2(s[2 * t + 0][2], s[2 * t + 0][3]);
            pah[2] = packf2(s[2 * t + 1][0], s[2 * t + 1][1]);
            pah[3] = packf2(s[2 * t + 1][2], s[2 * t + 1][3]);

            const int r = t * 16 + vrow;
            const uint32_t rbase = stage + 8192 + r * 128;
#pragma unroll
            for (int dg = 0; dg < 4; dg++) {
                const int db = dg * 2 + vdb;
                const uint32_t off = rbase + (uint32_t)((db ^ (r & 7)) * 16);
                uint32_t vf4[4];
                ldsm4t(vf4, off);
                mma16816(o[dg * 2],     pah, &vf4[0]);
                mma16816(o[dg * 2 + 1], pah, &vf4[2]);
            }
        }
    }
#undef ISSUE

    // --- epilogue: normalize, round to fp16, write g_Af ---
    const int bb  = bh >> 4;
    const int hh_ = bh & 15;
#pragma unroll
    for (int half = 0; half < 2; half++) {
        const int r = q0 + warp * 16 + gID + half * 8;
        const float inv = 1.0f / lrun[half];
#pragma unroll
        for (int j = 0; j < 8; j++) {
            const float f0 = o[j][half * 2 + 0] * inv;
            const float f1 = o[j][half * 2 + 1] * inv;
            const size_t idx = ((size_t)(r * BATCH + bb)) * DMODEL + hh_ * DK + j * 8 + tg * 2;
            *(uint32_t*)&g_Af[idx] = packf2(f0, f1);
        }
    }
}

// ---------------------------------------------------------------------------
extern "C" void kernel_launch(void* const* d_in, const int* in_sizes, int n_in,
                              void* d_out, int out_size)
{
    const float* q     = (const float*)d_in[0];
    const float* k     = (const float*)d_in[1];
    const float* v     = (const float*)d_in[2];
    const float* in_w  = (const float*)d_in[3];
    const float* in_b  = (const float*)d_in[4];
    const float* out_w = (const float*)d_in[5];
    const float* out_b = (const float*)d_in[6];
    float* out = (float*)d_out;

    static bool attr_done = false;
    if (!attr_done) {
        cudaFuncSetAttribute(attn_mma, cudaFuncAttributeMaxDynamicSharedMemorySize, AT_SMEM);
        cudaFuncSetAttribute(gemm_mma, cudaFuncAttributeMaxDynamicSharedMemorySize, GB_SMEM);
        attr_done = true;
    }

    cvt_all<<<dim3(4096, 5), 256>>>(q, k, v, in_w, out_w);

    dim3 gQKV(DMODEL / 128, MROWS / 128, 3);
    gemm_mma<<<gQKV, 256, GB_SMEM>>>(in_b, out, 0);

    dim3 gAttn(SEQ / 64, BH);
    attn_mma<<<gAttn, 128, AT_SMEM>>>();

    dim3 gOut(DMODEL / 128, MROWS / 128, 1);
    gemm_mma<<<gOut, 256, GB_SMEM>>>(out_b, out, 1);
}

// round 11
// speedup vs baseline: 9.0676x; 1.2966x over previous
#include <cuda_runtime.h>
#include <cuda_fp16.h>
#include <cstdint>

// ---------------------------------------------------------------------------
// Problem constants
// ---------------------------------------------------------------------------
#define SEQ     2048
#define BATCH   2
#define DMODEL  1024
#define NHEADS  16
#define DK      64
#define BH      (BATCH*NHEADS)   // 32
#define MROWS   (SEQ*BATCH)      // 4096

// ---------------------------------------------------------------------------
// Device scratch
// ---------------------------------------------------------------------------
__device__ __half g_Qf [BH * SEQ * DK];     // Q rounded fp16
__device__ __half g_Kf [BH * SEQ * DK];     // K rounded fp16
__device__ __half g_Vf [BH * SEQ * DK];     // V rounded fp16

__device__ __half g_Xf [3 * MROWS * DMODEL];  // X rounded fp16
__device__ __half g_Wf [3 * DMODEL * DMODEL]; // in_proj_w rounded fp16
__device__ __half g_OWf[DMODEL * DMODEL];     // out_proj_w rounded fp16
__device__ __half g_Af [MROWS * DMODEL];      // attention out rounded fp16

// ---------------------------------------------------------------------------
// Helpers
// ---------------------------------------------------------------------------
__device__ __forceinline__ uint32_t smem_u32(const void* p) {
    uint32_t r;
    asm("{ .reg .u64 t; cvta.to.shared.u64 t, %1; cvt.u32.u64 %0, t; }"
        : "=r"(r) : "l"(p));
    return r;
}

__device__ __forceinline__ void ldsm4(uint32_t* r, uint32_t addr) {
    asm volatile("ldmatrix.sync.aligned.m8n8.x4.shared.b16 {%0,%1,%2,%3}, [%4];"
                 : "=r"(r[0]), "=r"(r[1]), "=r"(r[2]), "=r"(r[3]) : "r"(addr));
}

__device__ __forceinline__ void ldsm4t(uint32_t* r, uint32_t addr) {
    asm volatile("ldmatrix.sync.aligned.m8n8.x4.trans.shared.b16 {%0,%1,%2,%3}, [%4];"
                 : "=r"(r[0]), "=r"(r[1]), "=r"(r[2]), "=r"(r[3]) : "r"(addr));
}

__device__ __forceinline__ void mma16816(float* c, const uint32_t* a, const uint32_t* b) {
    asm volatile(
        "mma.sync.aligned.m16n8k16.row.col.f32.f16.f16.f32 "
        "{%0,%1,%2,%3}, {%4,%5,%6,%7}, {%8,%9}, {%0,%1,%2,%3};"
        : "+f"(c[0]), "+f"(c[1]), "+f"(c[2]), "+f"(c[3])
        : "r"(a[0]), "r"(a[1]), "r"(a[2]), "r"(a[3]), "r"(b[0]), "r"(b[1]));
}

__device__ __forceinline__ void cp16(uint32_t d, const void* s) {
    asm volatile("cp.async.cg.shared.global [%0], [%1], 16;" :: "r"(d), "l"(s));
}

__device__ __forceinline__ uint32_t packf2(float a, float b) {
    float2 t; t.x = a; t.y = b;
    __half2 h = __float22half2_rn(t);
    return *(uint32_t*)&h;
}

// ---------------------------------------------------------------------------
// Kernel 0: fused conversion (all plain fp16 rounding now).
// jobs 0-2: q/k/v -> g_Xf; 3: in_w -> g_Wf; 4: out_w -> g_OWf. grid=(4096,5)
// ---------------------------------------------------------------------------
__global__ __launch_bounds__(256)
void cvt_all(const float* __restrict__ q, const float* __restrict__ k,
             const float* __restrict__ v, const float* __restrict__ in_w,
             const float* __restrict__ out_w)
{
    const int job = blockIdx.y;
    const int i = blockIdx.x * 256 + threadIdx.x;
    const float* src;
    __half* dst;
    int n4;
    if (job < 3) {
        n4 = MROWS * DMODEL / 4;
        src = (job == 0) ? q : (job == 1) ? k : v;
        dst = g_Xf + (size_t)job * MROWS * DMODEL;
    } else if (job == 3) {
        n4 = 3 * DMODEL * DMODEL / 4;
        src = in_w; dst = g_Wf;
    } else {
        n4 = DMODEL * DMODEL / 4;
        src = out_w; dst = g_OWf;
    }
    if (i >= n4) return;
    float4 x = ((const float4*)src)[i];
    __half2* d = (__half2*)dst;
    d[2 * i]     = __halves2half2(__float2half_rn(x.x), __float2half_rn(x.y));
    d[2 * i + 1] = __halves2half2(__float2half_rn(x.z), __float2half_rn(x.w));
}

// ---------------------------------------------------------------------------
// Kernel 1: plain fp16 HMMA GEMM, 128x128 CTA tile, 256 threads,
// __launch_bounds__(256,2) -> 2 CTAs/SM. K-chunk 32, 3-stage cp.async.
// mode 0: qkv (scatter head-major fp16), mode 1: out (fp32 linear)
// ---------------------------------------------------------------------------
#define GSTAGE  16384   // Af 8KB + Bf 8KB
#define GB_SMEM (3 * GSTAGE)

__global__ __launch_bounds__(256, 2)
void gemm_mma(const float* __restrict__ bias_in, float* __restrict__ dst, int mode)
{
    extern __shared__ char gsm[];
    const uint32_t sbase = smem_u32(gsm);

    const int tid  = threadIdx.x;
    const int lane = tid & 31;
    const int wid  = tid >> 5;
    const int wm   = wid & 1;
    const int wn   = wid >> 1;
    const int p    = blockIdx.z;
    const int n0   = blockIdx.x * 128;
    const int m0   = blockIdx.y * 128;

    const __half *Afp, *Bf;
    if (mode == 0) {
        Afp = g_Xf + (size_t)p * MROWS * DMODEL;
        Bf  = g_Wf + (size_t)p * DMODEL * DMODEL;
    } else {
        Afp = g_Af; Bf = g_OWf;
    }
    const float* bptr = bias_in + p * DMODEL;

    const int lrow = tid >> 1;
    const int lc0  = (tid & 1) * 2;
    const uint32_t soff0 = (uint32_t)(lrow * 64 + (((lc0)     ^ ((lrow >> 1) & 3)) * 16));
    const uint32_t soff1 = (uint32_t)(lrow * 64 + (((lc0 + 1) ^ ((lrow >> 1) & 3)) * 16));
    const size_t aoff = (size_t)(m0 + lrow) * DMODEL + lc0 * 8;
    const size_t boff = (size_t)(n0 + lrow) * DMODEL + lc0 * 8;

#define GISSUE(kc, st) do { \
    const size_t ko = (size_t)(kc) * 32; \
    const uint32_t sb_ = sbase + (st) * GSTAGE; \
    cp16(sb_        + soff0, Afp + aoff + ko);     \
    cp16(sb_        + soff1, Afp + aoff + ko + 8); \
    cp16(sb_ + 8192 + soff0, Bf + boff + ko);      \
    cp16(sb_ + 8192 + soff1, Bf + boff + ko + 8);  \
    asm volatile("cp.async.commit_group;" ::: "memory"); \
} while (0)

    const int arow = (lane & 7) + ((lane >> 3) & 1) * 8;
    const int akb  = (lane >> 4);
    const int brow = (lane & 7) + (lane >> 4) * 8;
    const int bkb  = ((lane >> 3) & 1);

    float acc[4][4][4];
#pragma unroll
    for (int i = 0; i < 4; i++)
#pragma unroll
        for (int j = 0; j < 4; j++)
#pragma unroll
            for (int e = 0; e < 4; e++) acc[i][j][e] = 0.f;

    GISSUE(0, 0);
    GISSUE(1, 1);

    for (int kc = 0; kc < 32; kc++) {
        const int st = kc % 3;
        if (kc < 30) {
            asm volatile("cp.async.wait_group 1;" ::: "memory");
        } else {
            asm volatile("cp.async.wait_group 0;" ::: "memory");
        }
        __syncthreads();
        if (kc + 2 < 32) GISSUE(kc + 2, (kc + 2) % 3);

        const uint32_t bufb = sbase + st * GSTAGE;
#pragma unroll
        for (int ks = 0; ks < 2; ks++) {
            uint32_t af[4][4];
#pragma unroll
            for (int mf = 0; mf < 4; mf++) {
                const int r  = wm * 64 + mf * 16 + arow;
                const int kb = ks * 2 + akb;
                const uint32_t off = (uint32_t)(r * 64 + ((kb ^ ((r >> 1) & 3)) * 16));
                ldsm4(af[mf], bufb + off);
            }
            uint32_t bf[2][4];
#pragma unroll
            for (int nq = 0; nq < 2; nq++) {
                const int r  = wn * 32 + nq * 16 + brow;
                const int kb = ks * 2 + bkb;
                const uint32_t off = (uint32_t)(r * 64 + ((kb ^ ((r >> 1) & 3)) * 16));
                ldsm4(bf[nq], bufb + 8192 + off);
            }
#pragma unroll
            for (int mf = 0; mf < 4; mf++)
#pragma unroll
                for (int nf = 0; nf < 4; nf++)
                    mma16816(acc[mf][nf], af[mf], &bf[nf >> 1][(nf & 1) * 2]);
        }
    }
#undef GISSUE
    __syncthreads();

    const int gID = lane >> 2;
    const int tg  = lane & 3;
#pragma unroll
    for (int mf = 0; mf < 4; mf++) {
#pragma unroll
        for (int nf = 0; nf < 4; nf++) {
            const int n = n0 + wn * 32 + nf * 8 + tg * 2;
            const float bx = bptr[n], by = bptr[n + 1];
#pragma unroll
            for (int half = 0; half < 2; half++) {
                const int m = m0 + wm * 64 + mf * 16 + gID + half * 8;
                const float fx = acc[mf][nf][half * 2 + 0] + bx;
                const float fy = acc[mf][nf][half * 2 + 1] + by;
                if (mode == 0) {
                    const int s  = m >> 1;
                    const int bb = m & 1;
                    const int h  = n >> 6;
                    const int j  = n & 63;
                    const size_t idx = (((size_t)(bb * NHEADS + h)) * SEQ + s) * DK + j;
                    __half* D = (p == 0) ? g_Qf : (p == 1) ? g_Kf : g_Vf;
                    *(uint32_t*)&D[idx] = packf2(fx, fy);
                } else {
                    float2 v; v.x = fx; v.y = fy;
                    *(float2*)&dst[(size_t)m * DMODEL + n] = v;
                }
            }
        }
    }
}

// ---------------------------------------------------------------------------
// Kernel 2: fp16 HMMA flash attention, all operands single fp16.
// S = Qf Kf^T ; O += Pf Vf. CTA = 64 q-rows, 4 warps, 4 CTAs/SM.
// K-tile 64, 3-stage cp.async (16KB/stage). grid = (SEQ/64, BH).
// ---------------------------------------------------------------------------
#define ASTAGE  16384   // Kf 8KB + Vf 8KB
#define AT_SMEM (3 * ASTAGE)

__global__ __launch_bounds__(128, 4)
void attn_mma()
{
    extern __shared__ char kvsm[];
    const uint32_t kvb = smem_u32(kvsm);
    const int tid  = threadIdx.x;
    const int lane = tid & 31;
    const int warp = tid >> 5;
    const int gID  = lane >> 2;
    const int tg   = lane & 3;
    const int q0   = blockIdx.x * 64;
    const int bh   = blockIdx.y;

    const __half* Kf = g_Kf + (size_t)bh * SEQ * DK;
    const __half* Vf = g_Vf + (size_t)bh * SEQ * DK;

    // Q fragments (single fp16, persistent)
    uint32_t qf[4][4];
    {
        const __half* Q = g_Qf + ((size_t)bh * SEQ + q0 + warp * 16) * DK;
#pragma unroll
        for (int ks = 0; ks < 4; ks++) {
            const int c = ks * 16 + tg * 2;
            qf[ks][0] = *(const uint32_t*)&Q[(gID)     * DK + c];
            qf[ks][1] = *(const uint32_t*)&Q[(gID + 8) * DK + c];
            qf[ks][2] = *(const uint32_t*)&Q[(gID)     * DK + c + 8];
            qf[ks][3] = *(const uint32_t*)&Q[(gID + 8) * DK + c + 8];
        }
    }

    float o[8][4];
#pragma unroll
    for (int j = 0; j < 8; j++)
#pragma unroll
        for (int e = 0; e < 4; e++) o[j][e] = 0.f;
    float mrun[2] = {-1e30f, -1e30f};
    float lrun[2] = {0.f, 0.f};

    // loader: 128 threads; 64 rows x 8 blocks x 2 arrays = 8 cp16/thread
    const int lrow = tid >> 1;            // 0..63
    const int lc0  = (tid & 1) * 4;       // 0 or 4

#define ISSUE(kt, st) do { \
    const size_t grow = ((size_t)((kt) * 64 + lrow)) * DK + lc0 * 8; \
    const uint32_t sb_ = kvb + (st) * ASTAGE + lrow * 128; \
    _Pragma("unroll") \
    for (int i_ = 0; i_ < 4; i_++) { \
        const int blk_ = lc0 + i_; \
        const uint32_t so_ = sb_ + (uint32_t)((blk_ ^ (lrow & 7)) * 16); \
        cp16(so_,         Kf + grow + i_ * 8); \
        cp16(so_ + 8192,  Vf + grow + i_ * 8); \
    } \
    asm volatile("cp.async.commit_group;" ::: "memory"); \
} while (0)

    ISSUE(0, 0);
    ISSUE(1, 1);

    const int krow = (lane & 7) + (lane >> 4) * 8;
    const int kkb  = (lane >> 3) & 1;
    const int vrow = (lane & 7) + ((lane >> 3) & 1) * 8;
    const int vdb  = (lane >> 4);

    for (int kt = 0; kt < 32; kt++) {
        const int st = kt % 3;
        if (kt < 30) {
            asm volatile("cp.async.wait_group 1;" ::: "memory");
        } else {
            asm volatile("cp.async.wait_group 0;" ::: "memory");
        }
        __syncthreads();
        if (kt + 2 < 32) ISSUE(kt + 2, (kt + 2) % 3);

        const uint32_t stage = kvb + st * ASTAGE;

        // --- S = Qf Kf^T ---
        float s[8][4];
#pragma unroll
        for (int j = 0; j < 8; j++)
#pragma unroll
            for (int e = 0; e < 4; e++) s[j][e] = 0.f;

#pragma unroll
        for (int ng = 0; ng < 4; ng++) {
            const int r = ng * 16 + krow;
            const uint32_t rbase = stage + r * 128;
#pragma unroll
            for (int ks = 0; ks < 4; ks++) {
                const int kb = ks * 2 + kkb;
                const uint32_t off = rbase + (uint32_t)((kb ^ (r & 7)) * 16);
                uint32_t kh4[4];
                ldsm4(kh4, off);
                mma16816(s[ng * 2],     qf[ks], &kh4[0]);
                mma16816(s[ng * 2 + 1], qf[ks], &kh4[2]);
            }
        }

        // --- online softmax (exp2 domain) ---
        const float SC = 0.125f * 1.4426950408889634f;
#pragma unroll
        for (int hf = 0; hf < 2; hf++) {
            float mx = -1e30f;
#pragma unroll
            for (int j = 0; j < 8; j++) {
                s[j][hf * 2]     *= SC;
                s[j][hf * 2 + 1] *= SC;
                mx = fmaxf(mx, fmaxf(s[j][hf * 2], s[j][hf * 2 + 1]));
            }
            mx = fmaxf(mx, __shfl_xor_sync(0xffffffffu, mx, 1));
            mx = fmaxf(mx, __shfl_xor_sync(0xffffffffu, mx, 2));
            const float mnew  = fmaxf(mrun[hf], mx);
            const float alpha = exp2f(mrun[hf] - mnew);
            mrun[hf] = mnew;
            float sum = 0.f;
#pragma unroll
            for (int j = 0; j < 8; j++) {
                const float p0 = exp2f(s[j][hf * 2]     - mnew);
                const float p1 = exp2f(s[j][hf * 2 + 1] - mnew);
                s[j][hf * 2]     = p0;
                s[j][hf * 2 + 1] = p1;
                sum += p0 + p1;
            }
            sum += __shfl_xor_sync(0xffffffffu, sum, 1);
            sum += __shfl_xor_sync(0xffffffffu, sum, 2);
            lrun[hf] = lrun[hf] * alpha + sum;
#pragma unroll
            for (int j = 0; j < 8; j++) {
                o[j][hf * 2]     *= alpha;
                o[j][hf * 2 + 1] *= alpha;
            }
        }

        // --- O += Pf Vf ---
#pragma unroll
        for (int t = 0; t < 4; t++) {
            uint32_t pah[4];
            pah[0] = packf2(s[2 * t + 0][0], s[2 * t + 0][1]);
            pah[1] = packf2(s[2 * t + 0][2], s[2 * t + 0][3]);
            pah[2] = packf2(s[2 * t + 1][0], s[2 * t + 1][1]);
            pah[3] = packf2(s[2 * t + 1][2], s[2 * t + 1][3]);

            const int r = t * 16 + vrow;
            const uint32_t rbase = stage + 8192 + r * 128;
#pragma unroll
            for (int dg = 0; dg < 4; dg++) {
                const int db = dg * 2 + vdb;
                const uint32_t off = rbase + (uint32_t)((db ^ (r & 7)) * 16);
                uint32_t vf4[4];
                ldsm4t(vf4, off);
                mma16816(o[dg * 2],     pah, &vf4[0]);
                mma16816(o[dg * 2 + 1], pah, &vf4[2]);
            }
        }
    }
#undef ISSUE

    // --- epilogue: normalize, round to fp16, write g_Af ---
    const int bb  = bh >> 4;
    const int hh_ = bh & 15;
#pragma unroll
    for (int half = 0; half < 2; half++) {
        const int r = q0 + warp * 16 + gID + half * 8;
        const float inv = 1.0f / lrun[half];
#pragma unroll
        for (int j = 0; j < 8; j++) {
            const float f0 = o[j][half * 2 + 0] * inv;
            const float f1 = o[j][half * 2 + 1] * inv;
            const size_t idx = ((size_t)(r * BATCH + bb)) * DMODEL + hh_ * DK + j * 8 + tg * 2;
            *(uint32_t*)&g_Af[idx] = packf2(f0, f1);
        }
    }
}

// ---------------------------------------------------------------------------
extern "C" void kernel_launch(void* const* d_in, const int* in_sizes, int n_in,
                              void* d_out, int out_size)
{
    const float* q     = (const float*)d_in[0];
    const float* k     = (const float*)d_in[1];
    const float* v     = (const float*)d_in[2];
    const float* in_w  = (const float*)d_in[3];
    const float* in_b  = (const float*)d_in[4];
    const float* out_w = (const float*)d_in[5];
    const float* out_b = (const float*)d_in[6];
    float* out = (float*)d_out;

    static bool attr_done = false;
    if (!attr_done) {
        cudaFuncSetAttribute(attn_mma, cudaFuncAttributeMaxDynamicSharedMemorySize, AT_SMEM);
        cudaFuncSetAttribute(gemm_mma, cudaFuncAttributeMaxDynamicSharedMemorySize, GB_SMEM);
        attr_done = true;
    }

    cvt_all<<<dim3(4096, 5), 256>>>(q, k, v, in_w, out_w);

    dim3 gQKV(DMODEL / 128, MROWS / 128, 3);
    gemm_mma<<<gQKV, 256, GB_SMEM>>>(in_b, out, 0);

    dim3 gAttn(SEQ / 64, BH);
    attn_mma<<<gAttn, 128, AT_SMEM>>>();

    dim3 gOut(DMODEL / 128, MROWS / 128, 1);
    gemm_mma<<<gOut, 256, GB_SMEM>>>(out_b, out, 1);
}

// round 12
// speedup vs baseline: 9.4124x; 1.0380x over previous
#include <cuda_runtime.h>
#include <cuda_fp16.h>
#include <cstdint>

// ---------------------------------------------------------------------------
// Problem constants
// ---------------------------------------------------------------------------
#define SEQ     2048
#define BATCH   2
#define DMODEL  1024
#define NHEADS  16
#define DK      64
#define BH      (BATCH*NHEADS)   // 32
#define MROWS   (SEQ*BATCH)      // 4096

#define SC_Q    (0.125f * 1.4426950408889634f)   // 1/sqrt(dk) * log2(e)

// ---------------------------------------------------------------------------
// Device scratch
// ---------------------------------------------------------------------------
__device__ __half g_Qf [BH * SEQ * DK];     // Q rounded fp16, PRE-SCALED by SC_Q
__device__ __half g_Kf [BH * SEQ * DK];     // K rounded fp16
__device__ __half g_Vf [BH * SEQ * DK];     // V rounded fp16

__device__ __half g_Xf [3 * MROWS * DMODEL];  // X rounded fp16
__device__ __half g_Wf [3 * DMODEL * DMODEL]; // in_proj_w rounded fp16
__device__ __half g_OWf[DMODEL * DMODEL];     // out_proj_w rounded fp16
__device__ __half g_Af [MROWS * DMODEL];      // attention out rounded fp16

// ---------------------------------------------------------------------------
// Helpers
// ---------------------------------------------------------------------------
__device__ __forceinline__ uint32_t smem_u32(const void* p) {
    uint32_t r;
    asm("{ .reg .u64 t; cvta.to.shared.u64 t, %1; cvt.u32.u64 %0, t; }"
        : "=r"(r) : "l"(p));
    return r;
}

__device__ __forceinline__ void ldsm4(uint32_t* r, uint32_t addr) {
    asm volatile("ldmatrix.sync.aligned.m8n8.x4.shared.b16 {%0,%1,%2,%3}, [%4];"
                 : "=r"(r[0]), "=r"(r[1]), "=r"(r[2]), "=r"(r[3]) : "r"(addr));
}

__device__ __forceinline__ void ldsm4t(uint32_t* r, uint32_t addr) {
    asm volatile("ldmatrix.sync.aligned.m8n8.x4.trans.shared.b16 {%0,%1,%2,%3}, [%4];"
                 : "=r"(r[0]), "=r"(r[1]), "=r"(r[2]), "=r"(r[3]) : "r"(addr));
}

__device__ __forceinline__ void mma16816(float* c, const uint32_t* a, const uint32_t* b) {
    asm volatile(
        "mma.sync.aligned.m16n8k16.row.col.f32.f16.f16.f32 "
        "{%0,%1,%2,%3}, {%4,%5,%6,%7}, {%8,%9}, {%0,%1,%2,%3};"
        : "+f"(c[0]), "+f"(c[1]), "+f"(c[2]), "+f"(c[3])
        : "r"(a[0]), "r"(a[1]), "r"(a[2]), "r"(a[3]), "r"(b[0]), "r"(b[1]));
}

__device__ __forceinline__ void cp16(uint32_t d, const void* s) {
    asm volatile("cp.async.cg.shared.global [%0], [%1], 16;" :: "r"(d), "l"(s));
}

__device__ __forceinline__ uint32_t packf2(float a, float b) {
    float2 t; t.x = a; t.y = b;
    __half2 h = __float22half2_rn(t);
    return *(uint32_t*)&h;
}

// packed half2 exp2 (approx) — inputs <= 0, result in [0,1]
__device__ __forceinline__ uint32_t ex2h2(uint32_t x) {
    uint32_t r;
    asm volatile("ex2.approx.f16x2 %0, %1;" : "=r"(r) : "r"(x));
    return r;
}

// ---------------------------------------------------------------------------
// Kernel 0: fused conversion (plain fp16 rounding).
// jobs 0-2: q/k/v -> g_Xf; 3: in_w -> g_Wf; 4: out_w -> g_OWf. grid=(4096,5)
// ---------------------------------------------------------------------------
__global__ __launch_bounds__(256)
void cvt_all(const float* __restrict__ q, const float* __restrict__ k,
             const float* __restrict__ v, const float* __restrict__ in_w,
             const float* __restrict__ out_w)
{
    const int job = blockIdx.y;
    const int i = blockIdx.x * 256 + threadIdx.x;
    const float* src;
    __half* dst;
    int n4;
    if (job < 3) {
        n4 = MROWS * DMODEL / 4;
        src = (job == 0) ? q : (job == 1) ? k : v;
        dst = g_Xf + (size_t)job * MROWS * DMODEL;
    } else if (job == 3) {
        n4 = 3 * DMODEL * DMODEL / 4;
        src = in_w; dst = g_Wf;
    } else {
        n4 = DMODEL * DMODEL / 4;
        src = out_w; dst = g_OWf;
    }
    if (i >= n4) return;
    float4 x = ((const float4*)src)[i];
    __half2* d = (__half2*)dst;
    d[2 * i]     = __halves2half2(__float2half_rn(x.x), __float2half_rn(x.y));
    d[2 * i + 1] = __halves2half2(__float2half_rn(x.z), __float2half_rn(x.w));
}

// ---------------------------------------------------------------------------
// Kernel 1: plain fp16 HMMA GEMM, 128x128 CTA tile, 256 threads,
// 2 CTAs/SM. K-chunk 32, 3-stage cp.async.
// mode 0: qkv (scatter head-major fp16; Q pre-scaled by SC_Q)
// mode 1: out (fp32 linear)
// ---------------------------------------------------------------------------
#define GSTAGE  16384   // Af 8KB + Bf 8KB
#define GB_SMEM (3 * GSTAGE)

__global__ __launch_bounds__(256, 2)
void gemm_mma(const float* __restrict__ bias_in, float* __restrict__ dst, int mode)
{
    extern __shared__ char gsm[];
    const uint32_t sbase = smem_u32(gsm);

    const int tid  = threadIdx.x;
    const int lane = tid & 31;
    const int wid  = tid >> 5;
    const int wm   = wid & 1;
    const int wn   = wid >> 1;
    const int p    = blockIdx.z;
    const int n0   = blockIdx.x * 128;
    const int m0   = blockIdx.y * 128;

    const __half *Afp, *Bf;
    if (mode == 0) {
        Afp = g_Xf + (size_t)p * MROWS * DMODEL;
        Bf  = g_Wf + (size_t)p * DMODEL * DMODEL;
    } else {
        Afp = g_Af; Bf = g_OWf;
    }
    const float* bptr = bias_in + p * DMODEL;

    const int lrow = tid >> 1;
    const int lc0  = (tid & 1) * 2;
    const uint32_t soff0 = (uint32_t)(lrow * 64 + (((lc0)     ^ ((lrow >> 1) & 3)) * 16));
    const uint32_t soff1 = (uint32_t)(lrow * 64 + (((lc0 + 1) ^ ((lrow >> 1) & 3)) * 16));
    const size_t aoff = (size_t)(m0 + lrow) * DMODEL + lc0 * 8;
    const size_t boff = (size_t)(n0 + lrow) * DMODEL + lc0 * 8;

#define GISSUE(kc, st) do { \
    const size_t ko = (size_t)(kc) * 32; \
    const uint32_t sb_ = sbase + (st) * GSTAGE; \
    cp16(sb_        + soff0, Afp + aoff + ko);     \
    cp16(sb_        + soff1, Afp + aoff + ko + 8); \
    cp16(sb_ + 8192 + soff0, Bf + boff + ko);      \
    cp16(sb_ + 8192 + soff1, Bf + boff + ko + 8);  \
    asm volatile("cp.async.commit_group;" ::: "memory"); \
} while (0)

    const int arow = (lane & 7) + ((lane >> 3) & 1) * 8;
    const int akb  = (lane >> 4);
    const int brow = (lane & 7) + (lane >> 4) * 8;
    const int bkb  = ((lane >> 3) & 1);

    float acc[4][4][4];
#pragma unroll
    for (int i = 0; i < 4; i++)
#pragma unroll
        for (int j = 0; j < 4; j++)
#pragma unroll
            for (int e = 0; e < 4; e++) acc[i][j][e] = 0.f;

    GISSUE(0, 0);
    GISSUE(1, 1);

    for (int kc = 0; kc < 32; kc++) {
        const int st = kc % 3;
        if (kc < 30) {
            asm volatile("cp.async.wait_group 1;" ::: "memory");
        } else {
            asm volatile("cp.async.wait_group 0;" ::: "memory");
        }
        __syncthreads();
        if (kc + 2 < 32) GISSUE(kc + 2, (kc + 2) % 3);

        const uint32_t bufb = sbase + st * GSTAGE;
#pragma unroll
        for (int ks = 0; ks < 2; ks++) {
            uint32_t af[4][4];
#pragma unroll
            for (int mf = 0; mf < 4; mf++) {
                const int r  = wm * 64 + mf * 16 + arow;
                const int kb = ks * 2 + akb;
                const uint32_t off = (uint32_t)(r * 64 + ((kb ^ ((r >> 1) & 3)) * 16));
                ldsm4(af[mf], bufb + off);
            }
            uint32_t bf[2][4];
#pragma unroll
            for (int nq = 0; nq < 2; nq++) {
                const int r  = wn * 32 + nq * 16 + brow;
                const int kb = ks * 2 + bkb;
                const uint32_t off = (uint32_t)(r * 64 + ((kb ^ ((r >> 1) & 3)) * 16));
                ldsm4(bf[nq], bufb + 8192 + off);
            }
#pragma unroll
            for (int mf = 0; mf < 4; mf++)
#pragma unroll
                for (int nf = 0; nf < 4; nf++)
                    mma16816(acc[mf][nf], af[mf], &bf[nf >> 1][(nf & 1) * 2]);
        }
    }
#undef GISSUE
    __syncthreads();

    const int gID = lane >> 2;
    const int tg  = lane & 3;
#pragma unroll
    for (int mf = 0; mf < 4; mf++) {
#pragma unroll
        for (int nf = 0; nf < 4; nf++) {
            const int n = n0 + wn * 32 + nf * 8 + tg * 2;
            const float bx = bptr[n], by = bptr[n + 1];
#pragma unroll
            for (int half = 0; half < 2; half++) {
                const int m = m0 + wm * 64 + mf * 16 + gID + half * 8;
                float fx = acc[mf][nf][half * 2 + 0] + bx;
                float fy = acc[mf][nf][half * 2 + 1] + by;
                if (mode == 0) {
                    if (p == 0) { fx *= SC_Q; fy *= SC_Q; }   // pre-scale Q
                    const int s  = m >> 1;
                    const int bb = m & 1;
                    const int h  = n >> 6;
                    const int j  = n & 63;
                    const size_t idx = (((size_t)(bb * NHEADS + h)) * SEQ + s) * DK + j;
                    __half* D = (p == 0) ? g_Qf : (p == 1) ? g_Kf : g_Vf;
                    *(uint32_t*)&D[idx] = packf2(fx, fy);
                } else {
                    float2 v; v.x = fx; v.y = fy;
                    *(float2*)&dst[(size_t)m * DMODEL + n] = v;
                }
            }
        }
    }
}

// ---------------------------------------------------------------------------
// Kernel 2: fp16 HMMA flash attention, single fp16 operands.
// S = Qf Kf^T (Q pre-scaled); P via ex2.approx.f16x2; row sums via ones-MMA.
// CTA = 64 q-rows, 4 warps, 4 CTAs/SM. K-tile 64, 3-stage cp.async.
// grid = (SEQ/64, BH).
// ---------------------------------------------------------------------------
#define ASTAGE  16384   // Kf 8KB + Vf 8KB
#define AT_SMEM (3 * ASTAGE)

__global__ __launch_bounds__(128, 4)
void attn_mma()
{
    extern __shared__ char kvsm[];
    const uint32_t kvb = smem_u32(kvsm);
    const int tid  = threadIdx.x;
    const int lane = tid & 31;
    const int warp = tid >> 5;
    const int gID  = lane >> 2;
    const int tg   = lane & 3;
    const int q0   = blockIdx.x * 64;
    const int bh   = blockIdx.y;

    const __half* Kf = g_Kf + (size_t)bh * SEQ * DK;
    const __half* Vf = g_Vf + (size_t)bh * SEQ * DK;

    // ones b-frag for row-sum MMA: column n=0 is 1.0 (lanes 0-3), rest 0
    const uint32_t ones = (lane < 4) ? 0x3C003C00u : 0u;
    const uint32_t onesb[2] = { ones, ones };

    // Q fragments (single fp16, pre-scaled, persistent)
    uint32_t qf[4][4];
    {
        const __half* Q = g_Qf + ((size_t)bh * SEQ + q0 + warp * 16) * DK;
#pragma unroll
        for (int ks = 0; ks < 4; ks++) {
            const int c = ks * 16 + tg * 2;
            qf[ks][0] = *(const uint32_t*)&Q[(gID)     * DK + c];
            qf[ks][1] = *(const uint32_t*)&Q[(gID + 8) * DK + c];
            qf[ks][2] = *(const uint32_t*)&Q[(gID)     * DK + c + 8];
            qf[ks][3] = *(const uint32_t*)&Q[(gID + 8) * DK + c + 8];
        }
    }

    float o[8][4];
#pragma unroll
    for (int j = 0; j < 8; j++)
#pragma unroll
        for (int e = 0; e < 4; e++) o[j][e] = 0.f;
    float osum[4] = {0.f, 0.f, 0.f, 0.f};   // row sums accumulator (col 0)
    float mrun[2] = {-1e30f, -1e30f};

    // loader: 128 threads; 64 rows x 8 blocks x 2 arrays = 8 cp16/thread
    const int lrow = tid >> 1;            // 0..63
    const int lc0  = (tid & 1) * 4;       // 0 or 4

#define ISSUE(kt, st) do { \
    const size_t grow = ((size_t)((kt) * 64 + lrow)) * DK + lc0 * 8; \
    const uint32_t sb_ = kvb + (st) * ASTAGE + lrow * 128; \
    _Pragma("unroll") \
    for (int i_ = 0; i_ < 4; i_++) { \
        const int blk_ = lc0 + i_; \
        const uint32_t so_ = sb_ + (uint32_t)((blk_ ^ (lrow & 7)) * 16); \
        cp16(so_,         Kf + grow + i_ * 8); \
        cp16(so_ + 8192,  Vf + grow + i_ * 8); \
    } \
    asm volatile("cp.async.commit_group;" ::: "memory"); \
} while (0)

    ISSUE(0, 0);
    ISSUE(1, 1);

    const int krow = (lane & 7) + (lane >> 4) * 8;
    const int kkb  = (lane >> 3) & 1;
    const int vrow = (lane & 7) + ((lane >> 3) & 1) * 8;
    const int vdb  = (lane >> 4);

    for (int kt = 0; kt < 32; kt++) {
        const int st = kt % 3;
        if (kt < 30) {
            asm volatile("cp.async.wait_group 1;" ::: "memory");
        } else {
            asm volatile("cp.async.wait_group 0;" ::: "memory");
        }
        __syncthreads();
        if (kt + 2 < 32) ISSUE(kt + 2, (kt + 2) % 3);

        const uint32_t stage = kvb + st * ASTAGE;

        // --- S = Qf Kf^T (already in exp2 domain via Q pre-scale) ---
        float s[8][4];
#pragma unroll
        for (int j = 0; j < 8; j++)
#pragma unroll
            for (int e = 0; e < 4; e++) s[j][e] = 0.f;

#pragma unroll
        for (int ng = 0; ng < 4; ng++) {
            const int r = ng * 16 + krow;
            const uint32_t rbase = stage + r * 128;
#pragma unroll
            for (int ks = 0; ks < 4; ks++) {
                const int kb = ks * 2 + kkb;
                const uint32_t off = rbase + (uint32_t)((kb ^ (r & 7)) * 16);
                uint32_t kh4[4];
                ldsm4(kh4, off);
                mma16816(s[ng * 2],     qf[ks], &kh4[0]);
                mma16816(s[ng * 2 + 1], qf[ks], &kh4[2]);
            }
        }

        // --- online softmax: max + packed half2 exp2 ---
        uint32_t ph[8][2];   // P as half2 a-frags: [j][hf]
#pragma unroll
        for (int hf = 0; hf < 2; hf++) {
            float mx = -1e30f;
#pragma unroll
            for (int j = 0; j < 8; j++)
                mx = fmaxf(mx, fmaxf(s[j][hf * 2], s[j][hf * 2 + 1]));
            mx = fmaxf(mx, __shfl_xor_sync(0xffffffffu, mx, 1));
            mx = fmaxf(mx, __shfl_xor_sync(0xffffffffu, mx, 2));
            const float mnew  = fmaxf(mrun[hf], mx);
            const float alpha = exp2f(mrun[hf] - mnew);
            mrun[hf] = mnew;
#pragma unroll
            for (int j = 0; j < 8; j++)
                ph[j][hf] = ex2h2(packf2(s[j][hf * 2] - mnew, s[j][hf * 2 + 1] - mnew));
#pragma unroll
            for (int j = 0; j < 8; j++) {
                o[j][hf * 2]     *= alpha;
                o[j][hf * 2 + 1] *= alpha;
            }
            osum[hf * 2]     *= alpha;   // c0/c1: row gID (hf0); c2/c3: row gID+8 (hf1)
            osum[hf * 2 + 1] *= alpha;
        }

        // --- O += P V ;  osum += P ones ---
#pragma unroll
        for (int t = 0; t < 4; t++) {
            uint32_t pah[4];
            pah[0] = ph[2 * t + 0][0];
            pah[1] = ph[2 * t + 0][1];
            pah[2] = ph[2 * t + 1][0];
            pah[3] = ph[2 * t + 1][1];

            mma16816(osum, pah, onesb);   // row sums into column 0

            const int r = t * 16 + vrow;
            const uint32_t rbase = stage + 8192 + r * 128;
#pragma unroll
            for (int dg = 0; dg < 4; dg++) {
                const int db = dg * 2 + vdb;
                const uint32_t off = rbase + (uint32_t)((db ^ (r & 7)) * 16);
                uint32_t vf4[4];
                ldsm4t(vf4, off);
                mma16816(o[dg * 2],     pah, &vf4[0]);
                mma16816(o[dg * 2 + 1], pah, &vf4[2]);
            }
        }
    }
#undef ISSUE

    // --- epilogue: row sums live in col 0 (tg==0 lanes): broadcast in quad ---
    const int qb = (lane >> 2) << 2;
    const float l0 = __shfl_sync(0xffffffffu, osum[0], qb);
    const float l1 = __shfl_sync(0xffffffffu, osum[2], qb);
    const float inv0 = 1.0f / l0;
    const float inv1 = 1.0f / l1;

    const int bb  = bh >> 4;
    const int hh_ = bh & 15;
#pragma unroll
    for (int half = 0; half < 2; half++) {
        const int r = q0 + warp * 16 + gID + half * 8;
        const float inv = (half == 0) ? inv0 : inv1;
#pragma unroll
        for (int j = 0; j < 8; j++) {
            const float f0 = o[j][half * 2 + 0] * inv;
            const float f1 = o[j][half * 2 + 1] * inv;
            const size_t idx = ((size_t)(r * BATCH + bb)) * DMODEL + hh_ * DK + j * 8 + tg * 2;
            *(uint32_t*)&g_Af[idx] = packf2(f0, f1);
        }
    }
}

// ---------------------------------------------------------------------------
extern "C" void kernel_launch(void* const* d_in, const int* in_sizes, int n_in,
                              void* d_out, int out_size)
{
    const float* q     = (const float*)d_in[0];
    const float* k     = (const float*)d_in[1];
    const float* v     = (const float*)d_in[2];
    const float* in_w  = (const float*)d_in[3];
    const float* in_b  = (const float*)d_in[4];
    const float* out_w = (const float*)d_in[5];
    const float* out_b = (const float*)d_in[6];
    float* out = (float*)d_out;

    static bool attr_done = false;
    if (!attr_done) {
        cudaFuncSetAttribute(attn_mma, cudaFuncAttributeMaxDynamicSharedMemorySize, AT_SMEM);
        cudaFuncSetAttribute(gemm_mma, cudaFuncAttributeMaxDynamicSharedMemorySize, GB_SMEM);
        attr_done = true;
    }

    cvt_all<<<dim3(4096, 5), 256>>>(q, k, v, in_w, out_w);

    dim3 gQKV(DMODEL / 128, MROWS / 128, 3);
    gemm_mma<<<gQKV, 256, GB_SMEM>>>(in_b, out, 0);

    dim3 gAttn(SEQ / 64, BH);
    attn_mma<<<gAttn, 128, AT_SMEM>>>();

    dim3 gOut(DMODEL / 128, MROWS / 128, 1);
    gemm_mma<<<gOut, 256, GB_SMEM>>>(out_b, out, 1);
}